// round 1
// baseline (speedup 1.0000x reference)
#include <cuda_runtime.h>

// ---------------------------------------------------------------------------
// AttentionBlock: q,k,v = x@W+b ; S = q k^T / sqrt(D) ; A = softmax(S, axis=q)
// vals = A @ v ; out = vals @ Wo + bo.  Outputs: (out, A) concatenated.
// B=4, L=4096, IN=512, D=64, OUT=512.
// ---------------------------------------------------------------------------

namespace {
constexpr int BB  = 4;
constexpr int LL  = 4096;
constexpr int IN  = 512;
constexpr int DD  = 64;
constexpr int OUT = 512;
constexpr int MM  = BB * LL;          // 16384 total rows
constexpr int KSPLIT = 4;
constexpr float SCALE = 0.125f;       // 1/sqrt(64)
}

// Scratch (device globals: allocation-free per harness rules)
__device__ float g_q[MM * DD];
__device__ float g_k[MM * DD];
__device__ float g_v[MM * DD];
__device__ float g_colsum[MM];                   // per-(b,k) sum over q of exp
__device__ float g_vals[KSPLIT][MM * DD];        // k-split partials of A@v

// ---------------------------------------------------------------------------
// Kernel 1: QKV projection.  grid (MM/64, 3), 256 thr.  Also zeroes g_colsum.
// ---------------------------------------------------------------------------
__global__ __launch_bounds__(256) void qkv_kernel(
    const float* __restrict__ x,
    const float* __restrict__ Wq, const float* __restrict__ bq,
    const float* __restrict__ Wk, const float* __restrict__ bk,
    const float* __restrict__ Wv, const float* __restrict__ bv)
{
    const int t = threadIdx.x;
    // zero colsum (fresh every launch / every graph replay)
    const int gid = (blockIdx.y * gridDim.x + blockIdx.x) * 256 + t;
    if (gid < MM) g_colsum[gid] = 0.f;

    const float* W; const float* bias; float* out;
    if (blockIdx.y == 0)      { W = Wq; bias = bq; out = g_q; }
    else if (blockIdx.y == 1) { W = Wk; bias = bk; out = g_k; }
    else                      { W = Wv; bias = bv; out = g_v; }

    const int mb = blockIdx.x * 64;
    __shared__ float xs[64][32];
    __shared__ __align__(16) float ws[32][64];

    const int tx = t & 15, ty = t >> 4;
    float acc[4][4] = {};

    for (int k0 = 0; k0 < IN; k0 += 32) {
#pragma unroll
        for (int s = 0; s < 8; ++s) {
            int idx = t + s * 256;
            int r = idx >> 5, c = idx & 31;
            xs[r][c] = x[(size_t)(mb + r) * IN + (k0 + c)];
        }
#pragma unroll
        for (int s = 0; s < 8; ++s) {
            int idx = t + s * 256;
            int c = idx >> 6, n = idx & 63;
            ws[c][n] = W[(size_t)(k0 + c) * DD + n];
        }
        __syncthreads();
#pragma unroll
        for (int c = 0; c < 32; ++c) {
            float4 wv = *reinterpret_cast<const float4*>(&ws[c][tx * 4]);
#pragma unroll
            for (int i = 0; i < 4; ++i) {
                float a = xs[ty * 4 + i][c];
                acc[i][0] += a * wv.x; acc[i][1] += a * wv.y;
                acc[i][2] += a * wv.z; acc[i][3] += a * wv.w;
            }
        }
        __syncthreads();
    }
#pragma unroll
    for (int i = 0; i < 4; ++i) {
        int row = mb + ty * 4 + i;
#pragma unroll
        for (int j = 0; j < 4; ++j) {
            int col = tx * 4 + j;
            out[(size_t)row * DD + col] = acc[i][j] + bias[col];
        }
    }
}

// ---------------------------------------------------------------------------
// Kernel 2: E[b,q,k] = exp(scale * q.k), written into attn buffer; atomicAdd
// column (over-q) partial sums into g_colsum.  grid (L/64, L/64, B), 256 thr.
// ---------------------------------------------------------------------------
__global__ __launch_bounds__(256) void scores_kernel(float* __restrict__ attn)
{
    const int b  = blockIdx.z;
    const int qb = blockIdx.y * 64;
    const int kb = blockIdx.x * 64;
    const int t  = threadIdx.x;
    const int tx = t & 15, ty = t >> 4;

    __shared__ float qs[64][DD];                 // [qrow][d]
    __shared__ __align__(16) float kst[DD][68];  // [d][krow], padded for f4

    const float* qp = g_q + (size_t)(b * LL + qb) * DD;
    const float* kp = g_k + (size_t)(b * LL + kb) * DD;

#pragma unroll
    for (int s = 0; s < 16; ++s) {
        int idx = t + s * 256;
        int r = idx >> 6, c = idx & 63;          // r: row, c: d
        qs[r][c]  = qp[(size_t)r * DD + c];
        kst[c][r] = kp[(size_t)r * DD + c];
    }
    __syncthreads();

    float acc[4][4] = {};
#pragma unroll
    for (int d = 0; d < DD; ++d) {
        float4 kv = *reinterpret_cast<const float4*>(&kst[d][tx * 4]);
#pragma unroll
        for (int i = 0; i < 4; ++i) {
            float a = qs[ty * 4 + i][d];
            acc[i][0] += a * kv.x; acc[i][1] += a * kv.y;
            acc[i][2] += a * kv.z; acc[i][3] += a * kv.w;
        }
    }

    // exp + store E + per-thread column partials
    float* ap = attn + ((size_t)b * LL + qb) * LL + kb;
    float csum[4] = {0.f, 0.f, 0.f, 0.f};
#pragma unroll
    for (int i = 0; i < 4; ++i) {
#pragma unroll
        for (int j = 0; j < 4; ++j) {
            float e = __expf(acc[i][j] * SCALE);
            ap[(size_t)(ty * 4 + i) * LL + tx * 4 + j] = e;
            csum[j] += e;
        }
    }

    // reduce partials across ty (16 groups) using qs as scratch
    __syncthreads();
#pragma unroll
    for (int j = 0; j < 4; ++j) qs[ty][tx * 4 + j] = csum[j];
    __syncthreads();
    if (ty == 0) {
#pragma unroll
        for (int j = 0; j < 4; ++j) {
            int col = tx * 4 + j;
            float s = 0.f;
#pragma unroll
            for (int yy = 0; yy < 16; ++yy) s += qs[yy][col];
            atomicAdd(&g_colsum[b * LL + kb + col], s);
        }
    }
}

// ---------------------------------------------------------------------------
// Kernel 3: normalize attn in place (A = E / colsum[k]) AND accumulate
// partial vals = A @ v over this block's k-range.
// grid (L/64, KSPLIT, B), 256 thr.  Each attn element touched exactly once.
// ---------------------------------------------------------------------------
__global__ __launch_bounds__(256) void av_kernel(float* __restrict__ attn)
{
    const int b     = blockIdx.z;
    const int split = blockIdx.y;
    const int qb    = blockIdx.x * 64;
    const int t     = threadIdx.x;
    const int tx = t & 15, ty = t >> 4;
    const int kBeg = split * (LL / KSPLIT);
    const int kEnd = kBeg + (LL / KSPLIT);

    __shared__ float Es[64][64];                // normalized E, [q][k]
    __shared__ __align__(16) float vs[64][DD];  // [krow][d]
    __shared__ float inv[64];

    float acc[4][4] = {};
    float* abase = attn + ((size_t)b * LL + qb) * LL;
    const float* vp = g_v + (size_t)b * LL * DD;
    const float* cs = g_colsum + b * LL;

    for (int kc = kBeg; kc < kEnd; kc += 64) {
        if (t < 64) inv[t] = 1.f / cs[kc + t];
        __syncthreads();
#pragma unroll
        for (int s = 0; s < 16; ++s) {
            int idx = t + s * 256;
            int r = idx >> 6, c = idx & 63;     // r: qrow, c: kcol
            size_t gi = (size_t)r * LL + (kc + c);
            float a = abase[gi] * inv[c];
            abase[gi] = a;                      // normalized attention out
            Es[r][c] = a;
            vs[r][c] = vp[(size_t)(kc + r) * DD + c];  // r: krow, c: d
        }
        __syncthreads();
#pragma unroll
        for (int kk = 0; kk < 64; ++kk) {
            float4 vv = *reinterpret_cast<const float4*>(&vs[kk][tx * 4]);
#pragma unroll
            for (int i = 0; i < 4; ++i) {
                float a = Es[ty * 4 + i][kk];
                acc[i][0] += a * vv.x; acc[i][1] += a * vv.y;
                acc[i][2] += a * vv.z; acc[i][3] += a * vv.w;
            }
        }
        __syncthreads();
    }

#pragma unroll
    for (int i = 0; i < 4; ++i) {
        int row = b * LL + qb + ty * 4 + i;
#pragma unroll
        for (int j = 0; j < 4; ++j)
            g_vals[split][(size_t)row * DD + tx * 4 + j] = acc[i][j];
    }
}

// ---------------------------------------------------------------------------
// Kernel 4: out = (sum of k-split partial vals) @ Wo + bo.
// grid (MM/64, OUT/64), 256 thr.
// ---------------------------------------------------------------------------
__global__ __launch_bounds__(256) void out_kernel(
    const float* __restrict__ Wo, const float* __restrict__ bo,
    float* __restrict__ out)
{
    const int mb = blockIdx.x * 64;
    const int nb = blockIdx.y * 64;
    const int t  = threadIdx.x;
    const int tx = t & 15, ty = t >> 4;

    __shared__ float vsum[64][DD];              // [m][d]
    __shared__ __align__(16) float ws[DD][64];  // [d][n]

#pragma unroll
    for (int s = 0; s < 16; ++s) {
        int idx = t + s * 256;
        int r = idx >> 6, c = idx & 63;
        float v = 0.f;
#pragma unroll
        for (int p = 0; p < KSPLIT; ++p)
            v += g_vals[p][(size_t)(mb + r) * DD + c];
        vsum[r][c] = v;
        ws[r][c] = Wo[(size_t)r * OUT + nb + c];   // r is d here (both 64)
    }
    __syncthreads();

    float acc[4][4] = {};
#pragma unroll
    for (int d = 0; d < DD; ++d) {
        float4 wv = *reinterpret_cast<const float4*>(&ws[d][tx * 4]);
#pragma unroll
        for (int i = 0; i < 4; ++i) {
            float a = vsum[ty * 4 + i][d];
            acc[i][0] += a * wv.x; acc[i][1] += a * wv.y;
            acc[i][2] += a * wv.z; acc[i][3] += a * wv.w;
        }
    }
#pragma unroll
    for (int i = 0; i < 4; ++i) {
        int row = mb + ty * 4 + i;
#pragma unroll
        for (int j = 0; j < 4; ++j) {
            int col = nb + tx * 4 + j;
            out[(size_t)row * OUT + col] = acc[i][j] + bo[col];
        }
    }
}

// ---------------------------------------------------------------------------
extern "C" void kernel_launch(void* const* d_in, const int* in_sizes, int n_in,
                              void* d_out, int out_size)
{
    const float* x  = (const float*)d_in[0];
    const float* Wq = (const float*)d_in[1];
    const float* bq = (const float*)d_in[2];
    const float* Wk = (const float*)d_in[3];
    const float* bk = (const float*)d_in[4];
    const float* Wv = (const float*)d_in[5];
    const float* bv = (const float*)d_in[6];
    const float* Wo = (const float*)d_in[7];
    const float* bo = (const float*)d_in[8];

    float* out  = (float*)d_out;                       // [B, L, OUT]
    float* attn = out + (size_t)BB * LL * OUT;         // [B, L, L]

    qkv_kernel<<<dim3(MM / 64, 3), 256>>>(x, Wq, bq, Wk, bk, Wv, bv);
    scores_kernel<<<dim3(LL / 64, LL / 64, BB), 256>>>(attn);
    av_kernel<<<dim3(LL / 64, KSPLIT, BB), 256>>>(attn);
    out_kernel<<<dim3(MM / 64, OUT / 64), 256>>>(Wo, bo, out);
}

// round 2
// speedup vs baseline: 1.8117x; 1.8117x over previous
#include <cuda_runtime.h>

// ---------------------------------------------------------------------------
// AttentionBlock: q,k,v = x@W+b ; S = q k^T / sqrt(D) ; A = softmax(S, axis=q)
// vals = A @ v ; out = vals @ Wo + bo.  Outputs: (out, A) concatenated.
// B=4, L=4096, IN=512, D=64, OUT=512.
// Round 1: packed fp32 (fma.rn.f32x2), 8x8 register tiles, swizzled smem.
// ---------------------------------------------------------------------------

namespace {
constexpr int BB  = 4;
constexpr int LL  = 4096;
constexpr int IN  = 512;
constexpr int DD  = 64;
constexpr int OUT = 512;
constexpr int MM  = BB * LL;          // 16384 total rows
constexpr int KSPLIT = 4;
constexpr float SCALE = 0.125f;       // 1/sqrt(64)
}

typedef unsigned long long u64;

__device__ __forceinline__ void fma2(u64 &d, u64 a, u64 b) {
    asm("fma.rn.f32x2 %0, %1, %2, %0;" : "+l"(d) : "l"(a), "l"(b));
}
__device__ __forceinline__ u64 dup2(float a) {
    u64 r; asm("mov.b64 %0, {%1, %1};" : "=l"(r) : "f"(a)); return r;
}
__device__ __forceinline__ u64 pk2(float lo, float hi) {
    u64 r; asm("mov.b64 %0, {%1, %2};" : "=l"(r) : "f"(lo), "f"(hi)); return r;
}
__device__ __forceinline__ float2 up2(u64 v) {
    float2 r; asm("mov.b64 {%0, %1}, %2;" : "=f"(r.x), "=f"(r.y) : "l"(v)); return r;
}
// swizzled transposed tile index: logical (d, c) with pitch 128
__device__ __forceinline__ int swz(int d, int c) { return d * 128 + (c ^ (d & 28)); }

// Scratch (device globals: allocation-free per harness rules)
__device__ float g_q[MM * DD];
__device__ float g_k[MM * DD];
__device__ float g_v[MM * DD];
__device__ float g_colsum[MM];                   // per-(b,k) sum over q of exp
__device__ float g_vals[KSPLIT][MM * DD];        // k-split partials of A@v

// core 8x8 f32x2 rank-1 update: acc[32] pairs, a0/a1 rows, b0/b1 cols
__device__ __forceinline__ void rank1(u64* acc, float4 a0, float4 a1,
                                      float4 b0, float4 b1)
{
    u64 bp0 = pk2(b0.x, b0.y), bp1 = pk2(b0.z, b0.w);
    u64 bp2 = pk2(b1.x, b1.y), bp3 = pk2(b1.z, b1.w);
    float av[8] = {a0.x, a0.y, a0.z, a0.w, a1.x, a1.y, a1.z, a1.w};
#pragma unroll
    for (int i = 0; i < 8; ++i) {
        u64 ad = dup2(av[i]);
        fma2(acc[i * 4 + 0], ad, bp0);
        fma2(acc[i * 4 + 1], ad, bp1);
        fma2(acc[i * 4 + 2], ad, bp2);
        fma2(acc[i * 4 + 3], ad, bp3);
    }
}

// ---------------------------------------------------------------------------
// Kernel 1: QKV projection. grid (MM/128, 3), 128 thr. Tile 128x64, 8x8/thr.
// Also zeroes g_colsum.
// ---------------------------------------------------------------------------
__global__ __launch_bounds__(128) void qkv_kernel(
    const float* __restrict__ x,
    const float* __restrict__ Wq, const float* __restrict__ bq,
    const float* __restrict__ Wk, const float* __restrict__ bk,
    const float* __restrict__ Wv, const float* __restrict__ bv)
{
    const int t = threadIdx.x;
    const int gid = (blockIdx.y * gridDim.x + blockIdx.x) * 128 + t;
    if (gid < MM) g_colsum[gid] = 0.f;

    const float* W; const float* bias; float* outp;
    if (blockIdx.y == 0)      { W = Wq; bias = bq; outp = g_q; }
    else if (blockIdx.y == 1) { W = Wk; bias = bk; outp = g_k; }
    else                      { W = Wv; bias = bv; outp = g_v; }

    const int mb = blockIdx.x * 128;
    const int tx = t & 7, ty = t >> 3;           // tx: 8 col-groups, ty: 16 row-groups

    __shared__ float xs[64 * 128];               // transposed swizzled [k][row]
    __shared__ float ws[64 * 64];                // natural [k][n]

    u64 acc[32];
#pragma unroll
    for (int i = 0; i < 32; ++i) acc[i] = 0ull;

    const int dq = t & 15, rb = t >> 4;          // load-phase mapping

    for (int kc = 0; kc < IN; kc += 64) {
        __syncthreads();
        // x tile 128 rows x 64 k -> transpose
#pragma unroll
        for (int s = 0; s < 16; ++s) {
            int r = rb + s * 8;
            float4 v = *reinterpret_cast<const float4*>(&x[(size_t)(mb + r) * IN + kc + 4 * dq]);
            xs[swz(4 * dq + 0, r)] = v.x;
            xs[swz(4 * dq + 1, r)] = v.y;
            xs[swz(4 * dq + 2, r)] = v.z;
            xs[swz(4 * dq + 3, r)] = v.w;
        }
        // W tile 64 k x 64 n -> direct
#pragma unroll
        for (int s = 0; s < 8; ++s) {
            int kr = rb + s * 8;
            *reinterpret_cast<float4*>(&ws[kr * 64 + 4 * dq]) =
                *reinterpret_cast<const float4*>(&W[(size_t)(kc + kr) * DD + 4 * dq]);
        }
        __syncthreads();
#pragma unroll 8
        for (int k = 0; k < 64; ++k) {
            float4 a0 = *reinterpret_cast<const float4*>(&xs[swz(k, 4 * ty)]);
            float4 a1 = *reinterpret_cast<const float4*>(&xs[swz(k, 64 + 4 * ty)]);
            float4 b0 = *reinterpret_cast<const float4*>(&ws[k * 64 + 4 * tx]);
            float4 b1 = *reinterpret_cast<const float4*>(&ws[k * 64 + 32 + 4 * tx]);
            rank1(acc, a0, a1, b0, b1);
        }
    }
    // epilogue: rows {4ty+i, 64+4ty+i}, cols {4tx.., 32+4tx..}
    float4 bias0 = *reinterpret_cast<const float4*>(&bias[4 * tx]);
    float4 bias1 = *reinterpret_cast<const float4*>(&bias[32 + 4 * tx]);
#pragma unroll
    for (int i = 0; i < 8; ++i) {
        int r = (i < 4) ? (4 * ty + i) : (64 + 4 * ty + (i - 4));
        float2 p0 = up2(acc[i * 4 + 0]), p1 = up2(acc[i * 4 + 1]);
        float2 p2 = up2(acc[i * 4 + 2]), p3 = up2(acc[i * 4 + 3]);
        float4 o0 = make_float4(p0.x + bias0.x, p0.y + bias0.y, p1.x + bias0.z, p1.y + bias0.w);
        float4 o1 = make_float4(p2.x + bias1.x, p2.y + bias1.y, p3.x + bias1.z, p3.y + bias1.w);
        *reinterpret_cast<float4*>(&outp[(size_t)(mb + r) * DD + 4 * tx]) = o0;
        *reinterpret_cast<float4*>(&outp[(size_t)(mb + r) * DD + 32 + 4 * tx]) = o1;
    }
}

// ---------------------------------------------------------------------------
// Kernel 2: E = exp(scale * q k^T) into attn; column partial sums -> g_colsum.
// grid (L/128, L/128, B), 256 thr. Tile 128x128, 8x8/thr.
// ---------------------------------------------------------------------------
__global__ __launch_bounds__(256) void scores_kernel(float* __restrict__ attn)
{
    const int b  = blockIdx.z;
    const int qb = blockIdx.y * 128;
    const int kb = blockIdx.x * 128;
    const int t  = threadIdx.x;
    const int tx = t & 15, ty = t >> 4;

    __shared__ float qs[64 * 128];               // transposed swizzled [d][q]
    __shared__ float ks[64 * 128];               // transposed swizzled [d][k]

    const float* qp = g_q + (size_t)(b * LL + qb) * DD;
    const float* kp = g_k + (size_t)(b * LL + kb) * DD;

    const int dq = t & 15, rb = t >> 4;          // rb 0..15
#pragma unroll
    for (int s = 0; s < 8; ++s) {
        int r = rb + s * 16;
        float4 vq = *reinterpret_cast<const float4*>(&qp[(size_t)r * DD + 4 * dq]);
        float4 vk = *reinterpret_cast<const float4*>(&kp[(size_t)r * DD + 4 * dq]);
        qs[swz(4 * dq + 0, r)] = vq.x; qs[swz(4 * dq + 1, r)] = vq.y;
        qs[swz(4 * dq + 2, r)] = vq.z; qs[swz(4 * dq + 3, r)] = vq.w;
        ks[swz(4 * dq + 0, r)] = vk.x; ks[swz(4 * dq + 1, r)] = vk.y;
        ks[swz(4 * dq + 2, r)] = vk.z; ks[swz(4 * dq + 3, r)] = vk.w;
    }
    __syncthreads();

    u64 acc[32];
#pragma unroll
    for (int i = 0; i < 32; ++i) acc[i] = 0ull;

#pragma unroll 8
    for (int d = 0; d < 64; ++d) {
        float4 a0 = *reinterpret_cast<const float4*>(&qs[swz(d, 4 * ty)]);
        float4 a1 = *reinterpret_cast<const float4*>(&qs[swz(d, 64 + 4 * ty)]);
        float4 b0 = *reinterpret_cast<const float4*>(&ks[swz(d, 4 * tx)]);
        float4 b1 = *reinterpret_cast<const float4*>(&ks[swz(d, 64 + 4 * tx)]);
        rank1(acc, a0, a1, b0, b1);
    }

    // exp, store E, accumulate per-thread column sums
    float* ap = attn + ((size_t)b * LL + qb) * LL + kb;
    float csum[8] = {0.f, 0.f, 0.f, 0.f, 0.f, 0.f, 0.f, 0.f};
#pragma unroll
    for (int i = 0; i < 8; ++i) {
        int r = (i < 4) ? (4 * ty + i) : (64 + 4 * ty + (i - 4));
        float2 p0 = up2(acc[i * 4 + 0]), p1 = up2(acc[i * 4 + 1]);
        float2 p2 = up2(acc[i * 4 + 2]), p3 = up2(acc[i * 4 + 3]);
        float e0 = __expf(p0.x * SCALE), e1 = __expf(p0.y * SCALE);
        float e2 = __expf(p1.x * SCALE), e3 = __expf(p1.y * SCALE);
        float e4 = __expf(p2.x * SCALE), e5 = __expf(p2.y * SCALE);
        float e6 = __expf(p3.x * SCALE), e7 = __expf(p3.y * SCALE);
        *reinterpret_cast<float4*>(&ap[(size_t)r * LL + 4 * tx])      = make_float4(e0, e1, e2, e3);
        *reinterpret_cast<float4*>(&ap[(size_t)r * LL + 64 + 4 * tx]) = make_float4(e4, e5, e6, e7);
        csum[0] += e0; csum[1] += e1; csum[2] += e2; csum[3] += e3;
        csum[4] += e4; csum[5] += e5; csum[6] += e6; csum[7] += e7;
    }

    // reduce column sums across the 16 ty-groups via smem (reuse qs)
    __syncthreads();
    float* red = qs;                              // [16][136]
#pragma unroll
    for (int j = 0; j < 4; ++j) {
        red[ty * 136 + 4 * tx + j]      = csum[j];
        red[ty * 136 + 64 + 4 * tx + j] = csum[4 + j];
    }
    __syncthreads();
    if (t < 128) {
        float s = 0.f;
#pragma unroll
        for (int yy = 0; yy < 16; ++yy) s += red[yy * 136 + t];
        atomicAdd(&g_colsum[b * LL + kb + t], s);
    }
}

// ---------------------------------------------------------------------------
// Kernel 3: normalize attn in place (A = E / colsum[k]) AND accumulate
// partial vals = A @ v.  grid (L/128, KSPLIT, B), 128 thr. Tile 128q x 64d.
// ---------------------------------------------------------------------------
__global__ __launch_bounds__(128) void av_kernel(float* __restrict__ attn)
{
    const int b     = blockIdx.z;
    const int split = blockIdx.y;
    const int qb    = blockIdx.x * 128;
    const int t     = threadIdx.x;
    const int tx = t & 7, ty = t >> 3;            // tx: 8 d-groups, ty: 16 q-groups
    const int kBeg = split * (LL / KSPLIT);

    __shared__ float Es[64 * 128];                // transposed swizzled [k][q]
    __shared__ float vs[64 * 64];                 // natural [k][d]
    __shared__ float inv[64];

    u64 acc[32];
#pragma unroll
    for (int i = 0; i < 32; ++i) acc[i] = 0ull;

    float* abase = attn + ((size_t)b * LL + qb) * LL;
    const float* vp = g_v + (size_t)b * LL * DD;
    const float* cs = g_colsum + b * LL;

    const int kq = t & 15, qr = t >> 4;           // load-phase mapping

    for (int cidx = 0; cidx < (LL / KSPLIT) / 64; ++cidx) {
        int kc = kBeg + cidx * 64;
        if (t < 64) inv[t] = 1.f / cs[kc + t];
        __syncthreads();                          // inv ready & prev compute done
        // E tile 128q x 64k: load, normalize, write back, transpose into Es
#pragma unroll
        for (int s = 0; s < 16; ++s) {
            int q = qr + s * 8;
            float4 ev = *reinterpret_cast<const float4*>(&abase[(size_t)q * LL + kc + 4 * kq]);
            float4 iv = *reinterpret_cast<const float4*>(&inv[4 * kq]);
            ev.x *= iv.x; ev.y *= iv.y; ev.z *= iv.z; ev.w *= iv.w;
            *reinterpret_cast<float4*>(&abase[(size_t)q * LL + kc + 4 * kq]) = ev;
            Es[swz(4 * kq + 0, q)] = ev.x;
            Es[swz(4 * kq + 1, q)] = ev.y;
            Es[swz(4 * kq + 2, q)] = ev.z;
            Es[swz(4 * kq + 3, q)] = ev.w;
        }
        // v tile 64k x 64d
#pragma unroll
        for (int s = 0; s < 8; ++s) {
            int kr = qr + s * 8;
            *reinterpret_cast<float4*>(&vs[kr * 64 + 4 * kq]) =
                *reinterpret_cast<const float4*>(&vp[(size_t)(kc + kr) * DD + 4 * kq]);
        }
        __syncthreads();
#pragma unroll 8
        for (int k = 0; k < 64; ++k) {
            float4 a0 = *reinterpret_cast<const float4*>(&Es[swz(k, 4 * ty)]);
            float4 a1 = *reinterpret_cast<const float4*>(&Es[swz(k, 64 + 4 * ty)]);
            float4 b0 = *reinterpret_cast<const float4*>(&vs[k * 64 + 4 * tx]);
            float4 b1 = *reinterpret_cast<const float4*>(&vs[k * 64 + 32 + 4 * tx]);
            rank1(acc, a0, a1, b0, b1);
        }
    }

#pragma unroll
    for (int i = 0; i < 8; ++i) {
        int r = (i < 4) ? (4 * ty + i) : (64 + 4 * ty + (i - 4));
        size_t row = (size_t)(b * LL + qb + r);
        float2 p0 = up2(acc[i * 4 + 0]), p1 = up2(acc[i * 4 + 1]);
        float2 p2 = up2(acc[i * 4 + 2]), p3 = up2(acc[i * 4 + 3]);
        *reinterpret_cast<float4*>(&g_vals[split][row * DD + 4 * tx]) =
            make_float4(p0.x, p0.y, p1.x, p1.y);
        *reinterpret_cast<float4*>(&g_vals[split][row * DD + 32 + 4 * tx]) =
            make_float4(p2.x, p2.y, p3.x, p3.y);
    }
}

// ---------------------------------------------------------------------------
// Kernel 4: out = (sum_p g_vals[p]) @ Wo + bo. grid (MM/128, OUT/128), 256 thr.
// ---------------------------------------------------------------------------
__global__ __launch_bounds__(256) void out_kernel(
    const float* __restrict__ Wo, const float* __restrict__ bo,
    float* __restrict__ outp)
{
    const int mb = blockIdx.x * 128;
    const int nb = blockIdx.y * 128;
    const int t  = threadIdx.x;
    const int tx = t & 15, ty = t >> 4;

    __shared__ float vt[64 * 128];                // transposed swizzled [d][m]
    __shared__ float ws[64 * 128];                // natural [d][n]

    {
        const int dq = t & 15, rb = t >> 4;       // vsum: 128 rows x 64 d
#pragma unroll
        for (int s = 0; s < 8; ++s) {
            int r = rb + s * 16;
            size_t base = (size_t)(mb + r) * DD + 4 * dq;
            float4 v0 = *reinterpret_cast<const float4*>(&g_vals[0][base]);
            float4 v1 = *reinterpret_cast<const float4*>(&g_vals[1][base]);
            float4 v2 = *reinterpret_cast<const float4*>(&g_vals[2][base]);
            float4 v3 = *reinterpret_cast<const float4*>(&g_vals[3][base]);
            float4 v = make_float4(v0.x + v1.x + v2.x + v3.x,
                                   v0.y + v1.y + v2.y + v3.y,
                                   v0.z + v1.z + v2.z + v3.z,
                                   v0.w + v1.w + v2.w + v3.w);
            vt[swz(4 * dq + 0, r)] = v.x; vt[swz(4 * dq + 1, r)] = v.y;
            vt[swz(4 * dq + 2, r)] = v.z; vt[swz(4 * dq + 3, r)] = v.w;
        }
        const int nq = t & 31, kb2 = t >> 5;      // Wo: 64 k x 128 n
#pragma unroll
        for (int s = 0; s < 8; ++s) {
            int kr = kb2 + s * 8;
            *reinterpret_cast<float4*>(&ws[kr * 128 + 4 * nq]) =
                *reinterpret_cast<const float4*>(&Wo[(size_t)kr * OUT + nb + 4 * nq]);
        }
    }
    __syncthreads();

    u64 acc[32];
#pragma unroll
    for (int i = 0; i < 32; ++i) acc[i] = 0ull;

#pragma unroll 8
    for (int k = 0; k < 64; ++k) {
        float4 a0 = *reinterpret_cast<const float4*>(&vt[swz(k, 4 * ty)]);
        float4 a1 = *reinterpret_cast<const float4*>(&vt[swz(k, 64 + 4 * ty)]);
        float4 b0 = *reinterpret_cast<const float4*>(&ws[k * 128 + 4 * tx]);
        float4 b1 = *reinterpret_cast<const float4*>(&ws[k * 128 + 64 + 4 * tx]);
        rank1(acc, a0, a1, b0, b1);
    }

    float4 bo0 = *reinterpret_cast<const float4*>(&bo[nb + 4 * tx]);
    float4 bo1 = *reinterpret_cast<const float4*>(&bo[nb + 64 + 4 * tx]);
#pragma unroll
    for (int i = 0; i < 8; ++i) {
        int r = (i < 4) ? (4 * ty + i) : (64 + 4 * ty + (i - 4));
        float2 p0 = up2(acc[i * 4 + 0]), p1 = up2(acc[i * 4 + 1]);
        float2 p2 = up2(acc[i * 4 + 2]), p3 = up2(acc[i * 4 + 3]);
        float4 o0 = make_float4(p0.x + bo0.x, p0.y + bo0.y, p1.x + bo0.z, p1.y + bo0.w);
        float4 o1 = make_float4(p2.x + bo1.x, p2.y + bo1.y, p3.x + bo1.z, p3.y + bo1.w);
        *reinterpret_cast<float4*>(&outp[(size_t)(mb + r) * OUT + nb + 4 * tx]) = o0;
        *reinterpret_cast<float4*>(&outp[(size_t)(mb + r) * OUT + nb + 64 + 4 * tx]) = o1;
    }
}

// ---------------------------------------------------------------------------
extern "C" void kernel_launch(void* const* d_in, const int* in_sizes, int n_in,
                              void* d_out, int out_size)
{
    const float* x  = (const float*)d_in[0];
    const float* Wq = (const float*)d_in[1];
    const float* bq = (const float*)d_in[2];
    const float* Wk = (const float*)d_in[3];
    const float* bk = (const float*)d_in[4];
    const float* Wv = (const float*)d_in[5];
    const float* bv = (const float*)d_in[6];
    const float* Wo = (const float*)d_in[7];
    const float* bo = (const float*)d_in[8];

    float* outp = (float*)d_out;                       // [B, L, OUT]
    float* attn = outp + (size_t)BB * LL * OUT;        // [B, L, L]

    qkv_kernel<<<dim3(MM / 128, 3), 128>>>(x, Wq, bq, Wk, bk, Wv, bv);
    scores_kernel<<<dim3(LL / 128, LL / 128, BB), 256>>>(attn);
    av_kernel<<<dim3(LL / 128, KSPLIT, BB), 128>>>(attn);
    out_kernel<<<dim3(MM / 128, OUT / 128), 256>>>(Wo, bo, outp);
}

// round 3
// speedup vs baseline: 1.8154x; 1.0021x over previous
#include <cuda_runtime.h>

// ---------------------------------------------------------------------------
// AttentionBlock: q,k,v = x@W+b ; S = q k^T / sqrt(D) ; A = softmax(S, axis=q)
// vals = A @ v ; out = vals @ Wo + bo.  Outputs: (out, A) concatenated.
// B=4, L=4096, IN=512, D=64, OUT=512.
// Round 1: packed fp32 (fma.rn.f32x2), 8x8 register tiles, swizzled smem.
// ---------------------------------------------------------------------------

namespace {
constexpr int BB  = 4;
constexpr int LL  = 4096;
constexpr int IN  = 512;
constexpr int DD  = 64;
constexpr int OUT = 512;
constexpr int MM  = BB * LL;          // 16384 total rows
constexpr int KSPLIT = 4;
constexpr float SCALE = 0.125f;       // 1/sqrt(64)
}

typedef unsigned long long u64;

__device__ __forceinline__ void fma2(u64 &d, u64 a, u64 b) {
    asm("fma.rn.f32x2 %0, %1, %2, %0;" : "+l"(d) : "l"(a), "l"(b));
}
__device__ __forceinline__ u64 dup2(float a) {
    u64 r; asm("mov.b64 %0, {%1, %1};" : "=l"(r) : "f"(a)); return r;
}
__device__ __forceinline__ u64 pk2(float lo, float hi) {
    u64 r; asm("mov.b64 %0, {%1, %2};" : "=l"(r) : "f"(lo), "f"(hi)); return r;
}
__device__ __forceinline__ float2 up2(u64 v) {
    float2 r; asm("mov.b64 {%0, %1}, %2;" : "=f"(r.x), "=f"(r.y) : "l"(v)); return r;
}
// swizzled transposed tile index: logical (d, c) with pitch 128
__device__ __forceinline__ int swz(int d, int c) { return d * 128 + (c ^ (d & 28)); }

// Scratch (device globals: allocation-free per harness rules)
__device__ float g_q[MM * DD];
__device__ float g_k[MM * DD];
__device__ float g_v[MM * DD];
__device__ float g_colsum[MM];                   // per-(b,k) sum over q of exp
__device__ float g_vals[KSPLIT][MM * DD];        // k-split partials of A@v

// core 8x8 f32x2 rank-1 update: acc[32] pairs, a0/a1 rows, b0/b1 cols
__device__ __forceinline__ void rank1(u64* acc, float4 a0, float4 a1,
                                      float4 b0, float4 b1)
{
    u64 bp0 = pk2(b0.x, b0.y), bp1 = pk2(b0.z, b0.w);
    u64 bp2 = pk2(b1.x, b1.y), bp3 = pk2(b1.z, b1.w);
    float av[8] = {a0.x, a0.y, a0.z, a0.w, a1.x, a1.y, a1.z, a1.w};
#pragma unroll
    for (int i = 0; i < 8; ++i) {
        u64 ad = dup2(av[i]);
        fma2(acc[i * 4 + 0], ad, bp0);
        fma2(acc[i * 4 + 1], ad, bp1);
        fma2(acc[i * 4 + 2], ad, bp2);
        fma2(acc[i * 4 + 3], ad, bp3);
    }
}

// ---------------------------------------------------------------------------
// Kernel 1: QKV projection. grid (MM/128, 3), 128 thr. Tile 128x64, 8x8/thr.
// Also zeroes g_colsum.
// ---------------------------------------------------------------------------
__global__ __launch_bounds__(128) void qkv_kernel(
    const float* __restrict__ x,
    const float* __restrict__ Wq, const float* __restrict__ bq,
    const float* __restrict__ Wk, const float* __restrict__ bk,
    const float* __restrict__ Wv, const float* __restrict__ bv)
{
    const int t = threadIdx.x;
    const int gid = (blockIdx.y * gridDim.x + blockIdx.x) * 128 + t;
    if (gid < MM) g_colsum[gid] = 0.f;

    const float* W; const float* bias; float* outp;
    if (blockIdx.y == 0)      { W = Wq; bias = bq; outp = g_q; }
    else if (blockIdx.y == 1) { W = Wk; bias = bk; outp = g_k; }
    else                      { W = Wv; bias = bv; outp = g_v; }

    const int mb = blockIdx.x * 128;
    const int tx = t & 7, ty = t >> 3;           // tx: 8 col-groups, ty: 16 row-groups

    __shared__ float xs[64 * 128];               // transposed swizzled [k][row]
    __shared__ float ws[64 * 64];                // natural [k][n]

    u64 acc[32];
#pragma unroll
    for (int i = 0; i < 32; ++i) acc[i] = 0ull;

    const int dq = t & 15, rb = t >> 4;          // load-phase mapping

    for (int kc = 0; kc < IN; kc += 64) {
        __syncthreads();
        // x tile 128 rows x 64 k -> transpose
#pragma unroll
        for (int s = 0; s < 16; ++s) {
            int r = rb + s * 8;
            float4 v = *reinterpret_cast<const float4*>(&x[(size_t)(mb + r) * IN + kc + 4 * dq]);
            xs[swz(4 * dq + 0, r)] = v.x;
            xs[swz(4 * dq + 1, r)] = v.y;
            xs[swz(4 * dq + 2, r)] = v.z;
            xs[swz(4 * dq + 3, r)] = v.w;
        }
        // W tile 64 k x 64 n -> direct
#pragma unroll
        for (int s = 0; s < 8; ++s) {
            int kr = rb + s * 8;
            *reinterpret_cast<float4*>(&ws[kr * 64 + 4 * dq]) =
                *reinterpret_cast<const float4*>(&W[(size_t)(kc + kr) * DD + 4 * dq]);
        }
        __syncthreads();
#pragma unroll 8
        for (int k = 0; k < 64; ++k) {
            float4 a0 = *reinterpret_cast<const float4*>(&xs[swz(k, 4 * ty)]);
            float4 a1 = *reinterpret_cast<const float4*>(&xs[swz(k, 64 + 4 * ty)]);
            float4 b0 = *reinterpret_cast<const float4*>(&ws[k * 64 + 4 * tx]);
            float4 b1 = *reinterpret_cast<const float4*>(&ws[k * 64 + 32 + 4 * tx]);
            rank1(acc, a0, a1, b0, b1);
        }
    }
    // epilogue: rows {4ty+i, 64+4ty+i}, cols {4tx.., 32+4tx..}
    float4 bias0 = *reinterpret_cast<const float4*>(&bias[4 * tx]);
    float4 bias1 = *reinterpret_cast<const float4*>(&bias[32 + 4 * tx]);
#pragma unroll
    for (int i = 0; i < 8; ++i) {
        int r = (i < 4) ? (4 * ty + i) : (64 + 4 * ty + (i - 4));
        float2 p0 = up2(acc[i * 4 + 0]), p1 = up2(acc[i * 4 + 1]);
        float2 p2 = up2(acc[i * 4 + 2]), p3 = up2(acc[i * 4 + 3]);
        float4 o0 = make_float4(p0.x + bias0.x, p0.y + bias0.y, p1.x + bias0.z, p1.y + bias0.w);
        float4 o1 = make_float4(p2.x + bias1.x, p2.y + bias1.y, p3.x + bias1.z, p3.y + bias1.w);
        *reinterpret_cast<float4*>(&outp[(size_t)(mb + r) * DD + 4 * tx]) = o0;
        *reinterpret_cast<float4*>(&outp[(size_t)(mb + r) * DD + 32 + 4 * tx]) = o1;
    }
}

// ---------------------------------------------------------------------------
// Kernel 2: E = exp(scale * q k^T) into attn; column partial sums -> g_colsum.
// grid (L/128, L/128, B), 256 thr. Tile 128x128, 8x8/thr.
// ---------------------------------------------------------------------------
__global__ __launch_bounds__(256) void scores_kernel(float* __restrict__ attn)
{
    const int b  = blockIdx.z;
    const int qb = blockIdx.y * 128;
    const int kb = blockIdx.x * 128;
    const int t  = threadIdx.x;
    const int tx = t & 15, ty = t >> 4;

    __shared__ float qs[64 * 128];               // transposed swizzled [d][q]
    __shared__ float ks[64 * 128];               // transposed swizzled [d][k]

    const float* qp = g_q + (size_t)(b * LL + qb) * DD;
    const float* kp = g_k + (size_t)(b * LL + kb) * DD;

    const int dq = t & 15, rb = t >> 4;          // rb 0..15
#pragma unroll
    for (int s = 0; s < 8; ++s) {
        int r = rb + s * 16;
        float4 vq = *reinterpret_cast<const float4*>(&qp[(size_t)r * DD + 4 * dq]);
        float4 vk = *reinterpret_cast<const float4*>(&kp[(size_t)r * DD + 4 * dq]);
        qs[swz(4 * dq + 0, r)] = vq.x; qs[swz(4 * dq + 1, r)] = vq.y;
        qs[swz(4 * dq + 2, r)] = vq.z; qs[swz(4 * dq + 3, r)] = vq.w;
        ks[swz(4 * dq + 0, r)] = vk.x; ks[swz(4 * dq + 1, r)] = vk.y;
        ks[swz(4 * dq + 2, r)] = vk.z; ks[swz(4 * dq + 3, r)] = vk.w;
    }
    __syncthreads();

    u64 acc[32];
#pragma unroll
    for (int i = 0; i < 32; ++i) acc[i] = 0ull;

#pragma unroll 8
    for (int d = 0; d < 64; ++d) {
        float4 a0 = *reinterpret_cast<const float4*>(&qs[swz(d, 4 * ty)]);
        float4 a1 = *reinterpret_cast<const float4*>(&qs[swz(d, 64 + 4 * ty)]);
        float4 b0 = *reinterpret_cast<const float4*>(&ks[swz(d, 4 * tx)]);
        float4 b1 = *reinterpret_cast<const float4*>(&ks[swz(d, 64 + 4 * tx)]);
        rank1(acc, a0, a1, b0, b1);
    }

    // exp, store E, accumulate per-thread column sums
    float* ap = attn + ((size_t)b * LL + qb) * LL + kb;
    float csum[8] = {0.f, 0.f, 0.f, 0.f, 0.f, 0.f, 0.f, 0.f};
#pragma unroll
    for (int i = 0; i < 8; ++i) {
        int r = (i < 4) ? (4 * ty + i) : (64 + 4 * ty + (i - 4));
        float2 p0 = up2(acc[i * 4 + 0]), p1 = up2(acc[i * 4 + 1]);
        float2 p2 = up2(acc[i * 4 + 2]), p3 = up2(acc[i * 4 + 3]);
        float e0 = __expf(p0.x * SCALE), e1 = __expf(p0.y * SCALE);
        float e2 = __expf(p1.x * SCALE), e3 = __expf(p1.y * SCALE);
        float e4 = __expf(p2.x * SCALE), e5 = __expf(p2.y * SCALE);
        float e6 = __expf(p3.x * SCALE), e7 = __expf(p3.y * SCALE);
        *reinterpret_cast<float4*>(&ap[(size_t)r * LL + 4 * tx])      = make_float4(e0, e1, e2, e3);
        *reinterpret_cast<float4*>(&ap[(size_t)r * LL + 64 + 4 * tx]) = make_float4(e4, e5, e6, e7);
        csum[0] += e0; csum[1] += e1; csum[2] += e2; csum[3] += e3;
        csum[4] += e4; csum[5] += e5; csum[6] += e6; csum[7] += e7;
    }

    // reduce column sums across the 16 ty-groups via smem (reuse qs)
    __syncthreads();
    float* red = qs;                              // [16][136]
#pragma unroll
    for (int j = 0; j < 4; ++j) {
        red[ty * 136 + 4 * tx + j]      = csum[j];
        red[ty * 136 + 64 + 4 * tx + j] = csum[4 + j];
    }
    __syncthreads();
    if (t < 128) {
        float s = 0.f;
#pragma unroll
        for (int yy = 0; yy < 16; ++yy) s += red[yy * 136 + t];
        atomicAdd(&g_colsum[b * LL + kb + t], s);
    }
}

// ---------------------------------------------------------------------------
// Kernel 3: normalize attn in place (A = E / colsum[k]) AND accumulate
// partial vals = A @ v.  grid (L/128, KSPLIT, B), 128 thr. Tile 128q x 64d.
// ---------------------------------------------------------------------------
__global__ __launch_bounds__(128) void av_kernel(float* __restrict__ attn)
{
    const int b     = blockIdx.z;
    const int split = blockIdx.y;
    const int qb    = blockIdx.x * 128;
    const int t     = threadIdx.x;
    const int tx = t & 7, ty = t >> 3;            // tx: 8 d-groups, ty: 16 q-groups
    const int kBeg = split * (LL / KSPLIT);

    __shared__ float Es[64 * 128];                // transposed swizzled [k][q]
    __shared__ float vs[64 * 64];                 // natural [k][d]
    __shared__ float inv[64];

    u64 acc[32];
#pragma unroll
    for (int i = 0; i < 32; ++i) acc[i] = 0ull;

    float* abase = attn + ((size_t)b * LL + qb) * LL;
    const float* vp = g_v + (size_t)b * LL * DD;
    const float* cs = g_colsum + b * LL;

    const int kq = t & 15, qr = t >> 4;           // load-phase mapping

    for (int cidx = 0; cidx < (LL / KSPLIT) / 64; ++cidx) {
        int kc = kBeg + cidx * 64;
        if (t < 64) inv[t] = 1.f / cs[kc + t];
        __syncthreads();                          // inv ready & prev compute done
        // E tile 128q x 64k: load, normalize, write back, transpose into Es
#pragma unroll
        for (int s = 0; s < 16; ++s) {
            int q = qr + s * 8;
            float4 ev = *reinterpret_cast<const float4*>(&abase[(size_t)q * LL + kc + 4 * kq]);
            float4 iv = *reinterpret_cast<const float4*>(&inv[4 * kq]);
            ev.x *= iv.x; ev.y *= iv.y; ev.z *= iv.z; ev.w *= iv.w;
            *reinterpret_cast<float4*>(&abase[(size_t)q * LL + kc + 4 * kq]) = ev;
            Es[swz(4 * kq + 0, q)] = ev.x;
            Es[swz(4 * kq + 1, q)] = ev.y;
            Es[swz(4 * kq + 2, q)] = ev.z;
            Es[swz(4 * kq + 3, q)] = ev.w;
        }
        // v tile 64k x 64d
#pragma unroll
        for (int s = 0; s < 8; ++s) {
            int kr = qr + s * 8;
            *reinterpret_cast<float4*>(&vs[kr * 64 + 4 * kq]) =
                *reinterpret_cast<const float4*>(&vp[(size_t)(kc + kr) * DD + 4 * kq]);
        }
        __syncthreads();
#pragma unroll 8
        for (int k = 0; k < 64; ++k) {
            float4 a0 = *reinterpret_cast<const float4*>(&Es[swz(k, 4 * ty)]);
            float4 a1 = *reinterpret_cast<const float4*>(&Es[swz(k, 64 + 4 * ty)]);
            float4 b0 = *reinterpret_cast<const float4*>(&vs[k * 64 + 4 * tx]);
            float4 b1 = *reinterpret_cast<const float4*>(&vs[k * 64 + 32 + 4 * tx]);
            rank1(acc, a0, a1, b0, b1);
        }
    }

#pragma unroll
    for (int i = 0; i < 8; ++i) {
        int r = (i < 4) ? (4 * ty + i) : (64 + 4 * ty + (i - 4));
        size_t row = (size_t)(b * LL + qb + r);
        float2 p0 = up2(acc[i * 4 + 0]), p1 = up2(acc[i * 4 + 1]);
        float2 p2 = up2(acc[i * 4 + 2]), p3 = up2(acc[i * 4 + 3]);
        *reinterpret_cast<float4*>(&g_vals[split][row * DD + 4 * tx]) =
            make_float4(p0.x, p0.y, p1.x, p1.y);
        *reinterpret_cast<float4*>(&g_vals[split][row * DD + 32 + 4 * tx]) =
            make_float4(p2.x, p2.y, p3.x, p3.y);
    }
}

// ---------------------------------------------------------------------------
// Kernel 4: out = (sum_p g_vals[p]) @ Wo + bo. grid (MM/128, OUT/128), 256 thr.
// ---------------------------------------------------------------------------
__global__ __launch_bounds__(256) void out_kernel(
    const float* __restrict__ Wo, const float* __restrict__ bo,
    float* __restrict__ outp)
{
    const int mb = blockIdx.x * 128;
    const int nb = blockIdx.y * 128;
    const int t  = threadIdx.x;
    const int tx = t & 15, ty = t >> 4;

    __shared__ float vt[64 * 128];                // transposed swizzled [d][m]
    __shared__ float ws[64 * 128];                // natural [d][n]

    {
        const int dq = t & 15, rb = t >> 4;       // vsum: 128 rows x 64 d
#pragma unroll
        for (int s = 0; s < 8; ++s) {
            int r = rb + s * 16;
            size_t base = (size_t)(mb + r) * DD + 4 * dq;
            float4 v0 = *reinterpret_cast<const float4*>(&g_vals[0][base]);
            float4 v1 = *reinterpret_cast<const float4*>(&g_vals[1][base]);
            float4 v2 = *reinterpret_cast<const float4*>(&g_vals[2][base]);
            float4 v3 = *reinterpret_cast<const float4*>(&g_vals[3][base]);
            float4 v = make_float4(v0.x + v1.x + v2.x + v3.x,
                                   v0.y + v1.y + v2.y + v3.y,
                                   v0.z + v1.z + v2.z + v3.z,
                                   v0.w + v1.w + v2.w + v3.w);
            vt[swz(4 * dq + 0, r)] = v.x; vt[swz(4 * dq + 1, r)] = v.y;
            vt[swz(4 * dq + 2, r)] = v.z; vt[swz(4 * dq + 3, r)] = v.w;
        }
        const int nq = t & 31, kb2 = t >> 5;      // Wo: 64 k x 128 n
#pragma unroll
        for (int s = 0; s < 8; ++s) {
            int kr = kb2 + s * 8;
            *reinterpret_cast<float4*>(&ws[kr * 128 + 4 * nq]) =
                *reinterpret_cast<const float4*>(&Wo[(size_t)kr * OUT + nb + 4 * nq]);
        }
    }
    __syncthreads();

    u64 acc[32];
#pragma unroll
    for (int i = 0; i < 32; ++i) acc[i] = 0ull;

#pragma unroll 8
    for (int k = 0; k < 64; ++k) {
        float4 a0 = *reinterpret_cast<const float4*>(&vt[swz(k, 4 * ty)]);
        float4 a1 = *reinterpret_cast<const float4*>(&vt[swz(k, 64 + 4 * ty)]);
        float4 b0 = *reinterpret_cast<const float4*>(&ws[k * 128 + 4 * tx]);
        float4 b1 = *reinterpret_cast<const float4*>(&ws[k * 128 + 64 + 4 * tx]);
        rank1(acc, a0, a1, b0, b1);
    }

    float4 bo0 = *reinterpret_cast<const float4*>(&bo[nb + 4 * tx]);
    float4 bo1 = *reinterpret_cast<const float4*>(&bo[nb + 64 + 4 * tx]);
#pragma unroll
    for (int i = 0; i < 8; ++i) {
        int r = (i < 4) ? (4 * ty + i) : (64 + 4 * ty + (i - 4));
        float2 p0 = up2(acc[i * 4 + 0]), p1 = up2(acc[i * 4 + 1]);
        float2 p2 = up2(acc[i * 4 + 2]), p3 = up2(acc[i * 4 + 3]);
        float4 o0 = make_float4(p0.x + bo0.x, p0.y + bo0.y, p1.x + bo0.z, p1.y + bo0.w);
        float4 o1 = make_float4(p2.x + bo1.x, p2.y + bo1.y, p3.x + bo1.z, p3.y + bo1.w);
        *reinterpret_cast<float4*>(&outp[(size_t)(mb + r) * OUT + nb + 4 * tx]) = o0;
        *reinterpret_cast<float4*>(&outp[(size_t)(mb + r) * OUT + nb + 64 + 4 * tx]) = o1;
    }
}

// ---------------------------------------------------------------------------
extern "C" void kernel_launch(void* const* d_in, const int* in_sizes, int n_in,
                              void* d_out, int out_size)
{
    const float* x  = (const float*)d_in[0];
    const float* Wq = (const float*)d_in[1];
    const float* bq = (const float*)d_in[2];
    const float* Wk = (const float*)d_in[3];
    const float* bk = (const float*)d_in[4];
    const float* Wv = (const float*)d_in[5];
    const float* bv = (const float*)d_in[6];
    const float* Wo = (const float*)d_in[7];
    const float* bo = (const float*)d_in[8];

    float* outp = (float*)d_out;                       // [B, L, OUT]
    float* attn = outp + (size_t)BB * LL * OUT;        // [B, L, L]

    qkv_kernel<<<dim3(MM / 128, 3), 128>>>(x, Wq, bq, Wk, bk, Wv, bv);
    scores_kernel<<<dim3(LL / 128, LL / 128, BB), 256>>>(attn);
    av_kernel<<<dim3(LL / 128, KSPLIT, BB), 128>>>(attn);
    out_kernel<<<dim3(MM / 128, OUT / 128), 256>>>(Wo, bo, outp);
}

// round 5
// speedup vs baseline: 2.2679x; 1.2493x over previous
#include <cuda_runtime.h>
#include <cuda_bf16.h>
#include <cstdint>

// ---------------------------------------------------------------------------
// AttentionBlock, Round 4: warp-level bf16 mma.sync (HMMA) hi/lo split for the
// two LxL GEMMs.  B=4, L=4096, IN=512, D=64, OUT=512. Outputs: (out, attn).
// ---------------------------------------------------------------------------

namespace {
constexpr int BB  = 4;
constexpr int LL  = 4096;
constexpr int IN  = 512;
constexpr int DD  = 64;
constexpr int OUT = 512;
constexpr int MM  = BB * LL;
constexpr int KSPLIT = 4;
constexpr float SCALE = 0.125f;

// scores dynamic smem layout (bytes)
constexpr uint32_t S_QH = 0, S_QL = 16384, S_KH = 32768, S_KL = 49152,
                   S_RED = 65536, S_SMEM = 65536 + 2048;
// av dynamic smem layout
constexpr uint32_t A_AH = 0, A_AL = 16384, A_VH = 32768, A_VL = 40960,
                   A_INV = 49152, A_SMEM = 49408;
}

typedef unsigned long long u64;

// ------------------------------- helpers -----------------------------------
__device__ __forceinline__ uint32_t smem_u32(const void* p) {
    uint32_t a;
    asm("{ .reg .u64 t; cvta.to.shared.u64 t, %1; cvt.u32.u64 %0, t; }" : "=r"(a) : "l"(p));
    return a;
}
// swizzled byte offset in a [rows][64 bf16] tile (128B rows, 16B units)
__device__ __forceinline__ uint32_t swzo(int r, int c16) {
    return (uint32_t)(r * 128 + ((c16 ^ (r & 7)) << 4));
}
__device__ __forceinline__ void ldsm4(uint32_t r[4], uint32_t addr) {
    asm volatile("ldmatrix.sync.aligned.m8n8.x4.shared.b16 {%0,%1,%2,%3}, [%4];"
        : "=r"(r[0]), "=r"(r[1]), "=r"(r[2]), "=r"(r[3]) : "r"(addr));
}
__device__ __forceinline__ void mma16816(float c[4], const uint32_t a[4], const uint32_t b[2]) {
    asm volatile("mma.sync.aligned.m16n8k16.row.col.f32.bf16.bf16.f32 "
        "{%0,%1,%2,%3}, {%4,%5,%6,%7}, {%8,%9}, {%0,%1,%2,%3};"
        : "+f"(c[0]), "+f"(c[1]), "+f"(c[2]), "+f"(c[3])
        : "r"(a[0]), "r"(a[1]), "r"(a[2]), "r"(a[3]), "r"(b[0]), "r"(b[1]));
}
__device__ __forceinline__ uint32_t pk_bf(float a, float b) {
    return (uint32_t)__bfloat16_as_ushort(__float2bfloat16(a)) |
           ((uint32_t)__bfloat16_as_ushort(__float2bfloat16(b)) << 16);
}
__device__ __forceinline__ void split1(float v, float& hi, float& lo) {
    __nv_bfloat16 h = __float2bfloat16(v);
    hi = __bfloat162float(h);
    lo = v - hi;
}
// 8 consecutive floats -> bf16 hi/lo uint4s
__device__ __forceinline__ void split8(const float4& a, const float4& c, uint4& hi, uint4& lo) {
    float h0, l0, h1, l1;
    split1(a.x, h0, l0); split1(a.y, h1, l1);
    hi.x = pk_bf(h0, h1); lo.x = pk_bf(l0, l1);
    split1(a.z, h0, l0); split1(a.w, h1, l1);
    hi.y = pk_bf(h0, h1); lo.y = pk_bf(l0, l1);
    split1(c.x, h0, l0); split1(c.y, h1, l1);
    hi.z = pk_bf(h0, h1); lo.z = pk_bf(l0, l1);
    split1(c.z, h0, l0); split1(c.w, h1, l1);
    hi.w = pk_bf(h0, h1); lo.w = pk_bf(l0, l1);
}

// ---------------------------- f32x2 (qkv / out) ----------------------------
__device__ __forceinline__ void fma2(u64 &d, u64 a, u64 b) {
    asm("fma.rn.f32x2 %0, %1, %2, %0;" : "+l"(d) : "l"(a), "l"(b));
}
__device__ __forceinline__ u64 dup2(float a) {
    u64 r; asm("mov.b64 %0, {%1, %1};" : "=l"(r) : "f"(a)); return r;
}
__device__ __forceinline__ u64 pk2(float lo, float hi) {
    u64 r; asm("mov.b64 %0, {%1, %2};" : "=l"(r) : "f"(lo), "f"(hi)); return r;
}
__device__ __forceinline__ float2 up2(u64 v) {
    float2 r; asm("mov.b64 {%0, %1}, %2;" : "=f"(r.x), "=f"(r.y) : "l"(v)); return r;
}
__device__ __forceinline__ int swz(int d, int c) { return d * 128 + (c ^ (d & 28)); }

__device__ __forceinline__ void rank1(u64* acc, float4 a0, float4 a1,
                                      float4 b0, float4 b1)
{
    u64 bp0 = pk2(b0.x, b0.y), bp1 = pk2(b0.z, b0.w);
    u64 bp2 = pk2(b1.x, b1.y), bp3 = pk2(b1.z, b1.w);
    float av[8] = {a0.x, a0.y, a0.z, a0.w, a1.x, a1.y, a1.z, a1.w};
#pragma unroll
    for (int i = 0; i < 8; ++i) {
        u64 ad = dup2(av[i]);
        fma2(acc[i * 4 + 0], ad, bp0);
        fma2(acc[i * 4 + 1], ad, bp1);
        fma2(acc[i * 4 + 2], ad, bp2);
        fma2(acc[i * 4 + 3], ad, bp3);
    }
}

// ------------------------------ device scratch -----------------------------
__device__ float g_q[MM * DD];                  // pre-scaled by SCALE
__device__ float g_k[MM * DD];
__device__ float g_v[MM * DD];
__device__ float g_colsum[MM];
__device__ float g_vals[KSPLIT][MM * DD];
__device__ __nv_bfloat16 g_vt_hi[BB * DD * LL]; // v^T bf16 hi  [b][d][k]
__device__ __nv_bfloat16 g_vt_lo[BB * DD * LL]; // v^T bf16 lo

// ---------------------------------------------------------------------------
// Kernel 1: QKV projection (f32x2). grid (MM/128, 3), 128 thr.
// ---------------------------------------------------------------------------
__global__ __launch_bounds__(128) void qkv_kernel(
    const float* __restrict__ x,
    const float* __restrict__ Wq, const float* __restrict__ bq,
    const float* __restrict__ Wk, const float* __restrict__ bk,
    const float* __restrict__ Wv, const float* __restrict__ bv)
{
    const int t = threadIdx.x;
    const int gid = (blockIdx.y * gridDim.x + blockIdx.x) * 128 + t;
    if (gid < MM) g_colsum[gid] = 0.f;

    const float* W; const float* bias; float* outp; float oscale;
    if (blockIdx.y == 0)      { W = Wq; bias = bq; outp = g_q; oscale = SCALE; }
    else if (blockIdx.y == 1) { W = Wk; bias = bk; outp = g_k; oscale = 1.f; }
    else                      { W = Wv; bias = bv; outp = g_v; oscale = 1.f; }

    const int mb = blockIdx.x * 128;
    const int tx = t & 7, ty = t >> 3;

    __shared__ float xs[64 * 128];
    __shared__ float ws[64 * 64];

    u64 acc[32];
#pragma unroll
    for (int i = 0; i < 32; ++i) acc[i] = 0ull;

    const int dq = t & 15, rb = t >> 4;

    for (int kc = 0; kc < IN; kc += 64) {
        __syncthreads();
#pragma unroll
        for (int s = 0; s < 16; ++s) {
            int r = rb + s * 8;
            float4 v = *reinterpret_cast<const float4*>(&x[(size_t)(mb + r) * IN + kc + 4 * dq]);
            xs[swz(4 * dq + 0, r)] = v.x;
            xs[swz(4 * dq + 1, r)] = v.y;
            xs[swz(4 * dq + 2, r)] = v.z;
            xs[swz(4 * dq + 3, r)] = v.w;
        }
#pragma unroll
        for (int s = 0; s < 8; ++s) {
            int kr = rb + s * 8;
            *reinterpret_cast<float4*>(&ws[kr * 64 + 4 * dq]) =
                *reinterpret_cast<const float4*>(&W[(size_t)(kc + kr) * DD + 4 * dq]);
        }
        __syncthreads();
#pragma unroll 8
        for (int k = 0; k < 64; ++k) {
            float4 a0 = *reinterpret_cast<const float4*>(&xs[swz(k, 4 * ty)]);
            float4 a1 = *reinterpret_cast<const float4*>(&xs[swz(k, 64 + 4 * ty)]);
            float4 b0 = *reinterpret_cast<const float4*>(&ws[k * 64 + 4 * tx]);
            float4 b1 = *reinterpret_cast<const float4*>(&ws[k * 64 + 32 + 4 * tx]);
            rank1(acc, a0, a1, b0, b1);
        }
    }
    float4 bias0 = *reinterpret_cast<const float4*>(&bias[4 * tx]);
    float4 bias1 = *reinterpret_cast<const float4*>(&bias[32 + 4 * tx]);
#pragma unroll
    for (int i = 0; i < 8; ++i) {
        int r = (i < 4) ? (4 * ty + i) : (64 + 4 * ty + (i - 4));
        float2 p0 = up2(acc[i * 4 + 0]), p1 = up2(acc[i * 4 + 1]);
        float2 p2 = up2(acc[i * 4 + 2]), p3 = up2(acc[i * 4 + 3]);
        float4 o0 = make_float4((p0.x + bias0.x) * oscale, (p0.y + bias0.y) * oscale,
                                (p1.x + bias0.z) * oscale, (p1.y + bias0.w) * oscale);
        float4 o1 = make_float4((p2.x + bias1.x) * oscale, (p2.y + bias1.y) * oscale,
                                (p3.x + bias1.z) * oscale, (p3.y + bias1.w) * oscale);
        *reinterpret_cast<float4*>(&outp[(size_t)(mb + r) * DD + 4 * tx]) = o0;
        *reinterpret_cast<float4*>(&outp[(size_t)(mb + r) * DD + 32 + 4 * tx]) = o1;
    }
}

// ---------------------------------------------------------------------------
// Kernel 1b: v[b][k][d] -> bf16 hi/lo transposed g_vt[b][d][k].
// grid (LL/64, BB), 256 thr.
// ---------------------------------------------------------------------------
__global__ __launch_bounds__(256) void vtrans_kernel()
{
    const int b = blockIdx.y, kb = blockIdx.x * 64;
    const int t = threadIdx.x;
    __shared__ float tile[64][68];

    const int c4 = t & 15, r0 = t >> 4;
#pragma unroll
    for (int s = 0; s < 4; ++s) {
        int r = r0 + 16 * s;
        float4 v = *reinterpret_cast<const float4*>(&g_v[(size_t)(b * LL + kb + r) * DD + 4 * c4]);
        tile[r][4 * c4 + 0] = v.x; tile[r][4 * c4 + 1] = v.y;
        tile[r][4 * c4 + 2] = v.z; tile[r][4 * c4 + 3] = v.w;
    }
    __syncthreads();

    const int f8 = t & 7, d0 = t >> 3;
#pragma unroll
    for (int s = 0; s < 2; ++s) {
        int d = d0 + 32 * s;
        union { __nv_bfloat16 h[8]; uint4 u; } hi, lo;
#pragma unroll
        for (int j = 0; j < 8; ++j) {
            float v = tile[f8 * 8 + j][d];
            __nv_bfloat16 hb = __float2bfloat16(v);
            hi.h[j] = hb;
            lo.h[j] = __float2bfloat16(v - __bfloat162float(hb));
        }
        size_t o = (size_t)(b * DD + d) * LL + kb + f8 * 8;
        *reinterpret_cast<uint4*>(&g_vt_hi[o]) = hi.u;
        *reinterpret_cast<uint4*>(&g_vt_lo[o]) = lo.u;
    }
}

// ---------------------------------------------------------------------------
// Kernel 2: scores via mma.sync bf16 hi/lo.  E = exp(q' k^T) -> attn;
// column sums (over q) -> g_colsum atomics.
// grid (L/128, L/128, B), 256 thr (8 warps: wm=w&3 rows, wn=w>>2 cols).
// ---------------------------------------------------------------------------
__global__ __launch_bounds__(256) void scores_mma(float* __restrict__ attn)
{
    extern __shared__ char smem[];
    const uint32_t sb = smem_u32(smem);
    const int t = threadIdx.x, l = t & 31, w = t >> 5;
    const int wm = w & 3, wn = w >> 2;
    const int b = blockIdx.z, qb = blockIdx.y * 128, kb = blockIdx.x * 128;

    // ---- load q,k fp32; split into bf16 hi/lo swizzled tiles ----
    {
        const float* qp = g_q + (size_t)(b * LL + qb) * DD;
        const float* kp = g_k + (size_t)(b * LL + kb) * DD;
#pragma unroll
        for (int s = 0; s < 4; ++s) {
            int u = t + 256 * s;                 // 0..1023
            int r = u >> 3, c16 = u & 7;
            uint32_t off = swzo(r, c16);
            float4 a = *reinterpret_cast<const float4*>(&qp[(size_t)r * DD + c16 * 8]);
            float4 c = *reinterpret_cast<const float4*>(&qp[(size_t)r * DD + c16 * 8 + 4]);
            uint4 hi, lo;
            split8(a, c, hi, lo);
            *(uint4*)(smem + S_QH + off) = hi;
            *(uint4*)(smem + S_QL + off) = lo;
            a = *reinterpret_cast<const float4*>(&kp[(size_t)r * DD + c16 * 8]);
            c = *reinterpret_cast<const float4*>(&kp[(size_t)r * DD + c16 * 8 + 4]);
            split8(a, c, hi, lo);
            *(uint4*)(smem + S_KH + off) = hi;
            *(uint4*)(smem + S_KL + off) = lo;
        }
    }
    __syncthreads();

    // ---- mma: each warp 32(m) x 64(n), 3 passes hi/lo ----
    float acc[2][8][4];
#pragma unroll
    for (int mt = 0; mt < 2; ++mt)
#pragma unroll
        for (int nt = 0; nt < 8; ++nt)
#pragma unroll
            for (int j = 0; j < 4; ++j) acc[mt][nt][j] = 0.f;

#pragma unroll
    for (int ks = 0; ks < 4; ++ks) {
        // A fragments (q): lane i -> row (i&15), k-half (i>>4)
        uint32_t qh[2][4], ql[2][4];
        {
            uint32_t aoff = swzo(wm * 32 + (l & 15), ks * 2 + (l >> 4));
            ldsm4(qh[0], sb + S_QH + aoff);
            ldsm4(qh[1], sb + S_QH + aoff + 2048);   // +16 rows
            ldsm4(ql[0], sb + S_QL + aoff);
            ldsm4(ql[1], sb + S_QL + aoff + 2048);
        }
        // B fragments (k'): x4 loads 2 n-tiles (b0,b1 each)
        uint32_t kh[8][2], kl[8][2];
        {
            uint32_t boff = swzo(wn * 64 + ((l >> 4) << 3) + (l & 7),
                                 ks * 2 + ((l >> 3) & 1));
#pragma unroll
            for (int pg = 0; pg < 4; ++pg) {
                uint32_t r4[4];
                ldsm4(r4, sb + S_KH + boff + pg * 2048);
                kh[pg * 2][0] = r4[0]; kh[pg * 2][1] = r4[1];
                kh[pg * 2 + 1][0] = r4[2]; kh[pg * 2 + 1][1] = r4[3];
                ldsm4(r4, sb + S_KL + boff + pg * 2048);
                kl[pg * 2][0] = r4[0]; kl[pg * 2][1] = r4[1];
                kl[pg * 2 + 1][0] = r4[2]; kl[pg * 2 + 1][1] = r4[3];
            }
        }
#pragma unroll
        for (int mt = 0; mt < 2; ++mt)
#pragma unroll
            for (int nt = 0; nt < 8; ++nt) {
                mma16816(acc[mt][nt], qh[mt], kh[nt]);
                mma16816(acc[mt][nt], qh[mt], kl[nt]);
                mma16816(acc[mt][nt], ql[mt], kh[nt]);
            }
    }

    // ---- exp + store + column sums ----
    float* colred = (float*)(smem + S_RED);      // [4 wm][128 col]
    float* ap = attn + ((size_t)(b * LL + qb)) * LL + kb;

#pragma unroll
    for (int nt = 0; nt < 8; ++nt) {
        int col = wn * 64 + nt * 8 + 2 * (l & 3);
        float cs0 = 0.f, cs1 = 0.f;
#pragma unroll
        for (int mt = 0; mt < 2; ++mt) {
            int row = wm * 32 + mt * 16 + (l >> 2);
            float e0 = __expf(acc[mt][nt][0]);
            float e1 = __expf(acc[mt][nt][1]);
            float e2 = __expf(acc[mt][nt][2]);
            float e3 = __expf(acc[mt][nt][3]);
            *reinterpret_cast<float2*>(&ap[(size_t)row * LL + col]) = make_float2(e0, e1);
            *reinterpret_cast<float2*>(&ap[(size_t)(row + 8) * LL + col]) = make_float2(e2, e3);
            cs0 += e0 + e2;
            cs1 += e1 + e3;
        }
#pragma unroll
        for (int m = 4; m < 32; m <<= 1) {
            cs0 += __shfl_xor_sync(0xffffffffu, cs0, m);
            cs1 += __shfl_xor_sync(0xffffffffu, cs1, m);
        }
        if (l < 4) {
            colred[wm * 128 + wn * 64 + nt * 8 + 2 * l + 0] = cs0;
            colred[wm * 128 + wn * 64 + nt * 8 + 2 * l + 1] = cs1;
        }
    }
    __syncthreads();
    if (t < 128) {
        float s = colred[t] + colred[128 + t] + colred[256 + t] + colred[384 + t];
        atomicAdd(&g_colsum[b * LL + kb + t], s);
    }
}

// ---------------------------------------------------------------------------
// Kernel 3: av via mma.sync.  A = E/colsum written in place; vals = A @ v.
// grid (L/128, KSPLIT, B), 256 thr (8 warps x 16 q-rows each).
// ---------------------------------------------------------------------------
__global__ __launch_bounds__(256) void av_mma(float* __restrict__ attn)
{
    extern __shared__ char smem[];
    const uint32_t sb = smem_u32(smem);
    const int t = threadIdx.x, l = t & 31, w = t >> 5;
    const int b = blockIdx.z, split = blockIdx.y, qb = blockIdx.x * 128;
    const int kBeg = split * (LL / KSPLIT);

    float* abase = attn + ((size_t)(b * LL + qb)) * LL;
    const float* cs = g_colsum + b * LL;
    float* inv_s = (float*)(smem + A_INV);

    float acc[8][4];
#pragma unroll
    for (int nt = 0; nt < 8; ++nt)
#pragma unroll
        for (int j = 0; j < 4; ++j) acc[nt][j] = 0.f;

    for (int ci = 0; ci < (LL / KSPLIT) / 64; ++ci) {
        const int kc = kBeg + ci * 64;
        if (t < 64) inv_s[t] = 1.f / cs[kc + t];
        __syncthreads();

        // normalize E -> A (write back) + split A to bf16 hi/lo smem
#pragma unroll
        for (int s = 0; s < 4; ++s) {
            int u = t + 256 * s;                 // 0..1023
            int r = u >> 3, c16 = u & 7;
            float* gp = &abase[(size_t)r * LL + kc + c16 * 8];
            float4 e0 = *reinterpret_cast<const float4*>(gp);
            float4 e1 = *reinterpret_cast<const float4*>(gp + 4);
            float4 i0 = *reinterpret_cast<const float4*>(&inv_s[c16 * 8]);
            float4 i1 = *reinterpret_cast<const float4*>(&inv_s[c16 * 8 + 4]);
            e0.x *= i0.x; e0.y *= i0.y; e0.z *= i0.z; e0.w *= i0.w;
            e1.x *= i1.x; e1.y *= i1.y; e1.z *= i1.z; e1.w *= i1.w;
            *reinterpret_cast<float4*>(gp) = e0;
            *reinterpret_cast<float4*>(gp + 4) = e1;
            uint4 hi, lo;
            split8(e0, e1, hi, lo);
            uint32_t off = swzo(r, c16);
            *(uint4*)(smem + A_AH + off) = hi;
            *(uint4*)(smem + A_AL + off) = lo;
        }
        // copy v^T chunk [64 d][64 k] bf16 hi/lo into smem
#pragma unroll
        for (int s = 0; s < 2; ++s) {
            int u = t + 256 * s;                 // 0..511
            int d = u >> 3, c16 = u & 7;
            size_t go = (size_t)(b * DD + d) * LL + kc + c16 * 8;
            uint32_t off = swzo(d, c16);
            *(uint4*)(smem + A_VH + off) = *reinterpret_cast<const uint4*>(&g_vt_hi[go]);
            *(uint4*)(smem + A_VL + off) = *reinterpret_cast<const uint4*>(&g_vt_lo[go]);
        }
        __syncthreads();

#pragma unroll
        for (int ks = 0; ks < 4; ++ks) {
            uint32_t ah[4], al[4];
            {
                uint32_t aoff = swzo(w * 16 + (l & 15), ks * 2 + (l >> 4));
                ldsm4(ah, sb + A_AH + aoff);
                ldsm4(al, sb + A_AL + aoff);
            }
            uint32_t vh[8][2], vl[8][2];
            {
                uint32_t boff = swzo(((l >> 4) << 3) + (l & 7), ks * 2 + ((l >> 3) & 1));
#pragma unroll
                for (int pg = 0; pg < 4; ++pg) {
                    uint32_t r4[4];
                    ldsm4(r4, sb + A_VH + boff + pg * 2048);
                    vh[pg * 2][0] = r4[0]; vh[pg * 2][1] = r4[1];
                    vh[pg * 2 + 1][0] = r4[2]; vh[pg * 2 + 1][1] = r4[3];
                    ldsm4(r4, sb + A_VL + boff + pg * 2048);
                    vl[pg * 2][0] = r4[0]; vl[pg * 2][1] = r4[1];
                    vl[pg * 2 + 1][0] = r4[2]; vl[pg * 2 + 1][1] = r4[3];
                }
            }
#pragma unroll
            for (int nt = 0; nt < 8; ++nt) {
                mma16816(acc[nt], ah, vh[nt]);
                mma16816(acc[nt], ah, vl[nt]);
                mma16816(acc[nt], al, vh[nt]);
            }
        }
        __syncthreads();
    }

    // epilogue: warp rows w*16 + {l>>2, +8}, cols nt*8 + 2*(l&3)
#pragma unroll
    for (int nt = 0; nt < 8; ++nt) {
        int col = nt * 8 + 2 * (l & 3);
        size_t row = (size_t)(b * LL + qb + w * 16 + (l >> 2));
        *reinterpret_cast<float2*>(&g_vals[split][row * DD + col]) =
            make_float2(acc[nt][0], acc[nt][1]);
        *reinterpret_cast<float2*>(&g_vals[split][(row + 8) * DD + col]) =
            make_float2(acc[nt][2], acc[nt][3]);
    }
}

// ---------------------------------------------------------------------------
// Kernel 4: out = (sum_p g_vals[p]) @ Wo + bo. grid (MM/128, OUT/128), 256 thr.
// ---------------------------------------------------------------------------
__global__ __launch_bounds__(256) void out_kernel(
    const float* __restrict__ Wo, const float* __restrict__ bo,
    float* __restrict__ outp)
{
    const int mb = blockIdx.x * 128;
    const int nb = blockIdx.y * 128;
    const int t  = threadIdx.x;
    const int tx = t & 15, ty = t >> 4;

    __shared__ float vt[64 * 128];
    __shared__ float ws[64 * 128];

    {
        const int dq = t & 15, rb = t >> 4;
#pragma unroll
        for (int s = 0; s < 8; ++s) {
            int r = rb + s * 16;
            size_t base = (size_t)(mb + r) * DD + 4 * dq;
            float4 v0 = *reinterpret_cast<const float4*>(&g_vals[0][base]);
            float4 v1 = *reinterpret_cast<const float4*>(&g_vals[1][base]);
            float4 v2 = *reinterpret_cast<const float4*>(&g_vals[2][base]);
            float4 v3 = *reinterpret_cast<const float4*>(&g_vals[3][base]);
            float4 v = make_float4(v0.x + v1.x + v2.x + v3.x,
                                   v0.y + v1.y + v2.y + v3.y,
                                   v0.z + v1.z + v2.z + v3.z,
                                   v0.w + v1.w + v2.w + v3.w);
            vt[swz(4 * dq + 0, r)] = v.x; vt[swz(4 * dq + 1, r)] = v.y;
            vt[swz(4 * dq + 2, r)] = v.z; vt[swz(4 * dq + 3, r)] = v.w;
        }
        const int nq = t & 31, kb2 = t >> 5;
#pragma unroll
        for (int s = 0; s < 8; ++s) {
            int kr = kb2 + s * 8;
            *reinterpret_cast<float4*>(&ws[kr * 128 + 4 * nq]) =
                *reinterpret_cast<const float4*>(&Wo[(size_t)kr * OUT + nb + 4 * nq]);
        }
    }
    __syncthreads();

    u64 acc[32];
#pragma unroll
    for (int i = 0; i < 32; ++i) acc[i] = 0ull;

#pragma unroll 8
    for (int k = 0; k < 64; ++k) {
        float4 a0 = *reinterpret_cast<const float4*>(&vt[swz(k, 4 * ty)]);
        float4 a1 = *reinterpret_cast<const float4*>(&vt[swz(k, 64 + 4 * ty)]);
        float4 b0 = *reinterpret_cast<const float4*>(&ws[k * 128 + 4 * tx]);
        float4 b1 = *reinterpret_cast<const float4*>(&ws[k * 128 + 64 + 4 * tx]);
        rank1(acc, a0, a1, b0, b1);
    }

    float4 bo0 = *reinterpret_cast<const float4*>(&bo[nb + 4 * tx]);
    float4 bo1 = *reinterpret_cast<const float4*>(&bo[nb + 64 + 4 * tx]);
#pragma unroll
    for (int i = 0; i < 8; ++i) {
        int r = (i < 4) ? (4 * ty + i) : (64 + 4 * ty + (i - 4));
        float2 p0 = up2(acc[i * 4 + 0]), p1 = up2(acc[i * 4 + 1]);
        float2 p2 = up2(acc[i * 4 + 2]), p3 = up2(acc[i * 4 + 3]);
        float4 o0 = make_float4(p0.x + bo0.x, p0.y + bo0.y, p1.x + bo0.z, p1.y + bo0.w);
        float4 o1 = make_float4(p2.x + bo1.x, p2.y + bo1.y, p3.x + bo1.z, p3.y + bo1.w);
        *reinterpret_cast<float4*>(&outp[(size_t)(mb + r) * OUT + nb + 4 * tx]) = o0;
        *reinterpret_cast<float4*>(&outp[(size_t)(mb + r) * OUT + nb + 64 + 4 * tx]) = o1;
    }
}

// ---------------------------------------------------------------------------
extern "C" void kernel_launch(void* const* d_in, const int* in_sizes, int n_in,
                              void* d_out, int out_size)
{
    const float* x  = (const float*)d_in[0];
    const float* Wq = (const float*)d_in[1];
    const float* bq = (const float*)d_in[2];
    const float* Wk = (const float*)d_in[3];
    const float* bk = (const float*)d_in[4];
    const float* Wv = (const float*)d_in[5];
    const float* bv = (const float*)d_in[6];
    const float* Wo = (const float*)d_in[7];
    const float* bo = (const float*)d_in[8];

    float* outp = (float*)d_out;                   // [B, L, OUT]
    float* attn = outp + (size_t)BB * LL * OUT;    // [B, L, L]

    cudaFuncSetAttribute(scores_mma, cudaFuncAttributeMaxDynamicSharedMemorySize, S_SMEM);
    cudaFuncSetAttribute(av_mma,     cudaFuncAttributeMaxDynamicSharedMemorySize, A_SMEM);

    qkv_kernel<<<dim3(MM / 128, 3), 128>>>(x, Wq, bq, Wk, bk, Wv, bv);
    vtrans_kernel<<<dim3(LL / 64, BB), 256>>>();
    scores_mma<<<dim3(LL / 128, LL / 128, BB), 256, S_SMEM>>>(attn);
    av_mma<<<dim3(LL / 128, KSPLIT, BB), 256, A_SMEM>>>(attn);
    out_kernel<<<dim3(MM / 128, OUT / 128), 256>>>(Wo, bo, outp);
}

// round 6
// speedup vs baseline: 2.5677x; 1.1322x over previous
#include <cuda_runtime.h>
#include <cuda_bf16.h>
#include <cstdint>

// ---------------------------------------------------------------------------
// AttentionBlock, Round 5: recompute-S fused attention.
//  k1  qkv      : q,k,v projections; q,k stored as bf16 hi/lo; q pre-scaled.
//  k1b vtrans   : v -> v^T bf16 hi/lo.
//  k2  scores_sum: colsum[b,k] = sum_q exp(S) via 3-pass HMMA (no store).
//  k3  av_fused : recompute S (identical), P=exp(S)*inv, write A to attn,
//                 O += P@V via register fragment reuse (3-pass).
//  k4  out      : out = (sum partials) @ Wo + bo (f32x2).
// B=4, L=4096, IN=512, D=64, OUT=512.  Outputs: (out, attention).
// ---------------------------------------------------------------------------

namespace {
constexpr int BB  = 4;
constexpr int LL  = 4096;
constexpr int IN  = 512;
constexpr int DD  = 64;
constexpr int OUT = 512;
constexpr int MM  = BB * LL;
constexpr int KSPLIT = 4;
constexpr int NPART = KSPLIT * 2;            // 2 wn-halves per split
constexpr float SCALE = 0.125f;

// scores_sum smem
constexpr uint32_t S_QH = 0, S_QL = 16384, S_KH = 32768, S_KL = 49152,
                   S_RED = 65536, S_SMEM = 65536 + 2048;
// av_fused smem
constexpr uint32_t F_QH = 0, F_QL = 16384, F_KH = 32768, F_KL = 49152,
                   F_VH = 65536, F_VL = 81920, F_INV = 98304,
                   F_SMEM = 98304 + 512;
}

typedef unsigned long long u64;

// ------------------------------- helpers -----------------------------------
__device__ __forceinline__ uint32_t smem_u32(const void* p) {
    uint32_t a;
    asm("{ .reg .u64 t; cvta.to.shared.u64 t, %1; cvt.u32.u64 %0, t; }" : "=r"(a) : "l"(p));
    return a;
}
// swizzled byte offset in a [rows][64 bf16] tile (128B rows, 16B units)
__device__ __forceinline__ uint32_t swzo(int r, int c16) {
    return (uint32_t)(r * 128 + ((c16 ^ (r & 7)) << 4));
}
__device__ __forceinline__ void ldsm4(uint32_t r[4], uint32_t addr) {
    asm volatile("ldmatrix.sync.aligned.m8n8.x4.shared.b16 {%0,%1,%2,%3}, [%4];"
        : "=r"(r[0]), "=r"(r[1]), "=r"(r[2]), "=r"(r[3]) : "r"(addr));
}
__device__ __forceinline__ void mma16816(float c[4], const uint32_t a[4], const uint32_t b[2]) {
    asm volatile("mma.sync.aligned.m16n8k16.row.col.f32.bf16.bf16.f32 "
        "{%0,%1,%2,%3}, {%4,%5,%6,%7}, {%8,%9}, {%0,%1,%2,%3};"
        : "+f"(c[0]), "+f"(c[1]), "+f"(c[2]), "+f"(c[3])
        : "r"(a[0]), "r"(a[1]), "r"(a[2]), "r"(a[3]), "r"(b[0]), "r"(b[1]));
}
__device__ __forceinline__ uint32_t pk_bf(float a, float b) {
    return (uint32_t)__bfloat16_as_ushort(__float2bfloat16(a)) |
           ((uint32_t)__bfloat16_as_ushort(__float2bfloat16(b)) << 16);
}
__device__ __forceinline__ void split1(float v, float& hi, float& lo) {
    __nv_bfloat16 h = __float2bfloat16(v);
    hi = __bfloat162float(h);
    lo = v - hi;
}

// ---------------------------- f32x2 (qkv / out) ----------------------------
__device__ __forceinline__ void fma2(u64 &d, u64 a, u64 b) {
    asm("fma.rn.f32x2 %0, %1, %2, %0;" : "+l"(d) : "l"(a), "l"(b));
}
__device__ __forceinline__ u64 dup2(float a) {
    u64 r; asm("mov.b64 %0, {%1, %1};" : "=l"(r) : "f"(a)); return r;
}
__device__ __forceinline__ u64 pk2(float lo, float hi) {
    u64 r; asm("mov.b64 %0, {%1, %2};" : "=l"(r) : "f"(lo), "f"(hi)); return r;
}
__device__ __forceinline__ float2 up2(u64 v) {
    float2 r; asm("mov.b64 {%0, %1}, %2;" : "=f"(r.x), "=f"(r.y) : "l"(v)); return r;
}
__device__ __forceinline__ int swz(int d, int c) { return d * 128 + (c ^ (d & 28)); }

__device__ __forceinline__ void rank1(u64* acc, float4 a0, float4 a1,
                                      float4 b0, float4 b1)
{
    u64 bp0 = pk2(b0.x, b0.y), bp1 = pk2(b0.z, b0.w);
    u64 bp2 = pk2(b1.x, b1.y), bp3 = pk2(b1.z, b1.w);
    float av[8] = {a0.x, a0.y, a0.z, a0.w, a1.x, a1.y, a1.z, a1.w};
#pragma unroll
    for (int i = 0; i < 8; ++i) {
        u64 ad = dup2(av[i]);
        fma2(acc[i * 4 + 0], ad, bp0);
        fma2(acc[i * 4 + 1], ad, bp1);
        fma2(acc[i * 4 + 2], ad, bp2);
        fma2(acc[i * 4 + 3], ad, bp3);
    }
}

// ------------------------------ device scratch -----------------------------
__device__ __nv_bfloat16 g_qh[MM * DD], g_ql[MM * DD];   // q (pre-scaled) hi/lo
__device__ __nv_bfloat16 g_kh[MM * DD], g_kl[MM * DD];   // k hi/lo
__device__ float g_v[MM * DD];
__device__ float g_colsum[MM];
__device__ float g_vals[NPART][MM * DD];
__device__ __nv_bfloat16 g_vt_hi[BB * DD * LL];          // v^T hi [b][d][k]
__device__ __nv_bfloat16 g_vt_lo[BB * DD * LL];

// ---------------------------------------------------------------------------
// Kernel 1: QKV projection (f32x2). grid (MM/128, 3), 128 thr.
// ---------------------------------------------------------------------------
__global__ __launch_bounds__(128) void qkv_kernel(
    const float* __restrict__ x,
    const float* __restrict__ Wq, const float* __restrict__ bq,
    const float* __restrict__ Wk, const float* __restrict__ bk,
    const float* __restrict__ Wv, const float* __restrict__ bv)
{
    const int t = threadIdx.x;
    const int gid = (blockIdx.y * gridDim.x + blockIdx.x) * 128 + t;
    if (gid < MM) g_colsum[gid] = 0.f;

    const float* W; const float* bias; float oscale;
    __nv_bfloat16 *oh = nullptr, *ol = nullptr;
    if (blockIdx.y == 0)      { W = Wq; bias = bq; oh = g_qh; ol = g_ql; oscale = SCALE; }
    else if (blockIdx.y == 1) { W = Wk; bias = bk; oh = g_kh; ol = g_kl; oscale = 1.f; }
    else                      { W = Wv; bias = bv; oscale = 1.f; }
    const bool isv = (blockIdx.y == 2);

    const int mb = blockIdx.x * 128;
    const int tx = t & 7, ty = t >> 3;

    __shared__ float xs[64 * 128];
    __shared__ float ws[64 * 64];

    u64 acc[32];
#pragma unroll
    for (int i = 0; i < 32; ++i) acc[i] = 0ull;

    const int dq = t & 15, rb = t >> 4;

    for (int kc = 0; kc < IN; kc += 64) {
        __syncthreads();
#pragma unroll
        for (int s = 0; s < 16; ++s) {
            int r = rb + s * 8;
            float4 v = *reinterpret_cast<const float4*>(&x[(size_t)(mb + r) * IN + kc + 4 * dq]);
            xs[swz(4 * dq + 0, r)] = v.x;
            xs[swz(4 * dq + 1, r)] = v.y;
            xs[swz(4 * dq + 2, r)] = v.z;
            xs[swz(4 * dq + 3, r)] = v.w;
        }
#pragma unroll
        for (int s = 0; s < 8; ++s) {
            int kr = rb + s * 8;
            *reinterpret_cast<float4*>(&ws[kr * 64 + 4 * dq]) =
                *reinterpret_cast<const float4*>(&W[(size_t)(kc + kr) * DD + 4 * dq]);
        }
        __syncthreads();
#pragma unroll 8
        for (int k = 0; k < 64; ++k) {
            float4 a0 = *reinterpret_cast<const float4*>(&xs[swz(k, 4 * ty)]);
            float4 a1 = *reinterpret_cast<const float4*>(&xs[swz(k, 64 + 4 * ty)]);
            float4 b0 = *reinterpret_cast<const float4*>(&ws[k * 64 + 4 * tx]);
            float4 b1 = *reinterpret_cast<const float4*>(&ws[k * 64 + 32 + 4 * tx]);
            rank1(acc, a0, a1, b0, b1);
        }
    }
    float4 bias0 = *reinterpret_cast<const float4*>(&bias[4 * tx]);
    float4 bias1 = *reinterpret_cast<const float4*>(&bias[32 + 4 * tx]);
#pragma unroll
    for (int i = 0; i < 8; ++i) {
        int r = (i < 4) ? (4 * ty + i) : (64 + 4 * ty + (i - 4));
        float2 p0 = up2(acc[i * 4 + 0]), p1 = up2(acc[i * 4 + 1]);
        float2 p2 = up2(acc[i * 4 + 2]), p3 = up2(acc[i * 4 + 3]);
        float f[8] = {(p0.x + bias0.x) * oscale, (p0.y + bias0.y) * oscale,
                      (p1.x + bias0.z) * oscale, (p1.y + bias0.w) * oscale,
                      (p2.x + bias1.x) * oscale, (p2.y + bias1.y) * oscale,
                      (p3.x + bias1.z) * oscale, (p3.y + bias1.w) * oscale};
        if (isv) {
            *reinterpret_cast<float4*>(&g_v[(size_t)(mb + r) * DD + 4 * tx]) =
                make_float4(f[0], f[1], f[2], f[3]);
            *reinterpret_cast<float4*>(&g_v[(size_t)(mb + r) * DD + 32 + 4 * tx]) =
                make_float4(f[4], f[5], f[6], f[7]);
        } else {
            float h[8], l[8];
#pragma unroll
            for (int j = 0; j < 8; ++j) split1(f[j], h[j], l[j]);
            size_t o0 = (size_t)(mb + r) * DD + 4 * tx;
            size_t o1 = o0 + 32;
            *reinterpret_cast<uint2*>(&oh[o0]) = make_uint2(pk_bf(h[0], h[1]), pk_bf(h[2], h[3]));
            *reinterpret_cast<uint2*>(&ol[o0]) = make_uint2(pk_bf(l[0], l[1]), pk_bf(l[2], l[3]));
            *reinterpret_cast<uint2*>(&oh[o1]) = make_uint2(pk_bf(h[4], h[5]), pk_bf(h[6], h[7]));
            *reinterpret_cast<uint2*>(&ol[o1]) = make_uint2(pk_bf(l[4], l[5]), pk_bf(l[6], l[7]));
        }
    }
}

// ---------------------------------------------------------------------------
// Kernel 1b: v[b][k][d] -> bf16 hi/lo transposed g_vt[b][d][k].
// grid (LL/64, BB), 256 thr.
// ---------------------------------------------------------------------------
__global__ __launch_bounds__(256) void vtrans_kernel()
{
    const int b = blockIdx.y, kb = blockIdx.x * 64;
    const int t = threadIdx.x;
    __shared__ float tile[64][68];

    const int c4 = t & 15, r0 = t >> 4;
#pragma unroll
    for (int s = 0; s < 4; ++s) {
        int r = r0 + 16 * s;
        float4 v = *reinterpret_cast<const float4*>(&g_v[(size_t)(b * LL + kb + r) * DD + 4 * c4]);
        tile[r][4 * c4 + 0] = v.x; tile[r][4 * c4 + 1] = v.y;
        tile[r][4 * c4 + 2] = v.z; tile[r][4 * c4 + 3] = v.w;
    }
    __syncthreads();

    const int f8 = t & 7, d0 = t >> 3;
#pragma unroll
    for (int s = 0; s < 2; ++s) {
        int d = d0 + 32 * s;
        union { __nv_bfloat16 h[8]; uint4 u; } hi, lo;
#pragma unroll
        for (int j = 0; j < 8; ++j) {
            float v = tile[f8 * 8 + j][d];
            __nv_bfloat16 hb = __float2bfloat16(v);
            hi.h[j] = hb;
            lo.h[j] = __float2bfloat16(v - __bfloat162float(hb));
        }
        size_t o = (size_t)(b * DD + d) * LL + kb + f8 * 8;
        *reinterpret_cast<uint4*>(&g_vt_hi[o]) = hi.u;
        *reinterpret_cast<uint4*>(&g_vt_lo[o]) = lo.u;
    }
}

// ---------------------------------------------------------------------------
// Kernel 2: scores_sum.  colsum[b,k] += sum_q exp(S[q,k]); NO attn store.
// grid (L/128 kb, L/128 qb, B), 256 thr (wm=w&3 q-rows, wn=w>>2 k-cols).
// ---------------------------------------------------------------------------
__global__ __launch_bounds__(256) void scores_sum(void)
{
    extern __shared__ char smem[];
    const uint32_t sb = smem_u32(smem);
    const int t = threadIdx.x, l = t & 31, w = t >> 5;
    const int wm = w & 3, wn = w >> 2;
    const int b = blockIdx.z, qb = blockIdx.y * 128, kb = blockIdx.x * 128;

    // copy q,k bf16 hi/lo tiles into swizzled smem
    {
        const size_t qo = (size_t)(b * LL + qb) * DD;
        const size_t ko = (size_t)(b * LL + kb) * DD;
#pragma unroll
        for (int s = 0; s < 4; ++s) {
            int u = t + 256 * s;
            int r = u >> 3, c16 = u & 7;
            uint32_t off = swzo(r, c16);
            size_t gi = qo + (size_t)r * DD + c16 * 8;
            *(uint4*)(smem + S_QH + off) = *reinterpret_cast<const uint4*>(&g_qh[gi]);
            *(uint4*)(smem + S_QL + off) = *reinterpret_cast<const uint4*>(&g_ql[gi]);
            gi = ko + (size_t)r * DD + c16 * 8;
            *(uint4*)(smem + S_KH + off) = *reinterpret_cast<const uint4*>(&g_kh[gi]);
            *(uint4*)(smem + S_KL + off) = *reinterpret_cast<const uint4*>(&g_kl[gi]);
        }
    }
    __syncthreads();

    float acc[2][8][4];
#pragma unroll
    for (int mt = 0; mt < 2; ++mt)
#pragma unroll
        for (int nt = 0; nt < 8; ++nt)
#pragma unroll
            for (int j = 0; j < 4; ++j) acc[mt][nt][j] = 0.f;

#pragma unroll
    for (int ks = 0; ks < 4; ++ks) {
        uint32_t qh[2][4], ql[2][4];
        {
            uint32_t aoff = swzo(wm * 32 + (l & 15), ks * 2 + (l >> 4));
            ldsm4(qh[0], sb + S_QH + aoff);
            ldsm4(qh[1], sb + S_QH + aoff + 2048);
            ldsm4(ql[0], sb + S_QL + aoff);
            ldsm4(ql[1], sb + S_QL + aoff + 2048);
        }
        uint32_t kh[8][2], kl[8][2];
        {
            uint32_t boff = swzo(wn * 64 + ((l >> 4) << 3) + (l & 7),
                                 ks * 2 + ((l >> 3) & 1));
#pragma unroll
            for (int pg = 0; pg < 4; ++pg) {
                uint32_t r4[4];
                ldsm4(r4, sb + S_KH + boff + pg * 2048);
                kh[pg * 2][0] = r4[0]; kh[pg * 2][1] = r4[1];
                kh[pg * 2 + 1][0] = r4[2]; kh[pg * 2 + 1][1] = r4[3];
                ldsm4(r4, sb + S_KL + boff + pg * 2048);
                kl[pg * 2][0] = r4[0]; kl[pg * 2][1] = r4[1];
                kl[pg * 2 + 1][0] = r4[2]; kl[pg * 2 + 1][1] = r4[3];
            }
        }
#pragma unroll
        for (int mt = 0; mt < 2; ++mt)
#pragma unroll
            for (int nt = 0; nt < 8; ++nt) {
                mma16816(acc[mt][nt], qh[mt], kh[nt]);
                mma16816(acc[mt][nt], qh[mt], kl[nt]);
                mma16816(acc[mt][nt], ql[mt], kh[nt]);
            }
    }

    // exp + column-sum reduction (no store of E)
    float* colred = (float*)(smem + S_RED);
#pragma unroll
    for (int nt = 0; nt < 8; ++nt) {
        float cs0 = 0.f, cs1 = 0.f;
#pragma unroll
        for (int mt = 0; mt < 2; ++mt) {
            cs0 += __expf(acc[mt][nt][0]) + __expf(acc[mt][nt][2]);
            cs1 += __expf(acc[mt][nt][1]) + __expf(acc[mt][nt][3]);
        }
#pragma unroll
        for (int m = 4; m < 32; m <<= 1) {
            cs0 += __shfl_xor_sync(0xffffffffu, cs0, m);
            cs1 += __shfl_xor_sync(0xffffffffu, cs1, m);
        }
        if (l < 4) {
            colred[wm * 128 + wn * 64 + nt * 8 + 2 * l + 0] = cs0;
            colred[wm * 128 + wn * 64 + nt * 8 + 2 * l + 1] = cs1;
        }
    }
    __syncthreads();
    if (t < 128) {
        float s = colred[t] + colred[128 + t] + colred[256 + t] + colred[384 + t];
        atomicAdd(&g_colsum[b * LL + kb + t], s);
    }
}

// ---------------------------------------------------------------------------
// Kernel 3: av_fused.  Recompute S (identical op order), P = exp(S)*inv,
// write A to attn, O += P@V via register fragment reuse.
// grid (L/128 qtiles, KSPLIT, B), 256 thr.
// ---------------------------------------------------------------------------
__global__ __launch_bounds__(256) void av_fused(float* __restrict__ attn)
{
    extern __shared__ char smem[];
    const uint32_t sb = smem_u32(smem);
    const int t = threadIdx.x, l = t & 31, w = t >> 5;
    const int wm = w & 3, wn = w >> 2;                 // wn in {0,1}
    const int b = blockIdx.z, split = blockIdx.y, qb = blockIdx.x * 128;
    const int kBeg = split * (LL / KSPLIT);

    float* inv_s = (float*)(smem + F_INV);
    const float* cs = g_colsum + b * LL;
    float* ap = attn + (size_t)(b * LL + qb) * LL;

    // load q tiles once
    {
        const size_t qo = (size_t)(b * LL + qb) * DD;
#pragma unroll
        for (int s = 0; s < 4; ++s) {
            int u = t + 256 * s;
            int r = u >> 3, c16 = u & 7;
            uint32_t off = swzo(r, c16);
            size_t gi = qo + (size_t)r * DD + c16 * 8;
            *(uint4*)(smem + F_QH + off) = *reinterpret_cast<const uint4*>(&g_qh[gi]);
            *(uint4*)(smem + F_QL + off) = *reinterpret_cast<const uint4*>(&g_ql[gi]);
        }
    }

    float o[2][8][4];
#pragma unroll
    for (int mt = 0; mt < 2; ++mt)
#pragma unroll
        for (int nt = 0; nt < 8; ++nt)
#pragma unroll
            for (int j = 0; j < 4; ++j) o[mt][nt][j] = 0.f;

    for (int ci = 0; ci < (LL / KSPLIT) / 128; ++ci) {
        const int kc = kBeg + ci * 128;
        __syncthreads();                               // smem reuse guard
        if (t < 128) inv_s[t] = 1.f / cs[kc + t];
        // k tiles [128 rows][64 d] hi/lo
        {
            const size_t ko = (size_t)(b * LL + kc) * DD;
#pragma unroll
            for (int s = 0; s < 4; ++s) {
                int u = t + 256 * s;
                int r = u >> 3, c16 = u & 7;
                uint32_t off = swzo(r, c16);
                size_t gi = ko + (size_t)r * DD + c16 * 8;
                *(uint4*)(smem + F_KH + off) = *reinterpret_cast<const uint4*>(&g_kh[gi]);
                *(uint4*)(smem + F_KL + off) = *reinterpret_cast<const uint4*>(&g_kl[gi]);
            }
        }
        // v^T tiles [2 halves][64 d][64 k] hi/lo
        {
#pragma unroll
            for (int s = 0; s < 4; ++s) {
                int u = t + 256 * s;                   // 0..1023
                int half = u >> 9, rem = u & 511;
                int d = rem >> 3, c16 = rem & 7;
                uint32_t off = half * 8192 + swzo(d, c16);
                size_t gi = (size_t)(b * DD + d) * LL + kc + half * 64 + c16 * 8;
                *(uint4*)(smem + F_VH + off) = *reinterpret_cast<const uint4*>(&g_vt_hi[gi]);
                *(uint4*)(smem + F_VL + off) = *reinterpret_cast<const uint4*>(&g_vt_lo[gi]);
            }
        }
        __syncthreads();

        // ---- S = q k^T (identical op order to scores_sum) ----
        float acc[2][8][4];
#pragma unroll
        for (int mt = 0; mt < 2; ++mt)
#pragma unroll
            for (int nt = 0; nt < 8; ++nt)
#pragma unroll
                for (int j = 0; j < 4; ++j) acc[mt][nt][j] = 0.f;

#pragma unroll
        for (int ks = 0; ks < 4; ++ks) {
            uint32_t qh[2][4], ql[2][4];
            {
                uint32_t aoff = swzo(wm * 32 + (l & 15), ks * 2 + (l >> 4));
                ldsm4(qh[0], sb + F_QH + aoff);
                ldsm4(qh[1], sb + F_QH + aoff + 2048);
                ldsm4(ql[0], sb + F_QL + aoff);
                ldsm4(ql[1], sb + F_QL + aoff + 2048);
            }
            uint32_t kh[8][2], kl[8][2];
            {
                uint32_t boff = swzo(wn * 64 + ((l >> 4) << 3) + (l & 7),
                                     ks * 2 + ((l >> 3) & 1));
#pragma unroll
                for (int pg = 0; pg < 4; ++pg) {
                    uint32_t r4[4];
                    ldsm4(r4, sb + F_KH + boff + pg * 2048);
                    kh[pg * 2][0] = r4[0]; kh[pg * 2][1] = r4[1];
                    kh[pg * 2 + 1][0] = r4[2]; kh[pg * 2 + 1][1] = r4[3];
                    ldsm4(r4, sb + F_KL + boff + pg * 2048);
                    kl[pg * 2][0] = r4[0]; kl[pg * 2][1] = r4[1];
                    kl[pg * 2 + 1][0] = r4[2]; kl[pg * 2 + 1][1] = r4[3];
                }
            }
#pragma unroll
            for (int mt = 0; mt < 2; ++mt)
#pragma unroll
                for (int nt = 0; nt < 8; ++nt) {
                    mma16816(acc[mt][nt], qh[mt], kh[nt]);
                    mma16816(acc[mt][nt], qh[mt], kl[nt]);
                    mma16816(acc[mt][nt], ql[mt], kh[nt]);
                }
        }

        // ---- P = exp(S)*inv ; store A ; pack P -> A-fragments ----
        uint32_t ph[2][4][4], pl[2][4][4];
#pragma unroll
        for (int mt = 0; mt < 2; ++mt) {
#pragma unroll
            for (int nt = 0; nt < 8; ++nt) {
                int lc = wn * 64 + nt * 8 + 2 * (l & 3);
                float i0 = inv_s[lc], i1 = inv_s[lc + 1];
                float e0 = __expf(acc[mt][nt][0]) * i0;
                float e1 = __expf(acc[mt][nt][1]) * i1;
                float e2 = __expf(acc[mt][nt][2]) * i0;
                float e3 = __expf(acc[mt][nt][3]) * i1;
                int r0 = wm * 32 + mt * 16 + (l >> 2);
                *reinterpret_cast<float2*>(&ap[(size_t)r0 * LL + kc + lc]) = make_float2(e0, e1);
                *reinterpret_cast<float2*>(&ap[(size_t)(r0 + 8) * LL + kc + lc]) = make_float2(e2, e3);
                float h0, l0, h1, l1, h2, l2, h3, l3;
                split1(e0, h0, l0); split1(e1, h1, l1);
                split1(e2, h2, l2); split1(e3, h3, l3);
                int kb2 = nt >> 1, base = (nt & 1) * 2;
                ph[mt][kb2][base + 0] = pk_bf(h0, h1);
                ph[mt][kb2][base + 1] = pk_bf(h2, h3);
                pl[mt][kb2][base + 0] = pk_bf(l0, l1);
                pl[mt][kb2][base + 1] = pk_bf(l2, l3);
            }
        }

        // ---- O += P @ V (3-pass) ----
#pragma unroll
        for (int kb2 = 0; kb2 < 4; ++kb2) {
            uint32_t vh[8][2], vl[8][2];
            {
                uint32_t boff = wn * 8192 + swzo(((l >> 4) << 3) + (l & 7),
                                                 kb2 * 2 + ((l >> 3) & 1));
#pragma unroll
                for (int pg = 0; pg < 4; ++pg) {
                    uint32_t r4[4];
                    ldsm4(r4, sb + F_VH + boff + pg * 2048);
                    vh[pg * 2][0] = r4[0]; vh[pg * 2][1] = r4[1];
                    vh[pg * 2 + 1][0] = r4[2]; vh[pg * 2 + 1][1] = r4[3];
                    ldsm4(r4, sb + F_VL + boff + pg * 2048);
                    vl[pg * 2][0] = r4[0]; vl[pg * 2][1] = r4[1];
                    vl[pg * 2 + 1][0] = r4[2]; vl[pg * 2 + 1][1] = r4[3];
                }
            }
#pragma unroll
            for (int mt = 0; mt < 2; ++mt)
#pragma unroll
                for (int nt = 0; nt < 8; ++nt) {
                    mma16816(o[mt][nt], ph[mt][kb2], vh[nt]);
                    mma16816(o[mt][nt], ph[mt][kb2], vl[nt]);
                    mma16816(o[mt][nt], pl[mt][kb2], vh[nt]);
                }
        }
    }

    // epilogue: O partial -> g_vals[split*2 + wn]
    float* gv = g_vals[split * 2 + wn];
#pragma unroll
    for (int mt = 0; mt < 2; ++mt)
#pragma unroll
        for (int nt = 0; nt < 8; ++nt) {
            int col = nt * 8 + 2 * (l & 3);
            size_t row = (size_t)(b * LL + qb + wm * 32 + mt * 16 + (l >> 2));
            *reinterpret_cast<float2*>(&gv[row * DD + col]) =
                make_float2(o[mt][nt][0], o[mt][nt][1]);
            *reinterpret_cast<float2*>(&gv[(row + 8) * DD + col]) =
                make_float2(o[mt][nt][2], o[mt][nt][3]);
        }
}

// ---------------------------------------------------------------------------
// Kernel 4: out = (sum_p g_vals[p]) @ Wo + bo. grid (MM/128, OUT/128), 256 thr.
// ---------------------------------------------------------------------------
__global__ __launch_bounds__(256) void out_kernel(
    const float* __restrict__ Wo, const float* __restrict__ bo,
    float* __restrict__ outp)
{
    const int mb = blockIdx.x * 128;
    const int nb = blockIdx.y * 128;
    const int t  = threadIdx.x;
    const int tx = t & 15, ty = t >> 4;

    __shared__ float vt[64 * 128];
    __shared__ float ws[64 * 128];

    {
        const int dq = t & 15, rb = t >> 4;
#pragma unroll
        for (int s = 0; s < 8; ++s) {
            int r = rb + s * 16;
            size_t base = (size_t)(mb + r) * DD + 4 * dq;
            float4 v = *reinterpret_cast<const float4*>(&g_vals[0][base]);
#pragma unroll
            for (int p = 1; p < NPART; ++p) {
                float4 u = *reinterpret_cast<const float4*>(&g_vals[p][base]);
                v.x += u.x; v.y += u.y; v.z += u.z; v.w += u.w;
            }
            vt[swz(4 * dq + 0, r)] = v.x; vt[swz(4 * dq + 1, r)] = v.y;
            vt[swz(4 * dq + 2, r)] = v.z; vt[swz(4 * dq + 3, r)] = v.w;
        }
        const int nq = t & 31, kb2 = t >> 5;
#pragma unroll
        for (int s = 0; s < 8; ++s) {
            int kr = kb2 + s * 8;
            *reinterpret_cast<float4*>(&ws[kr * 128 + 4 * nq]) =
                *reinterpret_cast<const float4*>(&Wo[(size_t)kr * OUT + nb + 4 * nq]);
        }
    }
    __syncthreads();

    u64 acc[32];
#pragma unroll
    for (int i = 0; i < 32; ++i) acc[i] = 0ull;

#pragma unroll 8
    for (int k = 0; k < 64; ++k) {
        float4 a0 = *reinterpret_cast<const float4*>(&vt[swz(k, 4 * ty)]);
        float4 a1 = *reinterpret_cast<const float4*>(&vt[swz(k, 64 + 4 * ty)]);
        float4 b0 = *reinterpret_cast<const float4*>(&ws[k * 128 + 4 * tx]);
        float4 b1 = *reinterpret_cast<const float4*>(&ws[k * 128 + 64 + 4 * tx]);
        rank1(acc, a0, a1, b0, b1);
    }

    float4 bo0 = *reinterpret_cast<const float4*>(&bo[nb + 4 * tx]);
    float4 bo1 = *reinterpret_cast<const float4*>(&bo[nb + 64 + 4 * tx]);
#pragma unroll
    for (int i = 0; i < 8; ++i) {
        int r = (i < 4) ? (4 * ty + i) : (64 + 4 * ty + (i - 4));
        float2 p0 = up2(acc[i * 4 + 0]), p1 = up2(acc[i * 4 + 1]);
        float2 p2 = up2(acc[i * 4 + 2]), p3 = up2(acc[i * 4 + 3]);
        float4 o0 = make_float4(p0.x + bo0.x, p0.y + bo0.y, p1.x + bo0.z, p1.y + bo0.w);
        float4 o1 = make_float4(p2.x + bo1.x, p2.y + bo1.y, p3.x + bo1.z, p3.y + bo1.w);
        *reinterpret_cast<float4*>(&outp[(size_t)(mb + r) * OUT + nb + 4 * tx]) = o0;
        *reinterpret_cast<float4*>(&outp[(size_t)(mb + r) * OUT + nb + 64 + 4 * tx]) = o1;
    }
}

// ---------------------------------------------------------------------------
extern "C" void kernel_launch(void* const* d_in, const int* in_sizes, int n_in,
                              void* d_out, int out_size)
{
    const float* x  = (const float*)d_in[0];
    const float* Wq = (const float*)d_in[1];
    const float* bq = (const float*)d_in[2];
    const float* Wk = (const float*)d_in[3];
    const float* bk = (const float*)d_in[4];
    const float* Wv = (const float*)d_in[5];
    const float* bv = (const float*)d_in[6];
    const float* Wo = (const float*)d_in[7];
    const float* bo = (const float*)d_in[8];

    float* outp = (float*)d_out;                   // [B, L, OUT]
    float* attn = outp + (size_t)BB * LL * OUT;    // [B, L, L]

    cudaFuncSetAttribute(scores_sum, cudaFuncAttributeMaxDynamicSharedMemorySize, S_SMEM);
    cudaFuncSetAttribute(av_fused,   cudaFuncAttributeMaxDynamicSharedMemorySize, F_SMEM);

    qkv_kernel<<<dim3(MM / 128, 3), 128>>>(x, Wq, bq, Wk, bk, Wv, bv);
    vtrans_kernel<<<dim3(LL / 64, BB), 256>>>();
    scores_sum<<<dim3(LL / 128, LL / 128, BB), 256, S_SMEM>>>();
    av_fused<<<dim3(LL / 128, KSPLIT, BB), 256, F_SMEM>>>(attn);
    out_kernel<<<dim3(MM / 128, OUT / 128), 256>>>(Wo, bo, outp);
}

// round 9
// speedup vs baseline: 2.9088x; 1.1328x over previous
#include <cuda_runtime.h>
#include <cuda_bf16.h>
#include <cstdint>

// ---------------------------------------------------------------------------
// AttentionBlock, Round 8 (re-run of R6 after infra failure):
// recompute-S fused attention, occupancy-tuned.
//  k1  qkv       : q,k,v projections; q,k stored bf16 hi/lo; q pre-scaled.
//  k1b vtrans    : v -> v^T bf16 hi/lo.
//  k2  scores_sum: colsum[b,k] = sum_q exp(S) via 3-pass HMMA (no store).
//  k3  av_fused  : recompute S, P=exp(S)*inv, write A, O += P@V (reg reuse).
//                  16 q-rows/warp, 64-col chunks, 2 CTAs/SM.
//  k4  out       : out = (sum partials) @ Wo + bo (f32x2).
// B=4, L=4096, IN=512, D=64, OUT=512.  Outputs: (out, attention).
// ---------------------------------------------------------------------------

namespace {
constexpr int BB  = 4;
constexpr int LL  = 4096;
constexpr int IN  = 512;
constexpr int DD  = 64;
constexpr int OUT = 512;
constexpr int MM  = BB * LL;
constexpr int KSPLIT = 4;
constexpr int NPART = KSPLIT;
constexpr float SCALE = 0.125f;

// scores_sum smem
constexpr uint32_t S_QH = 0, S_QL = 16384, S_KH = 32768, S_KL = 49152,
                   S_RED = 65536, S_SMEM = 65536 + 2048;
// av_fused smem
constexpr uint32_t F_QH = 0, F_QL = 16384, F_KH = 32768, F_KL = 40960,
                   F_VH = 49152, F_VL = 57344, F_INV = 65536,
                   F_SMEM = 65536 + 256;
}

typedef unsigned long long u64;

// ------------------------------- helpers -----------------------------------
__device__ __forceinline__ uint32_t smem_u32(const void* p) {
    uint32_t a;
    asm("{ .reg .u64 t; cvta.to.shared.u64 t, %1; cvt.u32.u64 %0, t; }" : "=r"(a) : "l"(p));
    return a;
}
// swizzled byte offset in a [rows][64 bf16] tile (128B rows, 16B units)
__device__ __forceinline__ uint32_t swzo(int r, int c16) {
    return (uint32_t)(r * 128 + ((c16 ^ (r & 7)) << 4));
}
__device__ __forceinline__ void ldsm4(uint32_t r[4], uint32_t addr) {
    asm volatile("ldmatrix.sync.aligned.m8n8.x4.shared.b16 {%0,%1,%2,%3}, [%4];"
        : "=r"(r[0]), "=r"(r[1]), "=r"(r[2]), "=r"(r[3]) : "r"(addr));
}
__device__ __forceinline__ void mma16816(float c[4], const uint32_t a[4], const uint32_t b[2]) {
    asm volatile("mma.sync.aligned.m16n8k16.row.col.f32.bf16.bf16.f32 "
        "{%0,%1,%2,%3}, {%4,%5,%6,%7}, {%8,%9}, {%0,%1,%2,%3};"
        : "+f"(c[0]), "+f"(c[1]), "+f"(c[2]), "+f"(c[3])
        : "r"(a[0]), "r"(a[1]), "r"(a[2]), "r"(a[3]), "r"(b[0]), "r"(b[1]));
}
__device__ __forceinline__ uint32_t pk_bf(float a, float b) {
    return (uint32_t)__bfloat16_as_ushort(__float2bfloat16(a)) |
           ((uint32_t)__bfloat16_as_ushort(__float2bfloat16(b)) << 16);
}
__device__ __forceinline__ void split1(float v, float& hi, float& lo) {
    __nv_bfloat16 h = __float2bfloat16(v);
    hi = __bfloat162float(h);
    lo = v - hi;
}

// ---------------------------- f32x2 (qkv / out) ----------------------------
__device__ __forceinline__ void fma2(u64 &d, u64 a, u64 b) {
    asm("fma.rn.f32x2 %0, %1, %2, %0;" : "+l"(d) : "l"(a), "l"(b));
}
__device__ __forceinline__ u64 dup2(float a) {
    u64 r; asm("mov.b64 %0, {%1, %1};" : "=l"(r) : "f"(a)); return r;
}
__device__ __forceinline__ u64 pk2(float lo, float hi) {
    u64 r; asm("mov.b64 %0, {%1, %2};" : "=l"(r) : "f"(lo), "f"(hi)); return r;
}
__device__ __forceinline__ float2 up2(u64 v) {
    float2 r; asm("mov.b64 {%0, %1}, %2;" : "=f"(r.x), "=f"(r.y) : "l"(v)); return r;
}
__device__ __forceinline__ int swz(int d, int c) { return d * 128 + (c ^ (d & 28)); }

__device__ __forceinline__ void rank1(u64* acc, float4 a0, float4 a1,
                                      float4 b0, float4 b1)
{
    u64 bp0 = pk2(b0.x, b0.y), bp1 = pk2(b0.z, b0.w);
    u64 bp2 = pk2(b1.x, b1.y), bp3 = pk2(b1.z, b1.w);
    float av[8] = {a0.x, a0.y, a0.z, a0.w, a1.x, a1.y, a1.z, a1.w};
#pragma unroll
    for (int i = 0; i < 8; ++i) {
        u64 ad = dup2(av[i]);
        fma2(acc[i * 4 + 0], ad, bp0);
        fma2(acc[i * 4 + 1], ad, bp1);
        fma2(acc[i * 4 + 2], ad, bp2);
        fma2(acc[i * 4 + 3], ad, bp3);
    }
}

// ------------------------------ device scratch -----------------------------
__device__ __nv_bfloat16 g_qh[MM * DD], g_ql[MM * DD];   // q (pre-scaled) hi/lo
__device__ __nv_bfloat16 g_kh[MM * DD], g_kl[MM * DD];   // k hi/lo
__device__ float g_v[MM * DD];
__device__ float g_colsum[MM];
__device__ float g_vals[NPART][MM * DD];
__device__ __nv_bfloat16 g_vt_hi[BB * DD * LL];          // v^T hi [b][d][k]
__device__ __nv_bfloat16 g_vt_lo[BB * DD * LL];

// ---------------------------------------------------------------------------
// Kernel 1: QKV projection (f32x2). grid (MM/128, 3), 128 thr.
// ---------------------------------------------------------------------------
__global__ __launch_bounds__(128) void qkv_kernel(
    const float* __restrict__ x,
    const float* __restrict__ Wq, const float* __restrict__ bq,
    const float* __restrict__ Wk, const float* __restrict__ bk,
    const float* __restrict__ Wv, const float* __restrict__ bv)
{
    const int t = threadIdx.x;
    const int gid = (blockIdx.y * gridDim.x + blockIdx.x) * 128 + t;
    if (gid < MM) g_colsum[gid] = 0.f;

    const float* W; const float* bias; float oscale;
    __nv_bfloat16 *oh = nullptr, *ol = nullptr;
    if (blockIdx.y == 0)      { W = Wq; bias = bq; oh = g_qh; ol = g_ql; oscale = SCALE; }
    else if (blockIdx.y == 1) { W = Wk; bias = bk; oh = g_kh; ol = g_kl; oscale = 1.f; }
    else                      { W = Wv; bias = bv; oscale = 1.f; }
    const bool isv = (blockIdx.y == 2);

    const int mb = blockIdx.x * 128;
    const int tx = t & 7, ty = t >> 3;

    __shared__ float xs[64 * 128];
    __shared__ float ws[64 * 64];

    u64 acc[32];
#pragma unroll
    for (int i = 0; i < 32; ++i) acc[i] = 0ull;

    const int dq = t & 15, rb = t >> 4;

    for (int kc = 0; kc < IN; kc += 64) {
        __syncthreads();
#pragma unroll
        for (int s = 0; s < 16; ++s) {
            int r = rb + s * 8;
            float4 v = *reinterpret_cast<const float4*>(&x[(size_t)(mb + r) * IN + kc + 4 * dq]);
            xs[swz(4 * dq + 0, r)] = v.x;
            xs[swz(4 * dq + 1, r)] = v.y;
            xs[swz(4 * dq + 2, r)] = v.z;
            xs[swz(4 * dq + 3, r)] = v.w;
        }
#pragma unroll
        for (int s = 0; s < 8; ++s) {
            int kr = rb + s * 8;
            *reinterpret_cast<float4*>(&ws[kr * 64 + 4 * dq]) =
                *reinterpret_cast<const float4*>(&W[(size_t)(kc + kr) * DD + 4 * dq]);
        }
        __syncthreads();
#pragma unroll 8
        for (int k = 0; k < 64; ++k) {
            float4 a0 = *reinterpret_cast<const float4*>(&xs[swz(k, 4 * ty)]);
            float4 a1 = *reinterpret_cast<const float4*>(&xs[swz(k, 64 + 4 * ty)]);
            float4 b0 = *reinterpret_cast<const float4*>(&ws[k * 64 + 4 * tx]);
            float4 b1 = *reinterpret_cast<const float4*>(&ws[k * 64 + 32 + 4 * tx]);
            rank1(acc, a0, a1, b0, b1);
        }
    }
    float4 bias0 = *reinterpret_cast<const float4*>(&bias[4 * tx]);
    float4 bias1 = *reinterpret_cast<const float4*>(&bias[32 + 4 * tx]);
#pragma unroll
    for (int i = 0; i < 8; ++i) {
        int r = (i < 4) ? (4 * ty + i) : (64 + 4 * ty + (i - 4));
        float2 p0 = up2(acc[i * 4 + 0]), p1 = up2(acc[i * 4 + 1]);
        float2 p2 = up2(acc[i * 4 + 2]), p3 = up2(acc[i * 4 + 3]);
        float f[8] = {(p0.x + bias0.x) * oscale, (p0.y + bias0.y) * oscale,
                      (p1.x + bias0.z) * oscale, (p1.y + bias0.w) * oscale,
                      (p2.x + bias1.x) * oscale, (p2.y + bias1.y) * oscale,
                      (p3.x + bias1.z) * oscale, (p3.y + bias1.w) * oscale};
        if (isv) {
            *reinterpret_cast<float4*>(&g_v[(size_t)(mb + r) * DD + 4 * tx]) =
                make_float4(f[0], f[1], f[2], f[3]);
            *reinterpret_cast<float4*>(&g_v[(size_t)(mb + r) * DD + 32 + 4 * tx]) =
                make_float4(f[4], f[5], f[6], f[7]);
        } else {
            float h[8], l[8];
#pragma unroll
            for (int j = 0; j < 8; ++j) split1(f[j], h[j], l[j]);
            size_t o0 = (size_t)(mb + r) * DD + 4 * tx;
            size_t o1 = o0 + 32;
            *reinterpret_cast<uint2*>(&oh[o0]) = make_uint2(pk_bf(h[0], h[1]), pk_bf(h[2], h[3]));
            *reinterpret_cast<uint2*>(&ol[o0]) = make_uint2(pk_bf(l[0], l[1]), pk_bf(l[2], l[3]));
            *reinterpret_cast<uint2*>(&oh[o1]) = make_uint2(pk_bf(h[4], h[5]), pk_bf(h[6], h[7]));
            *reinterpret_cast<uint2*>(&ol[o1]) = make_uint2(pk_bf(l[4], l[5]), pk_bf(l[6], l[7]));
        }
    }
}

// ---------------------------------------------------------------------------
// Kernel 1b: v[b][k][d] -> bf16 hi/lo transposed g_vt[b][d][k].
// grid (LL/64, BB), 256 thr.
// ---------------------------------------------------------------------------
__global__ __launch_bounds__(256) void vtrans_kernel()
{
    const int b = blockIdx.y, kb = blockIdx.x * 64;
    const int t = threadIdx.x;
    __shared__ float tile[64][68];

    const int c4 = t & 15, r0 = t >> 4;
#pragma unroll
    for (int s = 0; s < 4; ++s) {
        int r = r0 + 16 * s;
        float4 v = *reinterpret_cast<const float4*>(&g_v[(size_t)(b * LL + kb + r) * DD + 4 * c4]);
        tile[r][4 * c4 + 0] = v.x; tile[r][4 * c4 + 1] = v.y;
        tile[r][4 * c4 + 2] = v.z; tile[r][4 * c4 + 3] = v.w;
    }
    __syncthreads();

    const int f8 = t & 7, d0 = t >> 3;
#pragma unroll
    for (int s = 0; s < 2; ++s) {
        int d = d0 + 32 * s;
        union { __nv_bfloat16 h[8]; uint4 u; } hi, lo;
#pragma unroll
        for (int j = 0; j < 8; ++j) {
            float v = tile[f8 * 8 + j][d];
            __nv_bfloat16 hb = __float2bfloat16(v);
            hi.h[j] = hb;
            lo.h[j] = __float2bfloat16(v - __bfloat162float(hb));
        }
        size_t o = (size_t)(b * DD + d) * LL + kb + f8 * 8;
        *reinterpret_cast<uint4*>(&g_vt_hi[o]) = hi.u;
        *reinterpret_cast<uint4*>(&g_vt_lo[o]) = lo.u;
    }
}

// ---------------------------------------------------------------------------
// Kernel 2: scores_sum.  colsum[b,k] += sum_q exp(S[q,k]); NO attn store.
// grid (L/128 kb, L/128 qb, B), 256 thr (wm=w&3 q-rows, wn=w>>2 k-cols).
// ---------------------------------------------------------------------------
__global__ __launch_bounds__(256) void scores_sum(void)
{
    extern __shared__ char smem[];
    const uint32_t sb = smem_u32(smem);
    const int t = threadIdx.x, l = t & 31, w = t >> 5;
    const int wm = w & 3, wn = w >> 2;
    const int b = blockIdx.z, qb = blockIdx.y * 128, kb = blockIdx.x * 128;

    {
        const size_t qo = (size_t)(b * LL + qb) * DD;
        const size_t ko = (size_t)(b * LL + kb) * DD;
#pragma unroll
        for (int s = 0; s < 4; ++s) {
            int u = t + 256 * s;
            int r = u >> 3, c16 = u & 7;
            uint32_t off = swzo(r, c16);
            size_t gi = qo + (size_t)r * DD + c16 * 8;
            *(uint4*)(smem + S_QH + off) = *reinterpret_cast<const uint4*>(&g_qh[gi]);
            *(uint4*)(smem + S_QL + off) = *reinterpret_cast<const uint4*>(&g_ql[gi]);
            gi = ko + (size_t)r * DD + c16 * 8;
            *(uint4*)(smem + S_KH + off) = *reinterpret_cast<const uint4*>(&g_kh[gi]);
            *(uint4*)(smem + S_KL + off) = *reinterpret_cast<const uint4*>(&g_kl[gi]);
        }
    }
    __syncthreads();

    float acc[2][8][4];
#pragma unroll
    for (int mt = 0; mt < 2; ++mt)
#pragma unroll
        for (int nt = 0; nt < 8; ++nt)
#pragma unroll
            for (int j = 0; j < 4; ++j) acc[mt][nt][j] = 0.f;

#pragma unroll
    for (int ks = 0; ks < 4; ++ks) {
        uint32_t qh[2][4], ql[2][4];
        {
            uint32_t aoff = swzo(wm * 32 + (l & 15), ks * 2 + (l >> 4));
            ldsm4(qh[0], sb + S_QH + aoff);
            ldsm4(qh[1], sb + S_QH + aoff + 2048);
            ldsm4(ql[0], sb + S_QL + aoff);
            ldsm4(ql[1], sb + S_QL + aoff + 2048);
        }
        uint32_t kh[8][2], kl[8][2];
        {
            uint32_t boff = swzo(wn * 64 + ((l >> 4) << 3) + (l & 7),
                                 ks * 2 + ((l >> 3) & 1));
#pragma unroll
            for (int pg = 0; pg < 4; ++pg) {
                uint32_t r4[4];
                ldsm4(r4, sb + S_KH + boff + pg * 2048);
                kh[pg * 2][0] = r4[0]; kh[pg * 2][1] = r4[1];
                kh[pg * 2 + 1][0] = r4[2]; kh[pg * 2 + 1][1] = r4[3];
                ldsm4(r4, sb + S_KL + boff + pg * 2048);
                kl[pg * 2][0] = r4[0]; kl[pg * 2][1] = r4[1];
                kl[pg * 2 + 1][0] = r4[2]; kl[pg * 2 + 1][1] = r4[3];
            }
        }
#pragma unroll
        for (int mt = 0; mt < 2; ++mt)
#pragma unroll
            for (int nt = 0; nt < 8; ++nt) {
                mma16816(acc[mt][nt], qh[mt], kh[nt]);
                mma16816(acc[mt][nt], qh[mt], kl[nt]);
                mma16816(acc[mt][nt], ql[mt], kh[nt]);
            }
    }

    float* colred = (float*)(smem + S_RED);
#pragma unroll
    for (int nt = 0; nt < 8; ++nt) {
        float cs0 = 0.f, cs1 = 0.f;
#pragma unroll
        for (int mt = 0; mt < 2; ++mt) {
            cs0 += __expf(acc[mt][nt][0]) + __expf(acc[mt][nt][2]);
            cs1 += __expf(acc[mt][nt][1]) + __expf(acc[mt][nt][3]);
        }
#pragma unroll
        for (int m = 4; m < 32; m <<= 1) {
            cs0 += __shfl_xor_sync(0xffffffffu, cs0, m);
            cs1 += __shfl_xor_sync(0xffffffffu, cs1, m);
        }
        if (l < 4) {
            colred[wm * 128 + wn * 64 + nt * 8 + 2 * l + 0] = cs0;
            colred[wm * 128 + wn * 64 + nt * 8 + 2 * l + 1] = cs1;
        }
    }
    __syncthreads();
    if (t < 128) {
        float s = colred[t] + colred[128 + t] + colred[256 + t] + colred[384 + t];
        atomicAdd(&g_colsum[b * LL + kb + t], s);
    }
}

// ---------------------------------------------------------------------------
// Kernel 3: av_fused.  16 q-rows per warp, 64-col chunks, 2 CTAs/SM.
// Recompute S, P = exp(S)*inv, write A, O += P@V via fragment reuse.
// grid (L/128, KSPLIT, B), 256 thr.
// ---------------------------------------------------------------------------
__global__ __launch_bounds__(256, 2) void av_fused(float* __restrict__ attn)
{
    extern __shared__ char smem[];
    const uint32_t sb = smem_u32(smem);
    const int t = threadIdx.x, l = t & 31, w = t >> 5;
    const int b = blockIdx.z, split = blockIdx.y, qb = blockIdx.x * 128;
    const int kBeg = split * (LL / KSPLIT);

    float* inv_s = (float*)(smem + F_INV);
    const float* cs = g_colsum + b * LL;
    float* ap = attn + (size_t)(b * LL + qb) * LL;

    // load q tiles once (128 rows x 64 d, hi/lo)
    {
        const size_t qo = (size_t)(b * LL + qb) * DD;
#pragma unroll
        for (int s = 0; s < 4; ++s) {
            int u = t + 256 * s;
            int r = u >> 3, c16 = u & 7;
            uint32_t off = swzo(r, c16);
            size_t gi = qo + (size_t)r * DD + c16 * 8;
            *(uint4*)(smem + F_QH + off) = *reinterpret_cast<const uint4*>(&g_qh[gi]);
            *(uint4*)(smem + F_QL + off) = *reinterpret_cast<const uint4*>(&g_ql[gi]);
        }
    }

    float o[8][4];
#pragma unroll
    for (int nt = 0; nt < 8; ++nt)
#pragma unroll
        for (int j = 0; j < 4; ++j) o[nt][j] = 0.f;

    for (int ci = 0; ci < (LL / KSPLIT) / 64; ++ci) {
        const int kc = kBeg + ci * 64;
        __syncthreads();                               // smem reuse guard
        if (t < 64) inv_s[t] = 1.f / cs[kc + t];
        // k tile [64 rows][64 d] hi/lo
        {
            const size_t ko = (size_t)(b * LL + kc) * DD;
#pragma unroll
            for (int s = 0; s < 2; ++s) {
                int u = t + 256 * s;                   // 0..511
                int r = u >> 3, c16 = u & 7;
                uint32_t off = swzo(r, c16);
                size_t gi = ko + (size_t)r * DD + c16 * 8;
                *(uint4*)(smem + F_KH + off) = *reinterpret_cast<const uint4*>(&g_kh[gi]);
                *(uint4*)(smem + F_KL + off) = *reinterpret_cast<const uint4*>(&g_kl[gi]);
            }
        }
        // v^T tile [64 d][64 k] hi/lo
        {
#pragma unroll
            for (int s = 0; s < 2; ++s) {
                int u = t + 256 * s;
                int d = u >> 3, c16 = u & 7;
                uint32_t off = swzo(d, c16);
                size_t gi = (size_t)(b * DD + d) * LL + kc + c16 * 8;
                *(uint4*)(smem + F_VH + off) = *reinterpret_cast<const uint4*>(&g_vt_hi[gi]);
                *(uint4*)(smem + F_VL + off) = *reinterpret_cast<const uint4*>(&g_vt_lo[gi]);
            }
        }
        __syncthreads();

        // ---- S = q k^T for this warp's 16 rows x 64 cols ----
        float acc[8][4];
#pragma unroll
        for (int nt = 0; nt < 8; ++nt)
#pragma unroll
            for (int j = 0; j < 4; ++j) acc[nt][j] = 0.f;

#pragma unroll
        for (int ks = 0; ks < 4; ++ks) {
            uint32_t qh[4], ql[4];
            {
                uint32_t aoff = swzo(w * 16 + (l & 15), ks * 2 + (l >> 4));
                ldsm4(qh, sb + F_QH + aoff);
                ldsm4(ql, sb + F_QL + aoff);
            }
            uint32_t kh[8][2], kl[8][2];
            {
                uint32_t boff = swzo(((l >> 4) << 3) + (l & 7),
                                     ks * 2 + ((l >> 3) & 1));
#pragma unroll
                for (int pg = 0; pg < 4; ++pg) {
                    uint32_t r4[4];
                    ldsm4(r4, sb + F_KH + boff + pg * 2048);
                    kh[pg * 2][0] = r4[0]; kh[pg * 2][1] = r4[1];
                    kh[pg * 2 + 1][0] = r4[2]; kh[pg * 2 + 1][1] = r4[3];
                    ldsm4(r4, sb + F_KL + boff + pg * 2048);
                    kl[pg * 2][0] = r4[0]; kl[pg * 2][1] = r4[1];
                    kl[pg * 2 + 1][0] = r4[2]; kl[pg * 2 + 1][1] = r4[3];
                }
            }
#pragma unroll
            for (int nt = 0; nt < 8; ++nt) {
                mma16816(acc[nt], qh, kh[nt]);
                mma16816(acc[nt], qh, kl[nt]);
                mma16816(acc[nt], ql, kh[nt]);
            }
        }

        // ---- P = exp(S)*inv ; store A ; pack P -> A-fragments ----
        uint32_t ph[4][4], pl[4][4];
#pragma unroll
        for (int nt = 0; nt < 8; ++nt) {
            int lc = nt * 8 + 2 * (l & 3);
            float i0 = inv_s[lc], i1 = inv_s[lc + 1];
            float e0 = __expf(acc[nt][0]) * i0;
            float e1 = __expf(acc[nt][1]) * i1;
            float e2 = __expf(acc[nt][2]) * i0;
            float e3 = __expf(acc[nt][3]) * i1;
            int r0 = w * 16 + (l >> 2);
            *reinterpret_cast<float2*>(&ap[(size_t)r0 * LL + kc + lc]) = make_float2(e0, e1);
            *reinterpret_cast<float2*>(&ap[(size_t)(r0 + 8) * LL + kc + lc]) = make_float2(e2, e3);
            float h0, l0, h1, l1, h2, l2, h3, l3;
            split1(e0, h0, l0); split1(e1, h1, l1);
            split1(e2, h2, l2); split1(e3, h3, l3);
            int kb2 = nt >> 1, base = (nt & 1) * 2;
            ph[kb2][base + 0] = pk_bf(h0, h1);
            ph[kb2][base + 1] = pk_bf(h2, h3);
            pl[kb2][base + 0] = pk_bf(l0, l1);
            pl[kb2][base + 1] = pk_bf(l2, l3);
        }

        // ---- O += P @ V (3-pass) ----
#pragma unroll
        for (int kb2 = 0; kb2 < 4; ++kb2) {
            uint32_t vh[8][2], vl[8][2];
            {
                uint32_t boff = swzo(((l >> 4) << 3) + (l & 7),
                                     kb2 * 2 + ((l >> 3) & 1));
#pragma unroll
                for (int pg = 0; pg < 4; ++pg) {
                    uint32_t r4[4];
                    ldsm4(r4, sb + F_VH + boff + pg * 2048);
                    vh[pg * 2][0] = r4[0]; vh[pg * 2][1] = r4[1];
                    vh[pg * 2 + 1][0] = r4[2]; vh[pg * 2 + 1][1] = r4[3];
                    ldsm4(r4, sb + F_VL + boff + pg * 2048);
                    vl[pg * 2][0] = r4[0]; vl[pg * 2][1] = r4[1];
                    vl[pg * 2 + 1][0] = r4[2]; vl[pg * 2 + 1][1] = r4[3];
                }
            }
#pragma unroll
            for (int nt = 0; nt < 8; ++nt) {
                mma16816(o[nt], ph[kb2], vh[nt]);
                mma16816(o[nt], ph[kb2], vl[nt]);
                mma16816(o[nt], pl[kb2], vh[nt]);
            }
        }
    }

    // epilogue: O partial -> g_vals[split]
    float* gv = g_vals[split];
#pragma unroll
    for (int nt = 0; nt < 8; ++nt) {
        int col = nt * 8 + 2 * (l & 3);
        size_t row = (size_t)(b * LL + qb + w * 16 + (l >> 2));
        *reinterpret_cast<float2*>(&gv[row * DD + col]) =
            make_float2(o[nt][0], o[nt][1]);
        *reinterpret_cast<float2*>(&gv[(row + 8) * DD + col]) =
            make_float2(o[nt][2], o[nt][3]);
    }
}

// ---------------------------------------------------------------------------
// Kernel 4: out = (sum_p g_vals[p]) @ Wo + bo. grid (MM/128, OUT/128), 256 thr.
// ---------------------------------------------------------------------------
__global__ __launch_bounds__(256) void out_kernel(
    const float* __restrict__ Wo, const float* __restrict__ bo,
    float* __restrict__ outp)
{
    const int mb = blockIdx.x * 128;
    const int nb = blockIdx.y * 128;
    const int t  = threadIdx.x;
    const int tx = t & 15, ty = t >> 4;

    __shared__ float vt[64 * 128];
    __shared__ float ws[64 * 128];

    {
        const int dq = t & 15, rb = t >> 4;
#pragma unroll
        for (int s = 0; s < 8; ++s) {
            int r = rb + s * 16;
            size_t base = (size_t)(mb + r) * DD + 4 * dq;
            float4 v = *reinterpret_cast<const float4*>(&g_vals[0][base]);
#pragma unroll
            for (int p = 1; p < NPART; ++p) {
                float4 u = *reinterpret_cast<const float4*>(&g_vals[p][base]);
                v.x += u.x; v.y += u.y; v.z += u.z; v.w += u.w;
            }
            vt[swz(4 * dq + 0, r)] = v.x; vt[swz(4 * dq + 1, r)] = v.y;
            vt[swz(4 * dq + 2, r)] = v.z; vt[swz(4 * dq + 3, r)] = v.w;
        }
        const int nq = t & 31, kb2 = t >> 5;
#pragma unroll
        for (int s = 0; s < 8; ++s) {
            int kr = kb2 + s * 8;
            *reinterpret_cast<float4*>(&ws[kr * 128 + 4 * nq]) =
                *reinterpret_cast<const float4*>(&Wo[(size_t)kr * OUT + nb + 4 * nq]);
        }
    }
    __syncthreads();

    u64 acc[32];
#pragma unroll
    for (int i = 0; i < 32; ++i) acc[i] = 0ull;

#pragma unroll 8
    for (int k = 0; k < 64; ++k) {
        float4 a0 = *reinterpret_cast<const float4*>(&vt[swz(k, 4 * ty)]);
        float4 a1 = *reinterpret_cast<const float4*>(&vt[swz(k, 64 + 4 * ty)]);
        float4 b0 = *reinterpret_cast<const float4*>(&ws[k * 128 + 4 * tx]);
        float4 b1 = *reinterpret_cast<const float4*>(&ws[k * 128 + 64 + 4 * tx]);
        rank1(acc, a0, a1, b0, b1);
    }

    float4 bo0 = *reinterpret_cast<const float4*>(&bo[nb + 4 * tx]);
    float4 bo1 = *reinterpret_cast<const float4*>(&bo[nb + 64 + 4 * tx]);
#pragma unroll
    for (int i = 0; i < 8; ++i) {
        int r = (i < 4) ? (4 * ty + i) : (64 + 4 * ty + (i - 4));
        float2 p0 = up2(acc[i * 4 + 0]), p1 = up2(acc[i * 4 + 1]);
        float2 p2 = up2(acc[i * 4 + 2]), p3 = up2(acc[i * 4 + 3]);
        float4 o0 = make_float4(p0.x + bo0.x, p0.y + bo0.y, p1.x + bo0.z, p1.y + bo0.w);
        float4 o1 = make_float4(p2.x + bo1.x, p2.y + bo1.y, p3.x + bo1.z, p3.y + bo1.w);
        *reinterpret_cast<float4*>(&outp[(size_t)(mb + r) * OUT + nb + 4 * tx]) = o0;
        *reinterpret_cast<float4*>(&outp[(size_t)(mb + r) * OUT + nb + 64 + 4 * tx]) = o1;
    }
}

// ---------------------------------------------------------------------------
extern "C" void kernel_launch(void* const* d_in, const int* in_sizes, int n_in,
                              void* d_out, int out_size)
{
    const float* x  = (const float*)d_in[0];
    const float* Wq = (const float*)d_in[1];
    const float* bq = (const float*)d_in[2];
    const float* Wk = (const float*)d_in[3];
    const float* bk = (const float*)d_in[4];
    const float* Wv = (const float*)d_in[5];
    const float* bv = (const float*)d_in[6];
    const float* Wo = (const float*)d_in[7];
    const float* bo = (const float*)d_in[8];

    float* outp = (float*)d_out;                   // [B, L, OUT]
    float* attn = outp + (size_t)BB * LL * OUT;    // [B, L, L]

    cudaFuncSetAttribute(scores_sum, cudaFuncAttributeMaxDynamicSharedMemorySize, S_SMEM);
    cudaFuncSetAttribute(av_fused,   cudaFuncAttributeMaxDynamicSharedMemorySize, F_SMEM);

    qkv_kernel<<<dim3(MM / 128, 3), 128>>>(x, Wq, bq, Wk, bk, Wv, bv);
    vtrans_kernel<<<dim3(LL / 64, BB), 256>>>();
    scores_sum<<<dim3(LL / 128, LL / 128, BB), 256, S_SMEM>>>();
    av_fused<<<dim3(LL / 128, KSPLIT, BB), 256, F_SMEM>>>(attn);
    out_kernel<<<dim3(MM / 128, OUT / 128), 256>>>(Wo, bo, outp);
}

// round 10
// speedup vs baseline: 2.9960x; 1.0300x over previous
#include <cuda_runtime.h>
#include <cuda_bf16.h>
#include <cstdint>

// ---------------------------------------------------------------------------
// AttentionBlock, Round 9: recompute-S fused attention + cp.async double
// buffering in av_fused.
//  k1  qkv       : q,k,v projections; q,k stored bf16 hi/lo; q pre-scaled.
//  k1b vtrans    : v -> v^T bf16 hi/lo.
//  k2  scores_sum: colsum[b,k] = sum_q exp(S) via 3-pass HMMA (no store).
//  k3  av_fused  : recompute S, P=exp(S)*inv, write A, O += P@V (reg reuse).
//                  16 q-rows/warp, 64-col chunks, 2 CTAs/SM, cp.async pipe.
//  k4  out       : out = (sum partials) @ Wo + bo (f32x2).
// B=4, L=4096, IN=512, D=64, OUT=512.  Outputs: (out, attention).
// ---------------------------------------------------------------------------

namespace {
constexpr int BB  = 4;
constexpr int LL  = 4096;
constexpr int IN  = 512;
constexpr int DD  = 64;
constexpr int OUT = 512;
constexpr int MM  = BB * LL;
constexpr int KSPLIT = 4;
constexpr int NPART = KSPLIT;
constexpr float SCALE = 0.125f;

// scores_sum smem
constexpr uint32_t S_QH = 0, S_QL = 16384, S_KH = 32768, S_KL = 49152,
                   S_RED = 65536, S_SMEM = 65536 + 2048;
// av_fused smem: Q hi/lo, then 2 k/v buffers of 32KB (KH,KL,VH,VL 8KB each),
// then double-buffered inv.
constexpr uint32_t F_QH = 0, F_QL = 16384, F_KV = 32768,
                   F_INV = 98304, F_SMEM = 98304 + 512;
}

typedef unsigned long long u64;

// ------------------------------- helpers -----------------------------------
__device__ __forceinline__ uint32_t smem_u32(const void* p) {
    uint32_t a;
    asm("{ .reg .u64 t; cvta.to.shared.u64 t, %1; cvt.u32.u64 %0, t; }" : "=r"(a) : "l"(p));
    return a;
}
// swizzled byte offset in a [rows][64 bf16] tile (128B rows, 16B units)
__device__ __forceinline__ uint32_t swzo(int r, int c16) {
    return (uint32_t)(r * 128 + ((c16 ^ (r & 7)) << 4));
}
__device__ __forceinline__ void ldsm4(uint32_t r[4], uint32_t addr) {
    asm volatile("ldmatrix.sync.aligned.m8n8.x4.shared.b16 {%0,%1,%2,%3}, [%4];"
        : "=r"(r[0]), "=r"(r[1]), "=r"(r[2]), "=r"(r[3]) : "r"(addr));
}
__device__ __forceinline__ void mma16816(float c[4], const uint32_t a[4], const uint32_t b[2]) {
    asm volatile("mma.sync.aligned.m16n8k16.row.col.f32.bf16.bf16.f32 "
        "{%0,%1,%2,%3}, {%4,%5,%6,%7}, {%8,%9}, {%0,%1,%2,%3};"
        : "+f"(c[0]), "+f"(c[1]), "+f"(c[2]), "+f"(c[3])
        : "r"(a[0]), "r"(a[1]), "r"(a[2]), "r"(a[3]), "r"(b[0]), "r"(b[1]));
}
__device__ __forceinline__ uint32_t pk_bf(float a, float b) {
    return (uint32_t)__bfloat16_as_ushort(__float2bfloat16(a)) |
           ((uint32_t)__bfloat16_as_ushort(__float2bfloat16(b)) << 16);
}
__device__ __forceinline__ void split1(float v, float& hi, float& lo) {
    __nv_bfloat16 h = __float2bfloat16(v);
    hi = __bfloat162float(h);
    lo = v - hi;
}
__device__ __forceinline__ void cpa16(uint32_t s, const void* g) {
    asm volatile("cp.async.cg.shared.global [%0], [%1], 16;" :: "r"(s), "l"(g) : "memory");
}
#define CPA_COMMIT() asm volatile("cp.async.commit_group;" ::: "memory")

// ---------------------------- f32x2 (qkv / out) ----------------------------
__device__ __forceinline__ void fma2(u64 &d, u64 a, u64 b) {
    asm("fma.rn.f32x2 %0, %1, %2, %0;" : "+l"(d) : "l"(a), "l"(b));
}
__device__ __forceinline__ u64 dup2(float a) {
    u64 r; asm("mov.b64 %0, {%1, %1};" : "=l"(r) : "f"(a)); return r;
}
__device__ __forceinline__ u64 pk2(float lo, float hi) {
    u64 r; asm("mov.b64 %0, {%1, %2};" : "=l"(r) : "f"(lo), "f"(hi)); return r;
}
__device__ __forceinline__ float2 up2(u64 v) {
    float2 r; asm("mov.b64 {%0, %1}, %2;" : "=f"(r.x), "=f"(r.y) : "l"(v)); return r;
}
__device__ __forceinline__ int swz(int d, int c) { return d * 128 + (c ^ (d & 28)); }

__device__ __forceinline__ void rank1(u64* acc, float4 a0, float4 a1,
                                      float4 b0, float4 b1)
{
    u64 bp0 = pk2(b0.x, b0.y), bp1 = pk2(b0.z, b0.w);
    u64 bp2 = pk2(b1.x, b1.y), bp3 = pk2(b1.z, b1.w);
    float av[8] = {a0.x, a0.y, a0.z, a0.w, a1.x, a1.y, a1.z, a1.w};
#pragma unroll
    for (int i = 0; i < 8; ++i) {
        u64 ad = dup2(av[i]);
        fma2(acc[i * 4 + 0], ad, bp0);
        fma2(acc[i * 4 + 1], ad, bp1);
        fma2(acc[i * 4 + 2], ad, bp2);
        fma2(acc[i * 4 + 3], ad, bp3);
    }
}

// ------------------------------ device scratch -----------------------------
__device__ __nv_bfloat16 g_qh[MM * DD], g_ql[MM * DD];   // q (pre-scaled) hi/lo
__device__ __nv_bfloat16 g_kh[MM * DD], g_kl[MM * DD];   // k hi/lo
__device__ float g_v[MM * DD];
__device__ float g_colsum[MM];
__device__ float g_vals[NPART][MM * DD];
__device__ __nv_bfloat16 g_vt_hi[BB * DD * LL];          // v^T hi [b][d][k]
__device__ __nv_bfloat16 g_vt_lo[BB * DD * LL];

// ---------------------------------------------------------------------------
// Kernel 1: QKV projection (f32x2). grid (MM/128, 3), 128 thr.
// ---------------------------------------------------------------------------
__global__ __launch_bounds__(128) void qkv_kernel(
    const float* __restrict__ x,
    const float* __restrict__ Wq, const float* __restrict__ bq,
    const float* __restrict__ Wk, const float* __restrict__ bk,
    const float* __restrict__ Wv, const float* __restrict__ bv)
{
    const int t = threadIdx.x;
    const int gid = (blockIdx.y * gridDim.x + blockIdx.x) * 128 + t;
    if (gid < MM) g_colsum[gid] = 0.f;

    const float* W; const float* bias; float oscale;
    __nv_bfloat16 *oh = nullptr, *ol = nullptr;
    if (blockIdx.y == 0)      { W = Wq; bias = bq; oh = g_qh; ol = g_ql; oscale = SCALE; }
    else if (blockIdx.y == 1) { W = Wk; bias = bk; oh = g_kh; ol = g_kl; oscale = 1.f; }
    else                      { W = Wv; bias = bv; oscale = 1.f; }
    const bool isv = (blockIdx.y == 2);

    const int mb = blockIdx.x * 128;
    const int tx = t & 7, ty = t >> 3;

    __shared__ float xs[64 * 128];
    __shared__ float ws[64 * 64];

    u64 acc[32];
#pragma unroll
    for (int i = 0; i < 32; ++i) acc[i] = 0ull;

    const int dq = t & 15, rb = t >> 4;

    for (int kc = 0; kc < IN; kc += 64) {
        __syncthreads();
#pragma unroll
        for (int s = 0; s < 16; ++s) {
            int r = rb + s * 8;
            float4 v = *reinterpret_cast<const float4*>(&x[(size_t)(mb + r) * IN + kc + 4 * dq]);
            xs[swz(4 * dq + 0, r)] = v.x;
            xs[swz(4 * dq + 1, r)] = v.y;
            xs[swz(4 * dq + 2, r)] = v.z;
            xs[swz(4 * dq + 3, r)] = v.w;
        }
#pragma unroll
        for (int s = 0; s < 8; ++s) {
            int kr = rb + s * 8;
            *reinterpret_cast<float4*>(&ws[kr * 64 + 4 * dq]) =
                *reinterpret_cast<const float4*>(&W[(size_t)(kc + kr) * DD + 4 * dq]);
        }
        __syncthreads();
#pragma unroll 8
        for (int k = 0; k < 64; ++k) {
            float4 a0 = *reinterpret_cast<const float4*>(&xs[swz(k, 4 * ty)]);
            float4 a1 = *reinterpret_cast<const float4*>(&xs[swz(k, 64 + 4 * ty)]);
            float4 b0 = *reinterpret_cast<const float4*>(&ws[k * 64 + 4 * tx]);
            float4 b1 = *reinterpret_cast<const float4*>(&ws[k * 64 + 32 + 4 * tx]);
            rank1(acc, a0, a1, b0, b1);
        }
    }
    float4 bias0 = *reinterpret_cast<const float4*>(&bias[4 * tx]);
    float4 bias1 = *reinterpret_cast<const float4*>(&bias[32 + 4 * tx]);
#pragma unroll
    for (int i = 0; i < 8; ++i) {
        int r = (i < 4) ? (4 * ty + i) : (64 + 4 * ty + (i - 4));
        float2 p0 = up2(acc[i * 4 + 0]), p1 = up2(acc[i * 4 + 1]);
        float2 p2 = up2(acc[i * 4 + 2]), p3 = up2(acc[i * 4 + 3]);
        float f[8] = {(p0.x + bias0.x) * oscale, (p0.y + bias0.y) * oscale,
                      (p1.x + bias0.z) * oscale, (p1.y + bias0.w) * oscale,
                      (p2.x + bias1.x) * oscale, (p2.y + bias1.y) * oscale,
                      (p3.x + bias1.z) * oscale, (p3.y + bias1.w) * oscale};
        if (isv) {
            *reinterpret_cast<float4*>(&g_v[(size_t)(mb + r) * DD + 4 * tx]) =
                make_float4(f[0], f[1], f[2], f[3]);
            *reinterpret_cast<float4*>(&g_v[(size_t)(mb + r) * DD + 32 + 4 * tx]) =
                make_float4(f[4], f[5], f[6], f[7]);
        } else {
            float h[8], l[8];
#pragma unroll
            for (int j = 0; j < 8; ++j) split1(f[j], h[j], l[j]);
            size_t o0 = (size_t)(mb + r) * DD + 4 * tx;
            size_t o1 = o0 + 32;
            *reinterpret_cast<uint2*>(&oh[o0]) = make_uint2(pk_bf(h[0], h[1]), pk_bf(h[2], h[3]));
            *reinterpret_cast<uint2*>(&ol[o0]) = make_uint2(pk_bf(l[0], l[1]), pk_bf(l[2], l[3]));
            *reinterpret_cast<uint2*>(&oh[o1]) = make_uint2(pk_bf(h[4], h[5]), pk_bf(h[6], h[7]));
            *reinterpret_cast<uint2*>(&ol[o1]) = make_uint2(pk_bf(l[4], l[5]), pk_bf(l[6], l[7]));
        }
    }
}

// ---------------------------------------------------------------------------
// Kernel 1b: v[b][k][d] -> bf16 hi/lo transposed g_vt[b][d][k].
// grid (LL/64, BB), 256 thr.
// ---------------------------------------------------------------------------
__global__ __launch_bounds__(256) void vtrans_kernel()
{
    const int b = blockIdx.y, kb = blockIdx.x * 64;
    const int t = threadIdx.x;
    __shared__ float tile[64][68];

    const int c4 = t & 15, r0 = t >> 4;
#pragma unroll
    for (int s = 0; s < 4; ++s) {
        int r = r0 + 16 * s;
        float4 v = *reinterpret_cast<const float4*>(&g_v[(size_t)(b * LL + kb + r) * DD + 4 * c4]);
        tile[r][4 * c4 + 0] = v.x; tile[r][4 * c4 + 1] = v.y;
        tile[r][4 * c4 + 2] = v.z; tile[r][4 * c4 + 3] = v.w;
    }
    __syncthreads();

    const int f8 = t & 7, d0 = t >> 3;
#pragma unroll
    for (int s = 0; s < 2; ++s) {
        int d = d0 + 32 * s;
        union { __nv_bfloat16 h[8]; uint4 u; } hi, lo;
#pragma unroll
        for (int j = 0; j < 8; ++j) {
            float v = tile[f8 * 8 + j][d];
            __nv_bfloat16 hb = __float2bfloat16(v);
            hi.h[j] = hb;
            lo.h[j] = __float2bfloat16(v - __bfloat162float(hb));
        }
        size_t o = (size_t)(b * DD + d) * LL + kb + f8 * 8;
        *reinterpret_cast<uint4*>(&g_vt_hi[o]) = hi.u;
        *reinterpret_cast<uint4*>(&g_vt_lo[o]) = lo.u;
    }
}

// ---------------------------------------------------------------------------
// Kernel 2: scores_sum.  colsum[b,k] += sum_q exp(S[q,k]); NO attn store.
// grid (L/128 kb, L/128 qb, B), 256 thr, 2 CTAs/SM.
// ---------------------------------------------------------------------------
__global__ __launch_bounds__(256, 2) void scores_sum(void)
{
    extern __shared__ char smem[];
    const uint32_t sb = smem_u32(smem);
    const int t = threadIdx.x, l = t & 31, w = t >> 5;
    const int wm = w & 3, wn = w >> 2;
    const int b = blockIdx.z, qb = blockIdx.y * 128, kb = blockIdx.x * 128;

    {
        const size_t qo = (size_t)(b * LL + qb) * DD;
        const size_t ko = (size_t)(b * LL + kb) * DD;
#pragma unroll
        for (int s = 0; s < 4; ++s) {
            int u = t + 256 * s;
            int r = u >> 3, c16 = u & 7;
            uint32_t off = swzo(r, c16);
            size_t gi = qo + (size_t)r * DD + c16 * 8;
            *(uint4*)(smem + S_QH + off) = *reinterpret_cast<const uint4*>(&g_qh[gi]);
            *(uint4*)(smem + S_QL + off) = *reinterpret_cast<const uint4*>(&g_ql[gi]);
            gi = ko + (size_t)r * DD + c16 * 8;
            *(uint4*)(smem + S_KH + off) = *reinterpret_cast<const uint4*>(&g_kh[gi]);
            *(uint4*)(smem + S_KL + off) = *reinterpret_cast<const uint4*>(&g_kl[gi]);
        }
    }
    __syncthreads();

    float acc[2][8][4];
#pragma unroll
    for (int mt = 0; mt < 2; ++mt)
#pragma unroll
        for (int nt = 0; nt < 8; ++nt)
#pragma unroll
            for (int j = 0; j < 4; ++j) acc[mt][nt][j] = 0.f;

#pragma unroll
    for (int ks = 0; ks < 4; ++ks) {
        uint32_t qh[2][4], ql[2][4];
        {
            uint32_t aoff = swzo(wm * 32 + (l & 15), ks * 2 + (l >> 4));
            ldsm4(qh[0], sb + S_QH + aoff);
            ldsm4(qh[1], sb + S_QH + aoff + 2048);
            ldsm4(ql[0], sb + S_QL + aoff);
            ldsm4(ql[1], sb + S_QL + aoff + 2048);
        }
        uint32_t kh[8][2], kl[8][2];
        {
            uint32_t boff = swzo(wn * 64 + ((l >> 4) << 3) + (l & 7),
                                 ks * 2 + ((l >> 3) & 1));
#pragma unroll
            for (int pg = 0; pg < 4; ++pg) {
                uint32_t r4[4];
                ldsm4(r4, sb + S_KH + boff + pg * 2048);
                kh[pg * 2][0] = r4[0]; kh[pg * 2][1] = r4[1];
                kh[pg * 2 + 1][0] = r4[2]; kh[pg * 2 + 1][1] = r4[3];
                ldsm4(r4, sb + S_KL + boff + pg * 2048);
                kl[pg * 2][0] = r4[0]; kl[pg * 2][1] = r4[1];
                kl[pg * 2 + 1][0] = r4[2]; kl[pg * 2 + 1][1] = r4[3];
            }
        }
#pragma unroll
        for (int mt = 0; mt < 2; ++mt)
#pragma unroll
            for (int nt = 0; nt < 8; ++nt) {
                mma16816(acc[mt][nt], qh[mt], kh[nt]);
                mma16816(acc[mt][nt], qh[mt], kl[nt]);
                mma16816(acc[mt][nt], ql[mt], kh[nt]);
            }
    }

    float* colred = (float*)(smem + S_RED);
#pragma unroll
    for (int nt = 0; nt < 8; ++nt) {
        float cs0 = 0.f, cs1 = 0.f;
#pragma unroll
        for (int mt = 0; mt < 2; ++mt) {
            cs0 += __expf(acc[mt][nt][0]) + __expf(acc[mt][nt][2]);
            cs1 += __expf(acc[mt][nt][1]) + __expf(acc[mt][nt][3]);
        }
#pragma unroll
        for (int m = 4; m < 32; m <<= 1) {
            cs0 += __shfl_xor_sync(0xffffffffu, cs0, m);
            cs1 += __shfl_xor_sync(0xffffffffu, cs1, m);
        }
        if (l < 4) {
            colred[wm * 128 + wn * 64 + nt * 8 + 2 * l + 0] = cs0;
            colred[wm * 128 + wn * 64 + nt * 8 + 2 * l + 1] = cs1;
        }
    }
    __syncthreads();
    if (t < 128) {
        float s = colred[t] + colred[128 + t] + colred[256 + t] + colred[384 + t];
        atomicAdd(&g_colsum[b * LL + kb + t], s);
    }
}

// ---------------------------------------------------------------------------
// Kernel 3: av_fused.  16 q-rows/warp, 64-col chunks, 2 CTAs/SM,
// cp.async double-buffered k/v.  Recompute S, P = exp(S)*inv, write A,
// O += P@V via fragment reuse.  grid (L/128, KSPLIT, B), 256 thr.
// ---------------------------------------------------------------------------
__global__ __launch_bounds__(256, 2) void av_fused(float* __restrict__ attn)
{
    extern __shared__ char smem[];
    const uint32_t sb = smem_u32(smem);
    const int t = threadIdx.x, l = t & 31, w = t >> 5;
    const int b = blockIdx.z, split = blockIdx.y, qb = blockIdx.x * 128;
    const int kBeg = split * (LL / KSPLIT);
    constexpr int NCH = (LL / KSPLIT) / 64;          // 16 chunks

    float* invb = (float*)(smem + F_INV);            // [2][64]
    const float* cs = g_colsum + b * LL;
    float* ap = attn + (size_t)(b * LL + qb) * LL;

    // q tiles once (128 rows x 64 d, hi/lo) — regular loads
    {
        const size_t qo = (size_t)(b * LL + qb) * DD;
#pragma unroll
        for (int s = 0; s < 4; ++s) {
            int u = t + 256 * s;
            int r = u >> 3, c16 = u & 7;
            uint32_t off = swzo(r, c16);
            size_t gi = qo + (size_t)r * DD + c16 * 8;
            *(uint4*)(smem + F_QH + off) = *reinterpret_cast<const uint4*>(&g_qh[gi]);
            *(uint4*)(smem + F_QL + off) = *reinterpret_cast<const uint4*>(&g_ql[gi]);
        }
    }
    // inv for chunk 0
    if (t < 64) invb[t] = 1.f / cs[kBeg + t];

    // cp.async issue of one chunk's k/v tiles into buffer (ci&1)
    auto issue = [&](int ci) {
        const int kc = kBeg + ci * 64;
        const uint32_t base = sb + F_KV + (uint32_t)(ci & 1) * 32768;
        const size_t ko = (size_t)(b * LL + kc) * DD;
#pragma unroll
        for (int s = 0; s < 2; ++s) {
            int u = t + 256 * s;                     // 0..511
            int r = u >> 3, c16 = u & 7;
            uint32_t off = swzo(r, c16);
            size_t gk = ko + (size_t)r * DD + c16 * 8;
            cpa16(base + off,         &g_kh[gk]);
            cpa16(base + 8192 + off,  &g_kl[gk]);
            size_t gv = (size_t)(b * DD + r) * LL + kc + c16 * 8;
            cpa16(base + 16384 + off, &g_vt_hi[gv]);
            cpa16(base + 24576 + off, &g_vt_lo[gv]);
        }
        CPA_COMMIT();
    };
    issue(0);

    float o[8][4];
#pragma unroll
    for (int nt = 0; nt < 8; ++nt)
#pragma unroll
        for (int j = 0; j < 4; ++j) o[nt][j] = 0.f;

    for (int ci = 0; ci < NCH; ++ci) {
        const int kc = kBeg + ci * 64;
        if (ci + 1 < NCH) {
            issue(ci + 1);
            asm volatile("cp.async.wait_group 1;" ::: "memory");
        } else {
            asm volatile("cp.async.wait_group 0;" ::: "memory");
        }
        __syncthreads();                             // chunk ci data visible

        // prefetch inv for next chunk (read at ci+1's P phase, after its sync)
        if (ci + 1 < NCH && t < 64)
            invb[((ci + 1) & 1) * 64 + t] = 1.f / cs[kc + 64 + t];

        const uint32_t kb_hi = sb + F_KV + (uint32_t)(ci & 1) * 32768;
        const uint32_t kb_lo = kb_hi + 8192;
        const uint32_t vb_hi = kb_hi + 16384;
        const uint32_t vb_lo = kb_hi + 24576;
        const float* inv_s = invb + (ci & 1) * 64;

        // ---- S = q k^T for this warp's 16 rows x 64 cols ----
        float acc[8][4];
#pragma unroll
        for (int nt = 0; nt < 8; ++nt)
#pragma unroll
            for (int j = 0; j < 4; ++j) acc[nt][j] = 0.f;

#pragma unroll
        for (int ks = 0; ks < 4; ++ks) {
            uint32_t qh[4], ql[4];
            {
                uint32_t aoff = swzo(w * 16 + (l & 15), ks * 2 + (l >> 4));
                ldsm4(qh, sb + F_QH + aoff);
                ldsm4(ql, sb + F_QL + aoff);
            }
            uint32_t kh[8][2], kl[8][2];
            {
                uint32_t boff = swzo(((l >> 4) << 3) + (l & 7),
                                     ks * 2 + ((l >> 3) & 1));
#pragma unroll
                for (int pg = 0; pg < 4; ++pg) {
                    uint32_t r4[4];
                    ldsm4(r4, kb_hi + boff + pg * 2048);
                    kh[pg * 2][0] = r4[0]; kh[pg * 2][1] = r4[1];
                    kh[pg * 2 + 1][0] = r4[2]; kh[pg * 2 + 1][1] = r4[3];
                    ldsm4(r4, kb_lo + boff + pg * 2048);
                    kl[pg * 2][0] = r4[0]; kl[pg * 2][1] = r4[1];
                    kl[pg * 2 + 1][0] = r4[2]; kl[pg * 2 + 1][1] = r4[3];
                }
            }
#pragma unroll
            for (int nt = 0; nt < 8; ++nt) {
                mma16816(acc[nt], qh, kh[nt]);
                mma16816(acc[nt], qh, kl[nt]);
                mma16816(acc[nt], ql, kh[nt]);
            }
        }

        // ---- P = exp(S)*inv ; store A ; pack P -> A-fragments ----
        uint32_t ph[4][4], pl[4][4];
#pragma unroll
        for (int nt = 0; nt < 8; ++nt) {
            int lc = nt * 8 + 2 * (l & 3);
            float i0 = inv_s[lc], i1 = inv_s[lc + 1];
            float e0 = __expf(acc[nt][0]) * i0;
            float e1 = __expf(acc[nt][1]) * i1;
            float e2 = __expf(acc[nt][2]) * i0;
            float e3 = __expf(acc[nt][3]) * i1;
            int r0 = w * 16 + (l >> 2);
            *reinterpret_cast<float2*>(&ap[(size_t)r0 * LL + kc + lc]) = make_float2(e0, e1);
            *reinterpret_cast<float2*>(&ap[(size_t)(r0 + 8) * LL + kc + lc]) = make_float2(e2, e3);
            float h0, l0, h1, l1, h2, l2, h3, l3;
            split1(e0, h0, l0); split1(e1, h1, l1);
            split1(e2, h2, l2); split1(e3, h3, l3);
            int kb2 = nt >> 1, base = (nt & 1) * 2;
            ph[kb2][base + 0] = pk_bf(h0, h1);
            ph[kb2][base + 1] = pk_bf(h2, h3);
            pl[kb2][base + 0] = pk_bf(l0, l1);
            pl[kb2][base + 1] = pk_bf(l2, l3);
        }

        // ---- O += P @ V (3-pass) ----
#pragma unroll
        for (int kb2 = 0; kb2 < 4; ++kb2) {
            uint32_t vh[8][2], vl[8][2];
            {
                uint32_t boff = swzo(((l >> 4) << 3) + (l & 7),
                                     kb2 * 2 + ((l >> 3) & 1));
#pragma unroll
                for (int pg = 0; pg < 4; ++pg) {
                    uint32_t r4[4];
                    ldsm4(r4, vb_hi + boff + pg * 2048);
                    vh[pg * 2][0] = r4[0]; vh[pg * 2][1] = r4[1];
                    vh[pg * 2 + 1][0] = r4[2]; vh[pg * 2 + 1][1] = r4[3];
                    ldsm4(r4, vb_lo + boff + pg * 2048);
                    vl[pg * 2][0] = r4[0]; vl[pg * 2][1] = r4[1];
                    vl[pg * 2 + 1][0] = r4[2]; vl[pg * 2 + 1][1] = r4[3];
                }
            }
#pragma unroll
            for (int nt = 0; nt < 8; ++nt) {
                mma16816(o[nt], ph[kb2], vh[nt]);
                mma16816(o[nt], ph[kb2], vl[nt]);
                mma16816(o[nt], pl[kb2], vh[nt]);
            }
        }
        __syncthreads();                             // all warps done with buf
    }

    // epilogue: O partial -> g_vals[split]
    float* gv = g_vals[split];
#pragma unroll
    for (int nt = 0; nt < 8; ++nt) {
        int col = nt * 8 + 2 * (l & 3);
        size_t row = (size_t)(b * LL + qb + w * 16 + (l >> 2));
        *reinterpret_cast<float2*>(&gv[row * DD + col]) =
            make_float2(o[nt][0], o[nt][1]);
        *reinterpret_cast<float2*>(&gv[(row + 8) * DD + col]) =
            make_float2(o[nt][2], o[nt][3]);
    }
}

// ---------------------------------------------------------------------------
// Kernel 4: out = (sum_p g_vals[p]) @ Wo + bo. grid (MM/128, OUT/128), 256 thr.
// ---------------------------------------------------------------------------
__global__ __launch_bounds__(256) void out_kernel(
    const float* __restrict__ Wo, const float* __restrict__ bo,
    float* __restrict__ outp)
{
    const int mb = blockIdx.x * 128;
    const int nb = blockIdx.y * 128;
    const int t  = threadIdx.x;
    const int tx = t & 15, ty = t >> 4;

    __shared__ float vt[64 * 128];
    __shared__ float ws[64 * 128];

    {
        const int dq = t & 15, rb = t >> 4;
#pragma unroll
        for (int s = 0; s < 8; ++s) {
            int r = rb + s * 16;
            size_t base = (size_t)(mb + r) * DD + 4 * dq;
            float4 v = *reinterpret_cast<const float4*>(&g_vals[0][base]);
#pragma unroll
            for (int p = 1; p < NPART; ++p) {
                float4 u = *reinterpret_cast<const float4*>(&g_vals[p][base]);
                v.x += u.x; v.y += u.y; v.z += u.z; v.w += u.w;
            }
            vt[swz(4 * dq + 0, r)] = v.x; vt[swz(4 * dq + 1, r)] = v.y;
            vt[swz(4 * dq + 2, r)] = v.z; vt[swz(4 * dq + 3, r)] = v.w;
        }
        const int nq = t & 31, kb2 = t >> 5;
#pragma unroll
        for (int s = 0; s < 8; ++s) {
            int kr = kb2 + s * 8;
            *reinterpret_cast<float4*>(&ws[kr * 128 + 4 * nq]) =
                *reinterpret_cast<const float4*>(&Wo[(size_t)kr * OUT + nb + 4 * nq]);
        }
    }
    __syncthreads();

    u64 acc[32];
#pragma unroll
    for (int i = 0; i < 32; ++i) acc[i] = 0ull;

#pragma unroll 8
    for (int k = 0; k < 64; ++k) {
        float4 a0 = *reinterpret_cast<const float4*>(&vt[swz(k, 4 * ty)]);
        float4 a1 = *reinterpret_cast<const float4*>(&vt[swz(k, 64 + 4 * ty)]);
        float4 b0 = *reinterpret_cast<const float4*>(&ws[k * 128 + 4 * tx]);
        float4 b1 = *reinterpret_cast<const float4*>(&ws[k * 128 + 64 + 4 * tx]);
        rank1(acc, a0, a1, b0, b1);
    }

    float4 bo0 = *reinterpret_cast<const float4*>(&bo[nb + 4 * tx]);
    float4 bo1 = *reinterpret_cast<const float4*>(&bo[nb + 64 + 4 * tx]);
#pragma unroll
    for (int i = 0; i < 8; ++i) {
        int r = (i < 4) ? (4 * ty + i) : (64 + 4 * ty + (i - 4));
        float2 p0 = up2(acc[i * 4 + 0]), p1 = up2(acc[i * 4 + 1]);
        float2 p2 = up2(acc[i * 4 + 2]), p3 = up2(acc[i * 4 + 3]);
        float4 o0 = make_float4(p0.x + bo0.x, p0.y + bo0.y, p1.x + bo0.z, p1.y + bo0.w);
        float4 o1 = make_float4(p2.x + bo1.x, p2.y + bo1.y, p3.x + bo1.z, p3.y + bo1.w);
        *reinterpret_cast<float4*>(&outp[(size_t)(mb + r) * OUT + nb + 4 * tx]) = o0;
        *reinterpret_cast<float4*>(&outp[(size_t)(mb + r) * OUT + nb + 64 + 4 * tx]) = o1;
    }
}

// ---------------------------------------------------------------------------
extern "C" void kernel_launch(void* const* d_in, const int* in_sizes, int n_in,
                              void* d_out, int out_size)
{
    const float* x  = (const float*)d_in[0];
    const float* Wq = (const float*)d_in[1];
    const float* bq = (const float*)d_in[2];
    const float* Wk = (const float*)d_in[3];
    const float* bk = (const float*)d_in[4];
    const float* Wv = (const float*)d_in[5];
    const float* bv = (const float*)d_in[6];
    const float* Wo = (const float*)d_in[7];
    const float* bo = (const float*)d_in[8];

    float* outp = (float*)d_out;                   // [B, L, OUT]
    float* attn = outp + (size_t)BB * LL * OUT;    // [B, L, L]

    cudaFuncSetAttribute(scores_sum, cudaFuncAttributeMaxDynamicSharedMemorySize, S_SMEM);
    cudaFuncSetAttribute(av_fused,   cudaFuncAttributeMaxDynamicSharedMemorySize, F_SMEM);

    qkv_kernel<<<dim3(MM / 128, 3), 128>>>(x, Wq, bq, Wk, bk, Wv, bv);
    vtrans_kernel<<<dim3(LL / 64, BB), 256>>>();
    scores_sum<<<dim3(LL / 128, LL / 128, BB), 256, S_SMEM>>>();
    av_fused<<<dim3(LL / 128, KSPLIT, BB), 256, F_SMEM>>>(attn);
    out_kernel<<<dim3(MM / 128, OUT / 128), 256>>>(Wo, bo, outp);
}

// round 11
// speedup vs baseline: 3.2416x; 1.0820x over previous
#include <cuda_runtime.h>
#include <cuda_bf16.h>
#include <cstdint>

// ---------------------------------------------------------------------------
// AttentionBlock, Round 10: HMMA qkv + 2-pass scores_sum.
//  k1  qkv_mma   : q,k,v = x@W+b via bf16 hi/lo 3-pass HMMA; q pre-scaled;
//                  q,k stored bf16 hi/lo, v fp32.
//  k1b vtrans    : v -> v^T bf16 hi/lo.
//  k2  scores_sum: colsum[b,k] = sum_q exp(S), 2-pass HMMA (qh*kh + qh*kl).
//  k3  av_fused  : recompute S 3-pass, P=exp(S)*inv, write A, O += P@V.
//                  16 q-rows/warp, 64-col chunks, 2 CTAs/SM, cp.async pipe.
//  k4  out       : out = (sum partials) @ Wo + bo (f32x2).
// B=4, L=4096, IN=512, D=64, OUT=512.  Outputs: (out, attention).
// ---------------------------------------------------------------------------

namespace {
constexpr int BB  = 4;
constexpr int LL  = 4096;
constexpr int IN  = 512;
constexpr int DD  = 64;
constexpr int OUT = 512;
constexpr int MM  = BB * LL;
constexpr int KSPLIT = 4;
constexpr int NPART = KSPLIT;
constexpr float SCALE = 0.125f;

// qkv_mma smem
constexpr uint32_t Q_XH = 0, Q_XL = 16384, Q_WH = 32768, Q_WL = 40960,
                   Q_ST = 49152, Q_SMEM = 49152 + 16384;   // 65536
// scores_sum smem (QL slot unused now, layout kept)
constexpr uint32_t S_QH = 0, S_KH = 32768, S_KL = 49152,
                   S_RED = 65536, S_SMEM = 65536 + 2048;
// av_fused smem: Q hi/lo, 2 k/v buffers of 32KB, double-buffered inv.
constexpr uint32_t F_QH = 0, F_QL = 16384, F_KV = 32768,
                   F_INV = 98304, F_SMEM = 98304 + 512;
}

typedef unsigned long long u64;

// ------------------------------- helpers -----------------------------------
__device__ __forceinline__ uint32_t smem_u32(const void* p) {
    uint32_t a;
    asm("{ .reg .u64 t; cvta.to.shared.u64 t, %1; cvt.u32.u64 %0, t; }" : "=r"(a) : "l"(p));
    return a;
}
// swizzled byte offset in a [rows][64 bf16] tile (128B rows, 16B units)
__device__ __forceinline__ uint32_t swzo(int r, int c16) {
    return (uint32_t)(r * 128 + ((c16 ^ (r & 7)) << 4));
}
__device__ __forceinline__ void ldsm4(uint32_t r[4], uint32_t addr) {
    asm volatile("ldmatrix.sync.aligned.m8n8.x4.shared.b16 {%0,%1,%2,%3}, [%4];"
        : "=r"(r[0]), "=r"(r[1]), "=r"(r[2]), "=r"(r[3]) : "r"(addr));
}
__device__ __forceinline__ void mma16816(float c[4], const uint32_t a[4], const uint32_t b[2]) {
    asm volatile("mma.sync.aligned.m16n8k16.row.col.f32.bf16.bf16.f32 "
        "{%0,%1,%2,%3}, {%4,%5,%6,%7}, {%8,%9}, {%0,%1,%2,%3};"
        : "+f"(c[0]), "+f"(c[1]), "+f"(c[2]), "+f"(c[3])
        : "r"(a[0]), "r"(a[1]), "r"(a[2]), "r"(a[3]), "r"(b[0]), "r"(b[1]));
}
__device__ __forceinline__ uint32_t pk_bf(float a, float b) {
    return (uint32_t)__bfloat16_as_ushort(__float2bfloat16(a)) |
           ((uint32_t)__bfloat16_as_ushort(__float2bfloat16(b)) << 16);
}
__device__ __forceinline__ void split1(float v, float& hi, float& lo) {
    __nv_bfloat16 h = __float2bfloat16(v);
    hi = __bfloat162float(h);
    lo = v - hi;
}
// 8 consecutive floats -> bf16 hi/lo uint4s
__device__ __forceinline__ void split8(const float4& a, const float4& c, uint4& hi, uint4& lo) {
    float h0, l0, h1, l1;
    split1(a.x, h0, l0); split1(a.y, h1, l1);
    hi.x = pk_bf(h0, h1); lo.x = pk_bf(l0, l1);
    split1(a.z, h0, l0); split1(a.w, h1, l1);
    hi.y = pk_bf(h0, h1); lo.y = pk_bf(l0, l1);
    split1(c.x, h0, l0); split1(c.y, h1, l1);
    hi.z = pk_bf(h0, h1); lo.z = pk_bf(l0, l1);
    split1(c.z, h0, l0); split1(c.w, h1, l1);
    hi.w = pk_bf(h0, h1); lo.w = pk_bf(l0, l1);
}
__device__ __forceinline__ void cpa16(uint32_t s, const void* g) {
    asm volatile("cp.async.cg.shared.global [%0], [%1], 16;" :: "r"(s), "l"(g) : "memory");
}
#define CPA_COMMIT() asm volatile("cp.async.commit_group;" ::: "memory")

// ---------------------------- f32x2 (out) ----------------------------------
__device__ __forceinline__ void fma2(u64 &d, u64 a, u64 b) {
    asm("fma.rn.f32x2 %0, %1, %2, %0;" : "+l"(d) : "l"(a), "l"(b));
}
__device__ __forceinline__ u64 dup2(float a) {
    u64 r; asm("mov.b64 %0, {%1, %1};" : "=l"(r) : "f"(a)); return r;
}
__device__ __forceinline__ u64 pk2(float lo, float hi) {
    u64 r; asm("mov.b64 %0, {%1, %2};" : "=l"(r) : "f"(lo), "f"(hi)); return r;
}
__device__ __forceinline__ float2 up2(u64 v) {
    float2 r; asm("mov.b64 {%0, %1}, %2;" : "=f"(r.x), "=f"(r.y) : "l"(v)); return r;
}
__device__ __forceinline__ int swz(int d, int c) { return d * 128 + (c ^ (d & 28)); }

__device__ __forceinline__ void rank1(u64* acc, float4 a0, float4 a1,
                                      float4 b0, float4 b1)
{
    u64 bp0 = pk2(b0.x, b0.y), bp1 = pk2(b0.z, b0.w);
    u64 bp2 = pk2(b1.x, b1.y), bp3 = pk2(b1.z, b1.w);
    float av[8] = {a0.x, a0.y, a0.z, a0.w, a1.x, a1.y, a1.z, a1.w};
#pragma unroll
    for (int i = 0; i < 8; ++i) {
        u64 ad = dup2(av[i]);
        fma2(acc[i * 4 + 0], ad, bp0);
        fma2(acc[i * 4 + 1], ad, bp1);
        fma2(acc[i * 4 + 2], ad, bp2);
        fma2(acc[i * 4 + 3], ad, bp3);
    }
}

// ------------------------------ device scratch -----------------------------
__device__ __nv_bfloat16 g_qh[MM * DD], g_ql[MM * DD];   // q (pre-scaled) hi/lo
__device__ __nv_bfloat16 g_kh[MM * DD], g_kl[MM * DD];   // k hi/lo
__device__ float g_v[MM * DD];
__device__ float g_colsum[MM];
__device__ float g_vals[NPART][MM * DD];
__device__ __nv_bfloat16 g_vt_hi[BB * DD * LL];          // v^T hi [b][d][k]
__device__ __nv_bfloat16 g_vt_lo[BB * DD * LL];

// ---------------------------------------------------------------------------
// Kernel 1: qkv_mma.  q,k,v = x@W+b via 3-pass bf16 HMMA.
// grid (MM/128, 3), 256 thr.  Also zeroes g_colsum.
// ---------------------------------------------------------------------------
__global__ __launch_bounds__(256) void qkv_mma(
    const float* __restrict__ x,
    const float* __restrict__ Wq, const float* __restrict__ bq,
    const float* __restrict__ Wk, const float* __restrict__ bk,
    const float* __restrict__ Wv, const float* __restrict__ bv)
{
    extern __shared__ char smem[];
    const uint32_t sb = smem_u32(smem);
    const int t = threadIdx.x, l = t & 31, w = t >> 5;
    const int gid = (blockIdx.y * gridDim.x + blockIdx.x) * 256 + t;
    if (gid < MM) g_colsum[gid] = 0.f;

    const float* W; const float* bias; float oscale;
    __nv_bfloat16 *oh = nullptr, *ol = nullptr;
    if (blockIdx.y == 0)      { W = Wq; bias = bq; oh = g_qh; ol = g_ql; oscale = SCALE; }
    else if (blockIdx.y == 1) { W = Wk; bias = bk; oh = g_kh; ol = g_kl; oscale = 1.f; }
    else                      { W = Wv; bias = bv; oscale = 1.f; }
    const bool isv = (blockIdx.y == 2);
    const int mb = blockIdx.x * 128;

    float* stg = (float*)(smem + Q_ST);              // W fp32 stage [64][64]

    float acc[8][4];
#pragma unroll
    for (int nt = 0; nt < 8; ++nt)
#pragma unroll
        for (int j = 0; j < 4; ++j) acc[nt][j] = 0.f;

    for (int kc = 0; kc < IN; kc += 64) {
        __syncthreads();                             // smem reuse guard
        // x tile [128 rows][64 k] -> XH/XL (split bf16, swizzled)
#pragma unroll
        for (int s = 0; s < 4; ++s) {
            int u = t + 256 * s;
            int r = u >> 3, c16 = u & 7;
            const float* xp = &x[(size_t)(mb + r) * IN + kc + c16 * 8];
            float4 a = *reinterpret_cast<const float4*>(xp);
            float4 c = *reinterpret_cast<const float4*>(xp + 4);
            uint4 hi, lo;
            split8(a, c, hi, lo);
            uint32_t off = swzo(r, c16);
            *(uint4*)(smem + Q_XH + off) = hi;
            *(uint4*)(smem + Q_XL + off) = lo;
        }
        // W fp32 stage [k][n] coalesced
#pragma unroll
        for (int s = 0; s < 4; ++s) {
            int u = t + 256 * s;
            int k = u >> 4, c4 = u & 15;
            *reinterpret_cast<float4*>(&stg[k * 64 + 4 * c4]) =
                *reinterpret_cast<const float4*>(&W[(size_t)(kc + k) * DD + 4 * c4]);
        }
        __syncthreads();
        // transpose + split -> WH/WL [n][k]  (lane-contiguous n: conflict-free)
#pragma unroll
        for (int s = 0; s < 2; ++s) {
            int u = t + 256 * s;
            int k16 = u >> 6, n = u & 63;
            union { __nv_bfloat16 h[8]; uint4 u4; } hi, lo;
#pragma unroll
            for (int j = 0; j < 8; ++j) {
                float v = stg[(k16 * 8 + j) * 64 + n];
                __nv_bfloat16 hb = __float2bfloat16(v);
                hi.h[j] = hb;
                lo.h[j] = __float2bfloat16(v - __bfloat162float(hb));
            }
            uint32_t off = swzo(n, k16);
            *(uint4*)(smem + Q_WH + off) = hi.u4;
            *(uint4*)(smem + Q_WL + off) = lo.u4;
        }
        __syncthreads();
        // 3-pass MMA: acc += XH*WH + XH*WL + XL*WH
#pragma unroll
        for (int ks = 0; ks < 4; ++ks) {
            uint32_t xh[4], xl[4];
            uint32_t aoff = swzo(w * 16 + (l & 15), ks * 2 + (l >> 4));
            ldsm4(xh, sb + Q_XH + aoff);
            ldsm4(xl, sb + Q_XL + aoff);
            uint32_t wh[8][2], wl[8][2];
            uint32_t boff = swzo(((l >> 4) << 3) + (l & 7), ks * 2 + ((l >> 3) & 1));
#pragma unroll
            for (int pg = 0; pg < 4; ++pg) {
                uint32_t r4[4];
                ldsm4(r4, sb + Q_WH + boff + pg * 2048);
                wh[pg * 2][0] = r4[0]; wh[pg * 2][1] = r4[1];
                wh[pg * 2 + 1][0] = r4[2]; wh[pg * 2 + 1][1] = r4[3];
                ldsm4(r4, sb + Q_WL + boff + pg * 2048);
                wl[pg * 2][0] = r4[0]; wl[pg * 2][1] = r4[1];
                wl[pg * 2 + 1][0] = r4[2]; wl[pg * 2 + 1][1] = r4[3];
            }
#pragma unroll
            for (int nt = 0; nt < 8; ++nt) {
                mma16816(acc[nt], xh, wh[nt]);
                mma16816(acc[nt], xh, wl[nt]);
                mma16816(acc[nt], xl, wh[nt]);
            }
        }
    }
    // epilogue
#pragma unroll
    for (int nt = 0; nt < 8; ++nt) {
        int col = nt * 8 + 2 * (l & 3);
        float b0 = bias[col], b1 = bias[col + 1];
        int r0 = mb + w * 16 + (l >> 2);
        float e0 = (acc[nt][0] + b0) * oscale;
        float e1 = (acc[nt][1] + b1) * oscale;
        float e2 = (acc[nt][2] + b0) * oscale;
        float e3 = (acc[nt][3] + b1) * oscale;
        if (isv) {
            *reinterpret_cast<float2*>(&g_v[(size_t)r0 * DD + col]) = make_float2(e0, e1);
            *reinterpret_cast<float2*>(&g_v[(size_t)(r0 + 8) * DD + col]) = make_float2(e2, e3);
        } else {
            float h0, l0_, h1, l1_, h2, l2_, h3, l3_;
            split1(e0, h0, l0_); split1(e1, h1, l1_);
            split1(e2, h2, l2_); split1(e3, h3, l3_);
            *reinterpret_cast<uint32_t*>(&oh[(size_t)r0 * DD + col]) = pk_bf(h0, h1);
            *reinterpret_cast<uint32_t*>(&ol[(size_t)r0 * DD + col]) = pk_bf(l0_, l1_);
            *reinterpret_cast<uint32_t*>(&oh[(size_t)(r0 + 8) * DD + col]) = pk_bf(h2, h3);
            *reinterpret_cast<uint32_t*>(&ol[(size_t)(r0 + 8) * DD + col]) = pk_bf(l2_, l3_);
        }
    }
}

// ---------------------------------------------------------------------------
// Kernel 1b: v[b][k][d] -> bf16 hi/lo transposed g_vt[b][d][k].
// grid (LL/64, BB), 256 thr.
// ---------------------------------------------------------------------------
__global__ __launch_bounds__(256) void vtrans_kernel()
{
    const int b = blockIdx.y, kb = blockIdx.x * 64;
    const int t = threadIdx.x;
    __shared__ float tile[64][68];

    const int c4 = t & 15, r0 = t >> 4;
#pragma unroll
    for (int s = 0; s < 4; ++s) {
        int r = r0 + 16 * s;
        float4 v = *reinterpret_cast<const float4*>(&g_v[(size_t)(b * LL + kb + r) * DD + 4 * c4]);
        tile[r][4 * c4 + 0] = v.x; tile[r][4 * c4 + 1] = v.y;
        tile[r][4 * c4 + 2] = v.z; tile[r][4 * c4 + 3] = v.w;
    }
    __syncthreads();

    const int f8 = t & 7, d0 = t >> 3;
#pragma unroll
    for (int s = 0; s < 2; ++s) {
        int d = d0 + 32 * s;
        union { __nv_bfloat16 h[8]; uint4 u; } hi, lo;
#pragma unroll
        for (int j = 0; j < 8; ++j) {
            float v = tile[f8 * 8 + j][d];
            __nv_bfloat16 hb = __float2bfloat16(v);
            hi.h[j] = hb;
            lo.h[j] = __float2bfloat16(v - __bfloat162float(hb));
        }
        size_t o = (size_t)(b * DD + d) * LL + kb + f8 * 8;
        *reinterpret_cast<uint4*>(&g_vt_hi[o]) = hi.u;
        *reinterpret_cast<uint4*>(&g_vt_lo[o]) = lo.u;
    }
}

// ---------------------------------------------------------------------------
// Kernel 2: scores_sum (2-pass).  colsum[b,k] += sum_q exp(S[q,k]).
// S approx = qh*(kh+kl); dropped ql*kh averages out over column sums.
// grid (L/128 kb, L/128 qb, B), 256 thr, 2 CTAs/SM.
// ---------------------------------------------------------------------------
__global__ __launch_bounds__(256, 2) void scores_sum(void)
{
    extern __shared__ char smem[];
    const uint32_t sb = smem_u32(smem);
    const int t = threadIdx.x, l = t & 31, w = t >> 5;
    const int wm = w & 3, wn = w >> 2;
    const int b = blockIdx.z, qb = blockIdx.y * 128, kb = blockIdx.x * 128;

    {
        const size_t qo = (size_t)(b * LL + qb) * DD;
        const size_t ko = (size_t)(b * LL + kb) * DD;
#pragma unroll
        for (int s = 0; s < 4; ++s) {
            int u = t + 256 * s;
            int r = u >> 3, c16 = u & 7;
            uint32_t off = swzo(r, c16);
            size_t gi = qo + (size_t)r * DD + c16 * 8;
            *(uint4*)(smem + S_QH + off) = *reinterpret_cast<const uint4*>(&g_qh[gi]);
            gi = ko + (size_t)r * DD + c16 * 8;
            *(uint4*)(smem + S_KH + off) = *reinterpret_cast<const uint4*>(&g_kh[gi]);
            *(uint4*)(smem + S_KL + off) = *reinterpret_cast<const uint4*>(&g_kl[gi]);
        }
    }
    __syncthreads();

    float acc[2][8][4];
#pragma unroll
    for (int mt = 0; mt < 2; ++mt)
#pragma unroll
        for (int nt = 0; nt < 8; ++nt)
#pragma unroll
            for (int j = 0; j < 4; ++j) acc[mt][nt][j] = 0.f;

#pragma unroll
    for (int ks = 0; ks < 4; ++ks) {
        uint32_t qh[2][4];
        {
            uint32_t aoff = swzo(wm * 32 + (l & 15), ks * 2 + (l >> 4));
            ldsm4(qh[0], sb + S_QH + aoff);
            ldsm4(qh[1], sb + S_QH + aoff + 2048);
        }
        uint32_t kh[8][2], kl[8][2];
        {
            uint32_t boff = swzo(wn * 64 + ((l >> 4) << 3) + (l & 7),
                                 ks * 2 + ((l >> 3) & 1));
#pragma unroll
            for (int pg = 0; pg < 4; ++pg) {
                uint32_t r4[4];
                ldsm4(r4, sb + S_KH + boff + pg * 2048);
                kh[pg * 2][0] = r4[0]; kh[pg * 2][1] = r4[1];
                kh[pg * 2 + 1][0] = r4[2]; kh[pg * 2 + 1][1] = r4[3];
                ldsm4(r4, sb + S_KL + boff + pg * 2048);
                kl[pg * 2][0] = r4[0]; kl[pg * 2][1] = r4[1];
                kl[pg * 2 + 1][0] = r4[2]; kl[pg * 2 + 1][1] = r4[3];
            }
        }
#pragma unroll
        for (int mt = 0; mt < 2; ++mt)
#pragma unroll
            for (int nt = 0; nt < 8; ++nt) {
                mma16816(acc[mt][nt], qh[mt], kh[nt]);
                mma16816(acc[mt][nt], qh[mt], kl[nt]);
            }
    }

    float* colred = (float*)(smem + S_RED);
#pragma unroll
    for (int nt = 0; nt < 8; ++nt) {
        float cs0 = 0.f, cs1 = 0.f;
#pragma unroll
        for (int mt = 0; mt < 2; ++mt) {
            cs0 += __expf(acc[mt][nt][0]) + __expf(acc[mt][nt][2]);
            cs1 += __expf(acc[mt][nt][1]) + __expf(acc[mt][nt][3]);
        }
#pragma unroll
        for (int m = 4; m < 32; m <<= 1) {
            cs0 += __shfl_xor_sync(0xffffffffu, cs0, m);
            cs1 += __shfl_xor_sync(0xffffffffu, cs1, m);
        }
        if (l < 4) {
            colred[wm * 128 + wn * 64 + nt * 8 + 2 * l + 0] = cs0;
            colred[wm * 128 + wn * 64 + nt * 8 + 2 * l + 1] = cs1;
        }
    }
    __syncthreads();
    if (t < 128) {
        float s = colred[t] + colred[128 + t] + colred[256 + t] + colred[384 + t];
        atomicAdd(&g_colsum[b * LL + kb + t], s);
    }
}

// ---------------------------------------------------------------------------
// Kernel 3: av_fused.  16 q-rows/warp, 64-col chunks, 2 CTAs/SM,
// cp.async double-buffered k/v.  Recompute S (3-pass), P = exp(S)*inv,
// write A, O += P@V via fragment reuse.  grid (L/128, KSPLIT, B), 256 thr.
// ---------------------------------------------------------------------------
__global__ __launch_bounds__(256, 2) void av_fused(float* __restrict__ attn)
{
    extern __shared__ char smem[];
    const uint32_t sb = smem_u32(smem);
    const int t = threadIdx.x, l = t & 31, w = t >> 5;
    const int b = blockIdx.z, split = blockIdx.y, qb = blockIdx.x * 128;
    const int kBeg = split * (LL / KSPLIT);
    constexpr int NCH = (LL / KSPLIT) / 64;          // 16 chunks

    float* invb = (float*)(smem + F_INV);            // [2][64]
    const float* cs = g_colsum + b * LL;
    float* ap = attn + (size_t)(b * LL + qb) * LL;

    // q tiles once (128 rows x 64 d, hi/lo)
    {
        const size_t qo = (size_t)(b * LL + qb) * DD;
#pragma unroll
        for (int s = 0; s < 4; ++s) {
            int u = t + 256 * s;
            int r = u >> 3, c16 = u & 7;
            uint32_t off = swzo(r, c16);
            size_t gi = qo + (size_t)r * DD + c16 * 8;
            *(uint4*)(smem + F_QH + off) = *reinterpret_cast<const uint4*>(&g_qh[gi]);
            *(uint4*)(smem + F_QL + off) = *reinterpret_cast<const uint4*>(&g_ql[gi]);
        }
    }
    if (t < 64) invb[t] = 1.f / cs[kBeg + t];

    auto issue = [&](int ci) {
        const int kc = kBeg + ci * 64;
        const uint32_t base = sb + F_KV + (uint32_t)(ci & 1) * 32768;
        const size_t ko = (size_t)(b * LL + kc) * DD;
#pragma unroll
        for (int s = 0; s < 2; ++s) {
            int u = t + 256 * s;
            int r = u >> 3, c16 = u & 7;
            uint32_t off = swzo(r, c16);
            size_t gk = ko + (size_t)r * DD + c16 * 8;
            cpa16(base + off,         &g_kh[gk]);
            cpa16(base + 8192 + off,  &g_kl[gk]);
            size_t gv = (size_t)(b * DD + r) * LL + kc + c16 * 8;
            cpa16(base + 16384 + off, &g_vt_hi[gv]);
            cpa16(base + 24576 + off, &g_vt_lo[gv]);
        }
        CPA_COMMIT();
    };
    issue(0);

    float o[8][4];
#pragma unroll
    for (int nt = 0; nt < 8; ++nt)
#pragma unroll
        for (int j = 0; j < 4; ++j) o[nt][j] = 0.f;

    for (int ci = 0; ci < NCH; ++ci) {
        const int kc = kBeg + ci * 64;
        if (ci + 1 < NCH) {
            issue(ci + 1);
            asm volatile("cp.async.wait_group 1;" ::: "memory");
        } else {
            asm volatile("cp.async.wait_group 0;" ::: "memory");
        }
        __syncthreads();

        if (ci + 1 < NCH && t < 64)
            invb[((ci + 1) & 1) * 64 + t] = 1.f / cs[kc + 64 + t];

        const uint32_t kb_hi = sb + F_KV + (uint32_t)(ci & 1) * 32768;
        const uint32_t kb_lo = kb_hi + 8192;
        const uint32_t vb_hi = kb_hi + 16384;
        const uint32_t vb_lo = kb_hi + 24576;
        const float* inv_s = invb + (ci & 1) * 64;

        // ---- S = q k^T (3-pass) ----
        float acc[8][4];
#pragma unroll
        for (int nt = 0; nt < 8; ++nt)
#pragma unroll
            for (int j = 0; j < 4; ++j) acc[nt][j] = 0.f;

#pragma unroll
        for (int ks = 0; ks < 4; ++ks) {
            uint32_t qh[4], ql[4];
            {
                uint32_t aoff = swzo(w * 16 + (l & 15), ks * 2 + (l >> 4));
                ldsm4(qh, sb + F_QH + aoff);
                ldsm4(ql, sb + F_QL + aoff);
            }
            uint32_t kh[8][2], kl[8][2];
            {
                uint32_t boff = swzo(((l >> 4) << 3) + (l & 7),
                                     ks * 2 + ((l >> 3) & 1));
#pragma unroll
                for (int pg = 0; pg < 4; ++pg) {
                    uint32_t r4[4];
                    ldsm4(r4, kb_hi + boff + pg * 2048);
                    kh[pg * 2][0] = r4[0]; kh[pg * 2][1] = r4[1];
                    kh[pg * 2 + 1][0] = r4[2]; kh[pg * 2 + 1][1] = r4[3];
                    ldsm4(r4, kb_lo + boff + pg * 2048);
                    kl[pg * 2][0] = r4[0]; kl[pg * 2][1] = r4[1];
                    kl[pg * 2 + 1][0] = r4[2]; kl[pg * 2 + 1][1] = r4[3];
                }
            }
#pragma unroll
            for (int nt = 0; nt < 8; ++nt) {
                mma16816(acc[nt], qh, kh[nt]);
                mma16816(acc[nt], qh, kl[nt]);
                mma16816(acc[nt], ql, kh[nt]);
            }
        }

        // ---- P = exp(S)*inv ; store A ; pack P -> A-fragments ----
        uint32_t ph[4][4], pl[4][4];
#pragma unroll
        for (int nt = 0; nt < 8; ++nt) {
            int lc = nt * 8 + 2 * (l & 3);
            float i0 = inv_s[lc], i1 = inv_s[lc + 1];
            float e0 = __expf(acc[nt][0]) * i0;
            float e1 = __expf(acc[nt][1]) * i1;
            float e2 = __expf(acc[nt][2]) * i0;
            float e3 = __expf(acc[nt][3]) * i1;
            int r0 = w * 16 + (l >> 2);
            *reinterpret_cast<float2*>(&ap[(size_t)r0 * LL + kc + lc]) = make_float2(e0, e1);
            *reinterpret_cast<float2*>(&ap[(size_t)(r0 + 8) * LL + kc + lc]) = make_float2(e2, e3);
            float h0, l0, h1, l1, h2, l2, h3, l3;
            split1(e0, h0, l0); split1(e1, h1, l1);
            split1(e2, h2, l2); split1(e3, h3, l3);
            int kb2 = nt >> 1, base = (nt & 1) * 2;
            ph[kb2][base + 0] = pk_bf(h0, h1);
            ph[kb2][base + 1] = pk_bf(h2, h3);
            pl[kb2][base + 0] = pk_bf(l0, l1);
            pl[kb2][base + 1] = pk_bf(l2, l3);
        }

        // ---- O += P @ V (3-pass) ----
#pragma unroll
        for (int kb2 = 0; kb2 < 4; ++kb2) {
            uint32_t vh[8][2], vl[8][2];
            {
                uint32_t boff = swzo(((l >> 4) << 3) + (l & 7),
                                     kb2 * 2 + ((l >> 3) & 1));
#pragma unroll
                for (int pg = 0; pg < 4; ++pg) {
                    uint32_t r4[4];
                    ldsm4(r4, vb_hi + boff + pg * 2048);
                    vh[pg * 2][0] = r4[0]; vh[pg * 2][1] = r4[1];
                    vh[pg * 2 + 1][0] = r4[2]; vh[pg * 2 + 1][1] = r4[3];
                    ldsm4(r4, vb_lo + boff + pg * 2048);
                    vl[pg * 2][0] = r4[0]; vl[pg * 2][1] = r4[1];
                    vl[pg * 2 + 1][0] = r4[2]; vl[pg * 2 + 1][1] = r4[3];
                }
            }
#pragma unroll
            for (int nt = 0; nt < 8; ++nt) {
                mma16816(o[nt], ph[kb2], vh[nt]);
                mma16816(o[nt], ph[kb2], vl[nt]);
                mma16816(o[nt], pl[kb2], vh[nt]);
            }
        }
        __syncthreads();
    }

    float* gv = g_vals[split];
#pragma unroll
    for (int nt = 0; nt < 8; ++nt) {
        int col = nt * 8 + 2 * (l & 3);
        size_t row = (size_t)(b * LL + qb + w * 16 + (l >> 2));
        *reinterpret_cast<float2*>(&gv[row * DD + col]) =
            make_float2(o[nt][0], o[nt][1]);
        *reinterpret_cast<float2*>(&gv[(row + 8) * DD + col]) =
            make_float2(o[nt][2], o[nt][3]);
    }
}

// ---------------------------------------------------------------------------
// Kernel 4: out = (sum_p g_vals[p]) @ Wo + bo. grid (MM/128, OUT/128), 256 thr.
// ---------------------------------------------------------------------------
__global__ __launch_bounds__(256) void out_kernel(
    const float* __restrict__ Wo, const float* __restrict__ bo,
    float* __restrict__ outp)
{
    const int mb = blockIdx.x * 128;
    const int nb = blockIdx.y * 128;
    const int t  = threadIdx.x;
    const int tx = t & 15, ty = t >> 4;

    __shared__ float vt[64 * 128];
    __shared__ float ws[64 * 128];

    {
        const int dq = t & 15, rb = t >> 4;
#pragma unroll
        for (int s = 0; s < 8; ++s) {
            int r = rb + s * 16;
            size_t base = (size_t)(mb + r) * DD + 4 * dq;
            float4 v = *reinterpret_cast<const float4*>(&g_vals[0][base]);
#pragma unroll
            for (int p = 1; p < NPART; ++p) {
                float4 u = *reinterpret_cast<const float4*>(&g_vals[p][base]);
                v.x += u.x; v.y += u.y; v.z += u.z; v.w += u.w;
            }
            vt[swz(4 * dq + 0, r)] = v.x; vt[swz(4 * dq + 1, r)] = v.y;
            vt[swz(4 * dq + 2, r)] = v.z; vt[swz(4 * dq + 3, r)] = v.w;
        }
        const int nq = t & 31, kb2 = t >> 5;
#pragma unroll
        for (int s = 0; s < 8; ++s) {
            int kr = kb2 + s * 8;
            *reinterpret_cast<float4*>(&ws[kr * 128 + 4 * nq]) =
                *reinterpret_cast<const float4*>(&Wo[(size_t)kr * OUT + nb + 4 * nq]);
        }
    }
    __syncthreads();

    u64 acc[32];
#pragma unroll
    for (int i = 0; i < 32; ++i) acc[i] = 0ull;

#pragma unroll 8
    for (int k = 0; k < 64; ++k) {
        float4 a0 = *reinterpret_cast<const float4*>(&vt[swz(k, 4 * ty)]);
        float4 a1 = *reinterpret_cast<const float4*>(&vt[swz(k, 64 + 4 * ty)]);
        float4 b0 = *reinterpret_cast<const float4*>(&ws[k * 128 + 4 * tx]);
        float4 b1 = *reinterpret_cast<const float4*>(&ws[k * 128 + 64 + 4 * tx]);
        rank1(acc, a0, a1, b0, b1);
    }

    float4 bo0 = *reinterpret_cast<const float4*>(&bo[nb + 4 * tx]);
    float4 bo1 = *reinterpret_cast<const float4*>(&bo[nb + 64 + 4 * tx]);
#pragma unroll
    for (int i = 0; i < 8; ++i) {
        int r = (i < 4) ? (4 * ty + i) : (64 + 4 * ty + (i - 4));
        float2 p0 = up2(acc[i * 4 + 0]), p1 = up2(acc[i * 4 + 1]);
        float2 p2 = up2(acc[i * 4 + 2]), p3 = up2(acc[i * 4 + 3]);
        float4 o0 = make_float4(p0.x + bo0.x, p0.y + bo0.y, p1.x + bo0.z, p1.y + bo0.w);
        float4 o1 = make_float4(p2.x + bo1.x, p2.y + bo1.y, p3.x + bo1.z, p3.y + bo1.w);
        *reinterpret_cast<float4*>(&outp[(size_t)(mb + r) * OUT + nb + 4 * tx]) = o0;
        *reinterpret_cast<float4*>(&outp[(size_t)(mb + r) * OUT + nb + 64 + 4 * tx]) = o1;
    }
}

// ---------------------------------------------------------------------------
extern "C" void kernel_launch(void* const* d_in, const int* in_sizes, int n_in,
                              void* d_out, int out_size)
{
    const float* x  = (const float*)d_in[0];
    const float* Wq = (const float*)d_in[1];
    const float* bq = (const float*)d_in[2];
    const float* Wk = (const float*)d_in[3];
    const float* bk = (const float*)d_in[4];
    const float* Wv = (const float*)d_in[5];
    const float* bv = (const float*)d_in[6];
    const float* Wo = (const float*)d_in[7];
    const float* bo = (const float*)d_in[8];

    float* outp = (float*)d_out;                   // [B, L, OUT]
    float* attn = outp + (size_t)BB * LL * OUT;    // [B, L, L]

    cudaFuncSetAttribute(qkv_mma,    cudaFuncAttributeMaxDynamicSharedMemorySize, Q_SMEM);
    cudaFuncSetAttribute(scores_sum, cudaFuncAttributeMaxDynamicSharedMemorySize, S_SMEM);
    cudaFuncSetAttribute(av_fused,   cudaFuncAttributeMaxDynamicSharedMemorySize, F_SMEM);

    qkv_mma<<<dim3(MM / 128, 3), 256, Q_SMEM>>>(x, Wq, bq, Wk, bk, Wv, bv);
    vtrans_kernel<<<dim3(LL / 64, BB), 256>>>();
    scores_sum<<<dim3(LL / 128, LL / 128, BB), 256, S_SMEM>>>();
    av_fused<<<dim3(LL / 128, KSPLIT, BB), 256, F_SMEM>>>(attn);
    out_kernel<<<dim3(MM / 128, OUT / 128), 256>>>(Wo, bo, outp);
}

// round 12
// speedup vs baseline: 3.6046x; 1.1120x over previous
#include <cuda_runtime.h>
#include <cuda_bf16.h>
#include <cuda_fp16.h>
#include <cstdint>

// ---------------------------------------------------------------------------
// AttentionBlock, Round 11: fp16 single-pass P in the O-GEMM.
//  k1  qkv_mma   : q,k,v = x@W+b via bf16 hi/lo 3-pass HMMA; q pre-scaled.
//  k1b vtrans    : v -> v^T fp16 hi + fp16 residual.
//  k2  scores_sum: colsum[b,k] = sum_q exp(S), 2-pass HMMA.
//  k3  av_fused  : recompute S 3-pass bf16, P=exp(S)*inv (fp32 store to attn,
//                  fp16 pack for MMA), O += P@V 2-pass fp16.
//  k4  out       : out = (sum partials) @ Wo + bo (f32x2).
// B=4, L=4096, IN=512, D=64, OUT=512.  Outputs: (out, attention).
// ---------------------------------------------------------------------------

namespace {
constexpr int BB  = 4;
constexpr int LL  = 4096;
constexpr int IN  = 512;
constexpr int DD  = 64;
constexpr int OUT = 512;
constexpr int MM  = BB * LL;
constexpr int KSPLIT = 4;
constexpr int NPART = KSPLIT;
constexpr float SCALE = 0.125f;

// qkv_mma smem
constexpr uint32_t Q_XH = 0, Q_XL = 16384, Q_WH = 32768, Q_WL = 40960,
                   Q_ST = 49152, Q_SMEM = 49152 + 16384;   // 65536
// scores_sum smem
constexpr uint32_t S_QH = 0, S_KH = 32768, S_KL = 49152,
                   S_RED = 65536, S_SMEM = 65536 + 2048;
// av_fused smem: Q hi/lo, 2 k/v buffers of 32KB, double-buffered inv.
constexpr uint32_t F_QH = 0, F_QL = 16384, F_KV = 32768,
                   F_INV = 98304, F_SMEM = 98304 + 512;
}

typedef unsigned long long u64;

// ------------------------------- helpers -----------------------------------
__device__ __forceinline__ uint32_t smem_u32(const void* p) {
    uint32_t a;
    asm("{ .reg .u64 t; cvta.to.shared.u64 t, %1; cvt.u32.u64 %0, t; }" : "=r"(a) : "l"(p));
    return a;
}
// swizzled byte offset in a [rows][64 x 16-bit] tile (128B rows, 16B units)
__device__ __forceinline__ uint32_t swzo(int r, int c16) {
    return (uint32_t)(r * 128 + ((c16 ^ (r & 7)) << 4));
}
__device__ __forceinline__ void ldsm4(uint32_t r[4], uint32_t addr) {
    asm volatile("ldmatrix.sync.aligned.m8n8.x4.shared.b16 {%0,%1,%2,%3}, [%4];"
        : "=r"(r[0]), "=r"(r[1]), "=r"(r[2]), "=r"(r[3]) : "r"(addr));
}
__device__ __forceinline__ void mma16816(float c[4], const uint32_t a[4], const uint32_t b[2]) {
    asm volatile("mma.sync.aligned.m16n8k16.row.col.f32.bf16.bf16.f32 "
        "{%0,%1,%2,%3}, {%4,%5,%6,%7}, {%8,%9}, {%0,%1,%2,%3};"
        : "+f"(c[0]), "+f"(c[1]), "+f"(c[2]), "+f"(c[3])
        : "r"(a[0]), "r"(a[1]), "r"(a[2]), "r"(a[3]), "r"(b[0]), "r"(b[1]));
}
__device__ __forceinline__ void mma16816h(float c[4], const uint32_t a[4], const uint32_t b[2]) {
    asm volatile("mma.sync.aligned.m16n8k16.row.col.f32.f16.f16.f32 "
        "{%0,%1,%2,%3}, {%4,%5,%6,%7}, {%8,%9}, {%0,%1,%2,%3};"
        : "+f"(c[0]), "+f"(c[1]), "+f"(c[2]), "+f"(c[3])
        : "r"(a[0]), "r"(a[1]), "r"(a[2]), "r"(a[3]), "r"(b[0]), "r"(b[1]));
}
__device__ __forceinline__ uint32_t pk_bf(float a, float b) {
    return (uint32_t)__bfloat16_as_ushort(__float2bfloat16(a)) |
           ((uint32_t)__bfloat16_as_ushort(__float2bfloat16(b)) << 16);
}
// packed fp16x2: lo = a, hi = b (single cvt instruction)
__device__ __forceinline__ uint32_t pk_f16(float a, float b) {
    uint32_t r;
    asm("cvt.rn.f16x2.f32 %0, %1, %2;" : "=r"(r) : "f"(b), "f"(a));
    return r;
}
__device__ __forceinline__ void split1(float v, float& hi, float& lo) {
    __nv_bfloat16 h = __float2bfloat16(v);
    hi = __bfloat162float(h);
    lo = v - hi;
}
// 8 consecutive floats -> bf16 hi/lo uint4s
__device__ __forceinline__ void split8(const float4& a, const float4& c, uint4& hi, uint4& lo) {
    float h0, l0, h1, l1;
    split1(a.x, h0, l0); split1(a.y, h1, l1);
    hi.x = pk_bf(h0, h1); lo.x = pk_bf(l0, l1);
    split1(a.z, h0, l0); split1(a.w, h1, l1);
    hi.y = pk_bf(h0, h1); lo.y = pk_bf(l0, l1);
    split1(c.x, h0, l0); split1(c.y, h1, l1);
    hi.z = pk_bf(h0, h1); lo.z = pk_bf(l0, l1);
    split1(c.z, h0, l0); split1(c.w, h1, l1);
    hi.w = pk_bf(h0, h1); lo.w = pk_bf(l0, l1);
}
__device__ __forceinline__ void cpa16(uint32_t s, const void* g) {
    asm volatile("cp.async.cg.shared.global [%0], [%1], 16;" :: "r"(s), "l"(g) : "memory");
}
#define CPA_COMMIT() asm volatile("cp.async.commit_group;" ::: "memory")

// ---------------------------- f32x2 (out) ----------------------------------
__device__ __forceinline__ void fma2(u64 &d, u64 a, u64 b) {
    asm("fma.rn.f32x2 %0, %1, %2, %0;" : "+l"(d) : "l"(a), "l"(b));
}
__device__ __forceinline__ u64 dup2(float a) {
    u64 r; asm("mov.b64 %0, {%1, %1};" : "=l"(r) : "f"(a)); return r;
}
__device__ __forceinline__ u64 pk2(float lo, float hi) {
    u64 r; asm("mov.b64 %0, {%1, %2};" : "=l"(r) : "f"(lo), "f"(hi)); return r;
}
__device__ __forceinline__ float2 up2(u64 v) {
    float2 r; asm("mov.b64 {%0, %1}, %2;" : "=f"(r.x), "=f"(r.y) : "l"(v)); return r;
}
__device__ __forceinline__ int swz(int d, int c) { return d * 128 + (c ^ (d & 28)); }

__device__ __forceinline__ void rank1(u64* acc, float4 a0, float4 a1,
                                      float4 b0, float4 b1)
{
    u64 bp0 = pk2(b0.x, b0.y), bp1 = pk2(b0.z, b0.w);
    u64 bp2 = pk2(b1.x, b1.y), bp3 = pk2(b1.z, b1.w);
    float av[8] = {a0.x, a0.y, a0.z, a0.w, a1.x, a1.y, a1.z, a1.w};
#pragma unroll
    for (int i = 0; i < 8; ++i) {
        u64 ad = dup2(av[i]);
        fma2(acc[i * 4 + 0], ad, bp0);
        fma2(acc[i * 4 + 1], ad, bp1);
        fma2(acc[i * 4 + 2], ad, bp2);
        fma2(acc[i * 4 + 3], ad, bp3);
    }
}

// ------------------------------ device scratch -----------------------------
__device__ __nv_bfloat16 g_qh[MM * DD], g_ql[MM * DD];   // q (pre-scaled) hi/lo
__device__ __nv_bfloat16 g_kh[MM * DD], g_kl[MM * DD];   // k hi/lo
__device__ float g_v[MM * DD];
__device__ float g_colsum[MM];
__device__ float g_vals[NPART][MM * DD];
__device__ __half g_vt_hi[BB * DD * LL];                 // v^T fp16 [b][d][k]
__device__ __half g_vt_lo[BB * DD * LL];                 // fp16 residual

// ---------------------------------------------------------------------------
// Kernel 1: qkv_mma.  q,k,v = x@W+b via 3-pass bf16 HMMA.
// grid (MM/128, 3), 256 thr.  Also zeroes g_colsum.
// ---------------------------------------------------------------------------
__global__ __launch_bounds__(256) void qkv_mma(
    const float* __restrict__ x,
    const float* __restrict__ Wq, const float* __restrict__ bq,
    const float* __restrict__ Wk, const float* __restrict__ bk,
    const float* __restrict__ Wv, const float* __restrict__ bv)
{
    extern __shared__ char smem[];
    const uint32_t sb = smem_u32(smem);
    const int t = threadIdx.x, l = t & 31, w = t >> 5;
    const int gid = (blockIdx.y * gridDim.x + blockIdx.x) * 256 + t;
    if (gid < MM) g_colsum[gid] = 0.f;

    const float* W; const float* bias; float oscale;
    __nv_bfloat16 *oh = nullptr, *ol = nullptr;
    if (blockIdx.y == 0)      { W = Wq; bias = bq; oh = g_qh; ol = g_ql; oscale = SCALE; }
    else if (blockIdx.y == 1) { W = Wk; bias = bk; oh = g_kh; ol = g_kl; oscale = 1.f; }
    else                      { W = Wv; bias = bv; oscale = 1.f; }
    const bool isv = (blockIdx.y == 2);
    const int mb = blockIdx.x * 128;

    float* stg = (float*)(smem + Q_ST);              // W fp32 stage [64][64]

    float acc[8][4];
#pragma unroll
    for (int nt = 0; nt < 8; ++nt)
#pragma unroll
        for (int j = 0; j < 4; ++j) acc[nt][j] = 0.f;

    for (int kc = 0; kc < IN; kc += 64) {
        __syncthreads();
#pragma unroll
        for (int s = 0; s < 4; ++s) {
            int u = t + 256 * s;
            int r = u >> 3, c16 = u & 7;
            const float* xp = &x[(size_t)(mb + r) * IN + kc + c16 * 8];
            float4 a = *reinterpret_cast<const float4*>(xp);
            float4 c = *reinterpret_cast<const float4*>(xp + 4);
            uint4 hi, lo;
            split8(a, c, hi, lo);
            uint32_t off = swzo(r, c16);
            *(uint4*)(smem + Q_XH + off) = hi;
            *(uint4*)(smem + Q_XL + off) = lo;
        }
#pragma unroll
        for (int s = 0; s < 4; ++s) {
            int u = t + 256 * s;
            int k = u >> 4, c4 = u & 15;
            *reinterpret_cast<float4*>(&stg[k * 64 + 4 * c4]) =
                *reinterpret_cast<const float4*>(&W[(size_t)(kc + k) * DD + 4 * c4]);
        }
        __syncthreads();
#pragma unroll
        for (int s = 0; s < 2; ++s) {
            int u = t + 256 * s;
            int k16 = u >> 6, n = u & 63;
            union { __nv_bfloat16 h[8]; uint4 u4; } hi, lo;
#pragma unroll
            for (int j = 0; j < 8; ++j) {
                float v = stg[(k16 * 8 + j) * 64 + n];
                __nv_bfloat16 hb = __float2bfloat16(v);
                hi.h[j] = hb;
                lo.h[j] = __float2bfloat16(v - __bfloat162float(hb));
            }
            uint32_t off = swzo(n, k16);
            *(uint4*)(smem + Q_WH + off) = hi.u4;
            *(uint4*)(smem + Q_WL + off) = lo.u4;
        }
        __syncthreads();
#pragma unroll
        for (int ks = 0; ks < 4; ++ks) {
            uint32_t xh[4], xl[4];
            uint32_t aoff = swzo(w * 16 + (l & 15), ks * 2 + (l >> 4));
            ldsm4(xh, sb + Q_XH + aoff);
            ldsm4(xl, sb + Q_XL + aoff);
            uint32_t wh[8][2], wl[8][2];
            uint32_t boff = swzo(((l >> 4) << 3) + (l & 7), ks * 2 + ((l >> 3) & 1));
#pragma unroll
            for (int pg = 0; pg < 4; ++pg) {
                uint32_t r4[4];
                ldsm4(r4, sb + Q_WH + boff + pg * 2048);
                wh[pg * 2][0] = r4[0]; wh[pg * 2][1] = r4[1];
                wh[pg * 2 + 1][0] = r4[2]; wh[pg * 2 + 1][1] = r4[3];
                ldsm4(r4, sb + Q_WL + boff + pg * 2048);
                wl[pg * 2][0] = r4[0]; wl[pg * 2][1] = r4[1];
                wl[pg * 2 + 1][0] = r4[2]; wl[pg * 2 + 1][1] = r4[3];
            }
#pragma unroll
            for (int nt = 0; nt < 8; ++nt) {
                mma16816(acc[nt], xh, wh[nt]);
                mma16816(acc[nt], xh, wl[nt]);
                mma16816(acc[nt], xl, wh[nt]);
            }
        }
    }
#pragma unroll
    for (int nt = 0; nt < 8; ++nt) {
        int col = nt * 8 + 2 * (l & 3);
        float b0 = bias[col], b1 = bias[col + 1];
        int r0 = mb + w * 16 + (l >> 2);
        float e0 = (acc[nt][0] + b0) * oscale;
        float e1 = (acc[nt][1] + b1) * oscale;
        float e2 = (acc[nt][2] + b0) * oscale;
        float e3 = (acc[nt][3] + b1) * oscale;
        if (isv) {
            *reinterpret_cast<float2*>(&g_v[(size_t)r0 * DD + col]) = make_float2(e0, e1);
            *reinterpret_cast<float2*>(&g_v[(size_t)(r0 + 8) * DD + col]) = make_float2(e2, e3);
        } else {
            float h0, l0_, h1, l1_, h2, l2_, h3, l3_;
            split1(e0, h0, l0_); split1(e1, h1, l1_);
            split1(e2, h2, l2_); split1(e3, h3, l3_);
            *reinterpret_cast<uint32_t*>(&oh[(size_t)r0 * DD + col]) = pk_bf(h0, h1);
            *reinterpret_cast<uint32_t*>(&ol[(size_t)r0 * DD + col]) = pk_bf(l0_, l1_);
            *reinterpret_cast<uint32_t*>(&oh[(size_t)(r0 + 8) * DD + col]) = pk_bf(h2, h3);
            *reinterpret_cast<uint32_t*>(&ol[(size_t)(r0 + 8) * DD + col]) = pk_bf(l2_, l3_);
        }
    }
}

// ---------------------------------------------------------------------------
// Kernel 1b: v[b][k][d] -> fp16 hi + fp16 residual, transposed g_vt[b][d][k].
// grid (LL/64, BB), 256 thr.
// ---------------------------------------------------------------------------
__global__ __launch_bounds__(256) void vtrans_kernel()
{
    const int b = blockIdx.y, kb = blockIdx.x * 64;
    const int t = threadIdx.x;
    __shared__ float tile[64][68];

    const int c4 = t & 15, r0 = t >> 4;
#pragma unroll
    for (int s = 0; s < 4; ++s) {
        int r = r0 + 16 * s;
        float4 v = *reinterpret_cast<const float4*>(&g_v[(size_t)(b * LL + kb + r) * DD + 4 * c4]);
        tile[r][4 * c4 + 0] = v.x; tile[r][4 * c4 + 1] = v.y;
        tile[r][4 * c4 + 2] = v.z; tile[r][4 * c4 + 3] = v.w;
    }
    __syncthreads();

    const int f8 = t & 7, d0 = t >> 3;
#pragma unroll
    for (int s = 0; s < 2; ++s) {
        int d = d0 + 32 * s;
        union { __half h[8]; uint4 u; } hi, lo;
#pragma unroll
        for (int j = 0; j < 8; ++j) {
            float v = tile[f8 * 8 + j][d];
            __half hb = __float2half_rn(v);
            hi.h[j] = hb;
            lo.h[j] = __float2half_rn(v - __half2float(hb));
        }
        size_t o = (size_t)(b * DD + d) * LL + kb + f8 * 8;
        *reinterpret_cast<uint4*>(&g_vt_hi[o]) = hi.u;
        *reinterpret_cast<uint4*>(&g_vt_lo[o]) = lo.u;
    }
}

// ---------------------------------------------------------------------------
// Kernel 2: scores_sum (2-pass).  colsum[b,k] += sum_q exp(S[q,k]).
// grid (L/128 kb, L/128 qb, B), 256 thr, 2 CTAs/SM.
// ---------------------------------------------------------------------------
__global__ __launch_bounds__(256, 2) void scores_sum(void)
{
    extern __shared__ char smem[];
    const uint32_t sb = smem_u32(smem);
    const int t = threadIdx.x, l = t & 31, w = t >> 5;
    const int wm = w & 3, wn = w >> 2;
    const int b = blockIdx.z, qb = blockIdx.y * 128, kb = blockIdx.x * 128;

    {
        const size_t qo = (size_t)(b * LL + qb) * DD;
        const size_t ko = (size_t)(b * LL + kb) * DD;
#pragma unroll
        for (int s = 0; s < 4; ++s) {
            int u = t + 256 * s;
            int r = u >> 3, c16 = u & 7;
            uint32_t off = swzo(r, c16);
            size_t gi = qo + (size_t)r * DD + c16 * 8;
            *(uint4*)(smem + S_QH + off) = *reinterpret_cast<const uint4*>(&g_qh[gi]);
            gi = ko + (size_t)r * DD + c16 * 8;
            *(uint4*)(smem + S_KH + off) = *reinterpret_cast<const uint4*>(&g_kh[gi]);
            *(uint4*)(smem + S_KL + off) = *reinterpret_cast<const uint4*>(&g_kl[gi]);
        }
    }
    __syncthreads();

    float acc[2][8][4];
#pragma unroll
    for (int mt = 0; mt < 2; ++mt)
#pragma unroll
        for (int nt = 0; nt < 8; ++nt)
#pragma unroll
            for (int j = 0; j < 4; ++j) acc[mt][nt][j] = 0.f;

#pragma unroll
    for (int ks = 0; ks < 4; ++ks) {
        uint32_t qh[2][4];
        {
            uint32_t aoff = swzo(wm * 32 + (l & 15), ks * 2 + (l >> 4));
            ldsm4(qh[0], sb + S_QH + aoff);
            ldsm4(qh[1], sb + S_QH + aoff + 2048);
        }
        uint32_t kh[8][2], kl[8][2];
        {
            uint32_t boff = swzo(wn * 64 + ((l >> 4) << 3) + (l & 7),
                                 ks * 2 + ((l >> 3) & 1));
#pragma unroll
            for (int pg = 0; pg < 4; ++pg) {
                uint32_t r4[4];
                ldsm4(r4, sb + S_KH + boff + pg * 2048);
                kh[pg * 2][0] = r4[0]; kh[pg * 2][1] = r4[1];
                kh[pg * 2 + 1][0] = r4[2]; kh[pg * 2 + 1][1] = r4[3];
                ldsm4(r4, sb + S_KL + boff + pg * 2048);
                kl[pg * 2][0] = r4[0]; kl[pg * 2][1] = r4[1];
                kl[pg * 2 + 1][0] = r4[2]; kl[pg * 2 + 1][1] = r4[3];
            }
        }
#pragma unroll
        for (int mt = 0; mt < 2; ++mt)
#pragma unroll
            for (int nt = 0; nt < 8; ++nt) {
                mma16816(acc[mt][nt], qh[mt], kh[nt]);
                mma16816(acc[mt][nt], qh[mt], kl[nt]);
            }
    }

    float* colred = (float*)(smem + S_RED);
#pragma unroll
    for (int nt = 0; nt < 8; ++nt) {
        float cs0 = 0.f, cs1 = 0.f;
#pragma unroll
        for (int mt = 0; mt < 2; ++mt) {
            cs0 += __expf(acc[mt][nt][0]) + __expf(acc[mt][nt][2]);
            cs1 += __expf(acc[mt][nt][1]) + __expf(acc[mt][nt][3]);
        }
#pragma unroll
        for (int m = 4; m < 32; m <<= 1) {
            cs0 += __shfl_xor_sync(0xffffffffu, cs0, m);
            cs1 += __shfl_xor_sync(0xffffffffu, cs1, m);
        }
        if (l < 4) {
            colred[wm * 128 + wn * 64 + nt * 8 + 2 * l + 0] = cs0;
            colred[wm * 128 + wn * 64 + nt * 8 + 2 * l + 1] = cs1;
        }
    }
    __syncthreads();
    if (t < 128) {
        float s = colred[t] + colred[128 + t] + colred[256 + t] + colred[384 + t];
        atomicAdd(&g_colsum[b * LL + kb + t], s);
    }
}

// ---------------------------------------------------------------------------
// Kernel 3: av_fused.  S 3-pass bf16; P fp16 single-pass; O 2-pass vs fp16 V.
// 16 q-rows/warp, 64-col chunks, 2 CTAs/SM, cp.async double buffering.
// grid (L/128, KSPLIT, B), 256 thr.
// ---------------------------------------------------------------------------
__global__ __launch_bounds__(256, 2) void av_fused(float* __restrict__ attn)
{
    extern __shared__ char smem[];
    const uint32_t sb = smem_u32(smem);
    const int t = threadIdx.x, l = t & 31, w = t >> 5;
    const int b = blockIdx.z, split = blockIdx.y, qb = blockIdx.x * 128;
    const int kBeg = split * (LL / KSPLIT);
    constexpr int NCH = (LL / KSPLIT) / 64;          // 16 chunks

    float* invb = (float*)(smem + F_INV);            // [2][64]
    const float* cs = g_colsum + b * LL;
    float* ap = attn + (size_t)(b * LL + qb) * LL;

    // q tiles once (128 rows x 64 d, hi/lo)
    {
        const size_t qo = (size_t)(b * LL + qb) * DD;
#pragma unroll
        for (int s = 0; s < 4; ++s) {
            int u = t + 256 * s;
            int r = u >> 3, c16 = u & 7;
            uint32_t off = swzo(r, c16);
            size_t gi = qo + (size_t)r * DD + c16 * 8;
            *(uint4*)(smem + F_QH + off) = *reinterpret_cast<const uint4*>(&g_qh[gi]);
            *(uint4*)(smem + F_QL + off) = *reinterpret_cast<const uint4*>(&g_ql[gi]);
        }
    }
    if (t < 64) invb[t] = 1.f / cs[kBeg + t];

    auto issue = [&](int ci) {
        const int kc = kBeg + ci * 64;
        const uint32_t base = sb + F_KV + (uint32_t)(ci & 1) * 32768;
        const size_t ko = (size_t)(b * LL + kc) * DD;
#pragma unroll
        for (int s = 0; s < 2; ++s) {
            int u = t + 256 * s;
            int r = u >> 3, c16 = u & 7;
            uint32_t off = swzo(r, c16);
            size_t gk = ko + (size_t)r * DD + c16 * 8;
            cpa16(base + off,         &g_kh[gk]);
            cpa16(base + 8192 + off,  &g_kl[gk]);
            size_t gv = (size_t)(b * DD + r) * LL + kc + c16 * 8;
            cpa16(base + 16384 + off, &g_vt_hi[gv]);
            cpa16(base + 24576 + off, &g_vt_lo[gv]);
        }
        CPA_COMMIT();
    };
    issue(0);

    float o[8][4];
#pragma unroll
    for (int nt = 0; nt < 8; ++nt)
#pragma unroll
        for (int j = 0; j < 4; ++j) o[nt][j] = 0.f;

    for (int ci = 0; ci < NCH; ++ci) {
        const int kc = kBeg + ci * 64;
        if (ci + 1 < NCH) {
            issue(ci + 1);
            asm volatile("cp.async.wait_group 1;" ::: "memory");
        } else {
            asm volatile("cp.async.wait_group 0;" ::: "memory");
        }
        __syncthreads();

        if (ci + 1 < NCH && t < 64)
            invb[((ci + 1) & 1) * 64 + t] = 1.f / cs[kc + 64 + t];

        const uint32_t kb_hi = sb + F_KV + (uint32_t)(ci & 1) * 32768;
        const uint32_t kb_lo = kb_hi + 8192;
        const uint32_t vb_hi = kb_hi + 16384;
        const uint32_t vb_lo = kb_hi + 24576;
        const float* inv_s = invb + (ci & 1) * 64;

        // ---- S = q k^T (3-pass bf16) ----
        float acc[8][4];
#pragma unroll
        for (int nt = 0; nt < 8; ++nt)
#pragma unroll
            for (int j = 0; j < 4; ++j) acc[nt][j] = 0.f;

#pragma unroll
        for (int ks = 0; ks < 4; ++ks) {
            uint32_t qh[4], ql[4];
            {
                uint32_t aoff = swzo(w * 16 + (l & 15), ks * 2 + (l >> 4));
                ldsm4(qh, sb + F_QH + aoff);
                ldsm4(ql, sb + F_QL + aoff);
            }
            uint32_t kh[8][2], kl[8][2];
            {
                uint32_t boff = swzo(((l >> 4) << 3) + (l & 7),
                                     ks * 2 + ((l >> 3) & 1));
#pragma unroll
                for (int pg = 0; pg < 4; ++pg) {
                    uint32_t r4[4];
                    ldsm4(r4, kb_hi + boff + pg * 2048);
                    kh[pg * 2][0] = r4[0]; kh[pg * 2][1] = r4[1];
                    kh[pg * 2 + 1][0] = r4[2]; kh[pg * 2 + 1][1] = r4[3];
                    ldsm4(r4, kb_lo + boff + pg * 2048);
                    kl[pg * 2][0] = r4[0]; kl[pg * 2][1] = r4[1];
                    kl[pg * 2 + 1][0] = r4[2]; kl[pg * 2 + 1][1] = r4[3];
                }
            }
#pragma unroll
            for (int nt = 0; nt < 8; ++nt) {
                mma16816(acc[nt], qh, kh[nt]);
                mma16816(acc[nt], qh, kl[nt]);
                mma16816(acc[nt], ql, kh[nt]);
            }
        }

        // ---- P = exp(S)*inv ; store A fp32 ; pack P as fp16 A-fragments ----
        uint32_t ph[4][4];
#pragma unroll
        for (int nt = 0; nt < 8; ++nt) {
            int lc = nt * 8 + 2 * (l & 3);
            float i0 = inv_s[lc], i1 = inv_s[lc + 1];
            float e0 = __expf(acc[nt][0]) * i0;
            float e1 = __expf(acc[nt][1]) * i1;
            float e2 = __expf(acc[nt][2]) * i0;
            float e3 = __expf(acc[nt][3]) * i1;
            int r0 = w * 16 + (l >> 2);
            *reinterpret_cast<float2*>(&ap[(size_t)r0 * LL + kc + lc]) = make_float2(e0, e1);
            *reinterpret_cast<float2*>(&ap[(size_t)(r0 + 8) * LL + kc + lc]) = make_float2(e2, e3);
            int kb2 = nt >> 1, base = (nt & 1) * 2;
            ph[kb2][base + 0] = pk_f16(e0, e1);
            ph[kb2][base + 1] = pk_f16(e2, e3);
        }

        // ---- O += P @ V (2-pass fp16: vh + vl residual) ----
#pragma unroll
        for (int kb2 = 0; kb2 < 4; ++kb2) {
            uint32_t vh[8][2], vl[8][2];
            {
                uint32_t boff = swzo(((l >> 4) << 3) + (l & 7),
                                     kb2 * 2 + ((l >> 3) & 1));
#pragma unroll
                for (int pg = 0; pg < 4; ++pg) {
                    uint32_t r4[4];
                    ldsm4(r4, vb_hi + boff + pg * 2048);
                    vh[pg * 2][0] = r4[0]; vh[pg * 2][1] = r4[1];
                    vh[pg * 2 + 1][0] = r4[2]; vh[pg * 2 + 1][1] = r4[3];
                    ldsm4(r4, vb_lo + boff + pg * 2048);
                    vl[pg * 2][0] = r4[0]; vl[pg * 2][1] = r4[1];
                    vl[pg * 2 + 1][0] = r4[2]; vl[pg * 2 + 1][1] = r4[3];
                }
            }
#pragma unroll
            for (int nt = 0; nt < 8; ++nt) {
                mma16816h(o[nt], ph[kb2], vh[nt]);
                mma16816h(o[nt], ph[kb2], vl[nt]);
            }
        }
        __syncthreads();
    }

    float* gv = g_vals[split];
#pragma unroll
    for (int nt = 0; nt < 8; ++nt) {
        int col = nt * 8 + 2 * (l & 3);
        size_t row = (size_t)(b * LL + qb + w * 16 + (l >> 2));
        *reinterpret_cast<float2*>(&gv[row * DD + col]) =
            make_float2(o[nt][0], o[nt][1]);
        *reinterpret_cast<float2*>(&gv[(row + 8) * DD + col]) =
            make_float2(o[nt][2], o[nt][3]);
    }
}

// ---------------------------------------------------------------------------
// Kernel 4: out = (sum_p g_vals[p]) @ Wo + bo. grid (MM/128, OUT/128), 256 thr.
// ---------------------------------------------------------------------------
__global__ __launch_bounds__(256) void out_kernel(
    const float* __restrict__ Wo, const float* __restrict__ bo,
    float* __restrict__ outp)
{
    const int mb = blockIdx.x * 128;
    const int nb = blockIdx.y * 128;
    const int t  = threadIdx.x;
    const int tx = t & 15, ty = t >> 4;

    __shared__ float vt[64 * 128];
    __shared__ float ws[64 * 128];

    {
        const int dq = t & 15, rb = t >> 4;
#pragma unroll
        for (int s = 0; s < 8; ++s) {
            int r = rb + s * 16;
            size_t base = (size_t)(mb + r) * DD + 4 * dq;
            float4 v = *reinterpret_cast<const float4*>(&g_vals[0][base]);
#pragma unroll
            for (int p = 1; p < NPART; ++p) {
                float4 u = *reinterpret_cast<const float4*>(&g_vals[p][base]);
                v.x += u.x; v.y += u.y; v.z += u.z; v.w += u.w;
            }
            vt[swz(4 * dq + 0, r)] = v.x; vt[swz(4 * dq + 1, r)] = v.y;
            vt[swz(4 * dq + 2, r)] = v.z; vt[swz(4 * dq + 3, r)] = v.w;
        }
        const int nq = t & 31, kb2 = t >> 5;
#pragma unroll
        for (int s = 0; s < 8; ++s) {
            int kr = kb2 + s * 8;
            *reinterpret_cast<float4*>(&ws[kr * 128 + 4 * nq]) =
                *reinterpret_cast<const float4*>(&Wo[(size_t)kr * OUT + nb + 4 * nq]);
        }
    }
    __syncthreads();

    u64 acc[32];
#pragma unroll
    for (int i = 0; i < 32; ++i) acc[i] = 0ull;

#pragma unroll 8
    for (int k = 0; k < 64; ++k) {
        float4 a0 = *reinterpret_cast<const float4*>(&vt[swz(k, 4 * ty)]);
        float4 a1 = *reinterpret_cast<const float4*>(&vt[swz(k, 64 + 4 * ty)]);
        float4 b0 = *reinterpret_cast<const float4*>(&ws[k * 128 + 4 * tx]);
        float4 b1 = *reinterpret_cast<const float4*>(&ws[k * 128 + 64 + 4 * tx]);
        rank1(acc, a0, a1, b0, b1);
    }

    float4 bo0 = *reinterpret_cast<const float4*>(&bo[nb + 4 * tx]);
    float4 bo1 = *reinterpret_cast<const float4*>(&bo[nb + 64 + 4 * tx]);
#pragma unroll
    for (int i = 0; i < 8; ++i) {
        int r = (i < 4) ? (4 * ty + i) : (64 + 4 * ty + (i - 4));
        float2 p0 = up2(acc[i * 4 + 0]), p1 = up2(acc[i * 4 + 1]);
        float2 p2 = up2(acc[i * 4 + 2]), p3 = up2(acc[i * 4 + 3]);
        float4 o0 = make_float4(p0.x + bo0.x, p0.y + bo0.y, p1.x + bo0.z, p1.y + bo0.w);
        float4 o1 = make_float4(p2.x + bo1.x, p2.y + bo1.y, p3.x + bo1.z, p3.y + bo1.w);
        *reinterpret_cast<float4*>(&outp[(size_t)(mb + r) * OUT + nb + 4 * tx]) = o0;
        *reinterpret_cast<float4*>(&outp[(size_t)(mb + r) * OUT + nb + 64 + 4 * tx]) = o1;
    }
}

// ---------------------------------------------------------------------------
extern "C" void kernel_launch(void* const* d_in, const int* in_sizes, int n_in,
                              void* d_out, int out_size)
{
    const float* x  = (const float*)d_in[0];
    const float* Wq = (const float*)d_in[1];
    const float* bq = (const float*)d_in[2];
    const float* Wk = (const float*)d_in[3];
    const float* bk = (const float*)d_in[4];
    const float* Wv = (const float*)d_in[5];
    const float* bv = (const float*)d_in[6];
    const float* Wo = (const float*)d_in[7];
    const float* bo = (const float*)d_in[8];

    float* outp = (float*)d_out;                   // [B, L, OUT]
    float* attn = outp + (size_t)BB * LL * OUT;    // [B, L, L]

    cudaFuncSetAttribute(qkv_mma,    cudaFuncAttributeMaxDynamicSharedMemorySize, Q_SMEM);
    cudaFuncSetAttribute(scores_sum, cudaFuncAttributeMaxDynamicSharedMemorySize, S_SMEM);
    cudaFuncSetAttribute(av_fused,   cudaFuncAttributeMaxDynamicSharedMemorySize, F_SMEM);

    qkv_mma<<<dim3(MM / 128, 3), 256, Q_SMEM>>>(x, Wq, bq, Wk, bk, Wv, bv);
    vtrans_kernel<<<dim3(LL / 64, BB), 256>>>();
    scores_sum<<<dim3(LL / 128, LL / 128, BB), 256, S_SMEM>>>();
    av_fused<<<dim3(LL / 128, KSPLIT, BB), 256, F_SMEM>>>(attn);
    out_kernel<<<dim3(MM / 128, OUT / 128), 256>>>(Wo, bo, outp);
}

// round 14
// speedup vs baseline: 3.8850x; 1.0778x over previous
#include <cuda_runtime.h>
#include <cuda_bf16.h>
#include <cuda_fp16.h>
#include <cstdint>

// ---------------------------------------------------------------------------
// AttentionBlock, Round 12: 1-pass fp16 colsum + single-pass fp16 V.
//  k1  qkv_mma   : q,k,v = x@W+b via bf16 hi/lo 3-pass HMMA; q pre-scaled;
//                  q,k stored bf16 hi/lo AND plain fp16; v fp32.
//  k1b vtrans    : v -> v^T fp16 (single).
//  k2  scores_sum: colsum[b,k] = sum_q exp(S), 1-pass fp16 HMMA.
//  k3  av_fused  : recompute S 3-pass bf16, P=exp(S)*inv (fp32 store to attn,
//                  fp16 pack), O += P@V single-pass fp16.
//  k4  out       : out = (sum partials) @ Wo + bo (f32x2).
// B=4, L=4096, IN=512, D=64, OUT=512.  Outputs: (out, attention).
// ---------------------------------------------------------------------------

namespace {
constexpr int BB  = 4;
constexpr int LL  = 4096;
constexpr int IN  = 512;
constexpr int DD  = 64;
constexpr int OUT = 512;
constexpr int MM  = BB * LL;
constexpr int KSPLIT = 4;
constexpr int NPART = KSPLIT;
constexpr float SCALE = 0.125f;

// qkv_mma smem
constexpr uint32_t Q_XH = 0, Q_XL = 16384, Q_WH = 32768, Q_WL = 40960,
                   Q_ST = 49152, Q_SMEM = 49152 + 16384;   // 65536
// scores_sum smem (fp16 single tiles)
constexpr uint32_t S_QF = 0, S_KF = 16384, S_RED = 32768,
                   S_SMEM = 32768 + 2048;
// av_fused smem: Q hi/lo (32K), 2 stages x (KH 8K + KL 8K + VH 8K) = 48K, inv.
constexpr uint32_t F_QH = 0, F_QL = 16384, F_KV = 32768;
constexpr uint32_t F_STAGE = 24576;
constexpr uint32_t F_INV = F_KV + 2 * F_STAGE;             // 81920
constexpr uint32_t F_SMEM = F_INV + 512;                   // 82432
}

typedef unsigned long long u64;

// ------------------------------- helpers -----------------------------------
__device__ __forceinline__ uint32_t smem_u32(const void* p) {
    uint32_t a;
    asm("{ .reg .u64 t; cvta.to.shared.u64 t, %1; cvt.u32.u64 %0, t; }" : "=r"(a) : "l"(p));
    return a;
}
// swizzled byte offset in a [rows][64 x 16-bit] tile (128B rows, 16B units)
__device__ __forceinline__ uint32_t swzo(int r, int c16) {
    return (uint32_t)(r * 128 + ((c16 ^ (r & 7)) << 4));
}
__device__ __forceinline__ void ldsm4(uint32_t r[4], uint32_t addr) {
    asm volatile("ldmatrix.sync.aligned.m8n8.x4.shared.b16 {%0,%1,%2,%3}, [%4];"
        : "=r"(r[0]), "=r"(r[1]), "=r"(r[2]), "=r"(r[3]) : "r"(addr));
}
__device__ __forceinline__ void mma16816(float c[4], const uint32_t a[4], const uint32_t b[2]) {
    asm volatile("mma.sync.aligned.m16n8k16.row.col.f32.bf16.bf16.f32 "
        "{%0,%1,%2,%3}, {%4,%5,%6,%7}, {%8,%9}, {%0,%1,%2,%3};"
        : "+f"(c[0]), "+f"(c[1]), "+f"(c[2]), "+f"(c[3])
        : "r"(a[0]), "r"(a[1]), "r"(a[2]), "r"(a[3]), "r"(b[0]), "r"(b[1]));
}
__device__ __forceinline__ void mma16816h(float c[4], const uint32_t a[4], const uint32_t b[2]) {
    asm volatile("mma.sync.aligned.m16n8k16.row.col.f32.f16.f16.f32 "
        "{%0,%1,%2,%3}, {%4,%5,%6,%7}, {%8,%9}, {%0,%1,%2,%3};"
        : "+f"(c[0]), "+f"(c[1]), "+f"(c[2]), "+f"(c[3])
        : "r"(a[0]), "r"(a[1]), "r"(a[2]), "r"(a[3]), "r"(b[0]), "r"(b[1]));
}
__device__ __forceinline__ uint32_t pk_bf(float a, float b) {
    return (uint32_t)__bfloat16_as_ushort(__float2bfloat16(a)) |
           ((uint32_t)__bfloat16_as_ushort(__float2bfloat16(b)) << 16);
}
// packed fp16x2: lo = a, hi = b (single cvt instruction)
__device__ __forceinline__ uint32_t pk_f16(float a, float b) {
    uint32_t r;
    asm("cvt.rn.f16x2.f32 %0, %1, %2;" : "=r"(r) : "f"(b), "f"(a));
    return r;
}
__device__ __forceinline__ void split1(float v, float& hi, float& lo) {
    __nv_bfloat16 h = __float2bfloat16(v);
    hi = __bfloat162float(h);
    lo = v - hi;
}
// 8 consecutive floats -> bf16 hi/lo uint4s
__device__ __forceinline__ void split8(const float4& a, const float4& c, uint4& hi, uint4& lo) {
    float h0, l0, h1, l1;
    split1(a.x, h0, l0); split1(a.y, h1, l1);
    hi.x = pk_bf(h0, h1); lo.x = pk_bf(l0, l1);
    split1(a.z, h0, l0); split1(a.w, h1, l1);
    hi.y = pk_bf(h0, h1); lo.y = pk_bf(l0, l1);
    split1(c.x, h0, l0); split1(c.y, h1, l1);
    hi.z = pk_bf(h0, h1); lo.z = pk_bf(l0, l1);
    split1(c.z, h0, l0); split1(c.w, h1, l1);
    hi.w = pk_bf(h0, h1); lo.w = pk_bf(l0, l1);
}
__device__ __forceinline__ void cpa16(uint32_t s, const void* g) {
    asm volatile("cp.async.cg.shared.global [%0], [%1], 16;" :: "r"(s), "l"(g) : "memory");
}
#define CPA_COMMIT() asm volatile("cp.async.commit_group;" ::: "memory")

// ---------------------------- f32x2 (out) ----------------------------------
__device__ __forceinline__ void fma2(u64 &d, u64 a, u64 b) {
    asm("fma.rn.f32x2 %0, %1, %2, %0;" : "+l"(d) : "l"(a), "l"(b));
}
__device__ __forceinline__ u64 dup2(float a) {
    u64 r; asm("mov.b64 %0, {%1, %1};" : "=l"(r) : "f"(a)); return r;
}
__device__ __forceinline__ u64 pk2(float lo, float hi) {
    u64 r; asm("mov.b64 %0, {%1, %2};" : "=l"(r) : "f"(lo), "f"(hi)); return r;
}
__device__ __forceinline__ float2 up2(u64 v) {
    float2 r; asm("mov.b64 {%0, %1}, %2;" : "=f"(r.x), "=f"(r.y) : "l"(v)); return r;
}
__device__ __forceinline__ int swz(int d, int c) { return d * 128 + (c ^ (d & 28)); }

__device__ __forceinline__ void rank1(u64* acc, float4 a0, float4 a1,
                                      float4 b0, float4 b1)
{
    u64 bp0 = pk2(b0.x, b0.y), bp1 = pk2(b0.z, b0.w);
    u64 bp2 = pk2(b1.x, b1.y), bp3 = pk2(b1.z, b1.w);
    float av[8] = {a0.x, a0.y, a0.z, a0.w, a1.x, a1.y, a1.z, a1.w};
#pragma unroll
    for (int i = 0; i < 8; ++i) {
        u64 ad = dup2(av[i]);
        fma2(acc[i * 4 + 0], ad, bp0);
        fma2(acc[i * 4 + 1], ad, bp1);
        fma2(acc[i * 4 + 2], ad, bp2);
        fma2(acc[i * 4 + 3], ad, bp3);
    }
}

// ------------------------------ device scratch -----------------------------
__device__ __nv_bfloat16 g_qh[MM * DD], g_ql[MM * DD];   // q (pre-scaled) hi/lo
__device__ __nv_bfloat16 g_kh[MM * DD], g_kl[MM * DD];   // k hi/lo
__device__ __half g_qf[MM * DD], g_kf[MM * DD];          // q,k plain fp16
__device__ float g_v[MM * DD];
__device__ float g_colsum[MM];
__device__ float g_vals[NPART][MM * DD];
__device__ __half g_vt[BB * DD * LL];                    // v^T fp16 [b][d][k]

// ---------------------------------------------------------------------------
// Kernel 1: qkv_mma.  q,k,v = x@W+b via 3-pass bf16 HMMA.
// grid (MM/128, 3), 256 thr.  Also zeroes g_colsum.
// ---------------------------------------------------------------------------
__global__ __launch_bounds__(256) void qkv_mma(
    const float* __restrict__ x,
    const float* __restrict__ Wq, const float* __restrict__ bq,
    const float* __restrict__ Wk, const float* __restrict__ bk,
    const float* __restrict__ Wv, const float* __restrict__ bv)
{
    extern __shared__ char smem[];
    const uint32_t sb = smem_u32(smem);
    const int t = threadIdx.x, l = t & 31, w = t >> 5;
    const int gid = (blockIdx.y * gridDim.x + blockIdx.x) * 256 + t;
    if (gid < MM) g_colsum[gid] = 0.f;

    const float* W; const float* bias; float oscale;
    __nv_bfloat16 *oh = nullptr, *ol = nullptr;
    __half* of = nullptr;
    if (blockIdx.y == 0)      { W = Wq; bias = bq; oh = g_qh; ol = g_ql; of = g_qf; oscale = SCALE; }
    else if (blockIdx.y == 1) { W = Wk; bias = bk; oh = g_kh; ol = g_kl; of = g_kf; oscale = 1.f; }
    else                      { W = Wv; bias = bv; oscale = 1.f; }
    const bool isv = (blockIdx.y == 2);
    const int mb = blockIdx.x * 128;

    float* stg = (float*)(smem + Q_ST);              // W fp32 stage [64][64]

    float acc[8][4];
#pragma unroll
    for (int nt = 0; nt < 8; ++nt)
#pragma unroll
        for (int j = 0; j < 4; ++j) acc[nt][j] = 0.f;

    for (int kc = 0; kc < IN; kc += 64) {
        __syncthreads();
#pragma unroll
        for (int s = 0; s < 4; ++s) {
            int u = t + 256 * s;
            int r = u >> 3, c16 = u & 7;
            const float* xp = &x[(size_t)(mb + r) * IN + kc + c16 * 8];
            float4 a = *reinterpret_cast<const float4*>(xp);
            float4 c = *reinterpret_cast<const float4*>(xp + 4);
            uint4 hi, lo;
            split8(a, c, hi, lo);
            uint32_t off = swzo(r, c16);
            *(uint4*)(smem + Q_XH + off) = hi;
            *(uint4*)(smem + Q_XL + off) = lo;
        }
#pragma unroll
        for (int s = 0; s < 4; ++s) {
            int u = t + 256 * s;
            int k = u >> 4, c4 = u & 15;
            *reinterpret_cast<float4*>(&stg[k * 64 + 4 * c4]) =
                *reinterpret_cast<const float4*>(&W[(size_t)(kc + k) * DD + 4 * c4]);
        }
        __syncthreads();
#pragma unroll
        for (int s = 0; s < 2; ++s) {
            int u = t + 256 * s;
            int k16 = u >> 6, n = u & 63;
            union { __nv_bfloat16 h[8]; uint4 u4; } hi, lo;
#pragma unroll
            for (int j = 0; j < 8; ++j) {
                float v = stg[(k16 * 8 + j) * 64 + n];
                __nv_bfloat16 hb = __float2bfloat16(v);
                hi.h[j] = hb;
                lo.h[j] = __float2bfloat16(v - __bfloat162float(hb));
            }
            uint32_t off = swzo(n, k16);
            *(uint4*)(smem + Q_WH + off) = hi.u4;
            *(uint4*)(smem + Q_WL + off) = lo.u4;
        }
        __syncthreads();
#pragma unroll
        for (int ks = 0; ks < 4; ++ks) {
            uint32_t xh[4], xl[4];
            uint32_t aoff = swzo(w * 16 + (l & 15), ks * 2 + (l >> 4));
            ldsm4(xh, sb + Q_XH + aoff);
            ldsm4(xl, sb + Q_XL + aoff);
            uint32_t wh[8][2], wl[8][2];
            uint32_t boff = swzo(((l >> 4) << 3) + (l & 7), ks * 2 + ((l >> 3) & 1));
#pragma unroll
            for (int pg = 0; pg < 4; ++pg) {
                uint32_t r4[4];
                ldsm4(r4, sb + Q_WH + boff + pg * 2048);
                wh[pg * 2][0] = r4[0]; wh[pg * 2][1] = r4[1];
                wh[pg * 2 + 1][0] = r4[2]; wh[pg * 2 + 1][1] = r4[3];
                ldsm4(r4, sb + Q_WL + boff + pg * 2048);
                wl[pg * 2][0] = r4[0]; wl[pg * 2][1] = r4[1];
                wl[pg * 2 + 1][0] = r4[2]; wl[pg * 2 + 1][1] = r4[3];
            }
#pragma unroll
            for (int nt = 0; nt < 8; ++nt) {
                mma16816(acc[nt], xh, wh[nt]);
                mma16816(acc[nt], xh, wl[nt]);
                mma16816(acc[nt], xl, wh[nt]);
            }
        }
    }
#pragma unroll
    for (int nt = 0; nt < 8; ++nt) {
        int col = nt * 8 + 2 * (l & 3);
        float b0 = bias[col], b1 = bias[col + 1];
        int r0 = mb + w * 16 + (l >> 2);
        float e0 = (acc[nt][0] + b0) * oscale;
        float e1 = (acc[nt][1] + b1) * oscale;
        float e2 = (acc[nt][2] + b0) * oscale;
        float e3 = (acc[nt][3] + b1) * oscale;
        if (isv) {
            *reinterpret_cast<float2*>(&g_v[(size_t)r0 * DD + col]) = make_float2(e0, e1);
            *reinterpret_cast<float2*>(&g_v[(size_t)(r0 + 8) * DD + col]) = make_float2(e2, e3);
        } else {
            float h0, l0_, h1, l1_, h2, l2_, h3, l3_;
            split1(e0, h0, l0_); split1(e1, h1, l1_);
            split1(e2, h2, l2_); split1(e3, h3, l3_);
            *reinterpret_cast<uint32_t*>(&oh[(size_t)r0 * DD + col]) = pk_bf(h0, h1);
            *reinterpret_cast<uint32_t*>(&ol[(size_t)r0 * DD + col]) = pk_bf(l0_, l1_);
            *reinterpret_cast<uint32_t*>(&oh[(size_t)(r0 + 8) * DD + col]) = pk_bf(h2, h3);
            *reinterpret_cast<uint32_t*>(&ol[(size_t)(r0 + 8) * DD + col]) = pk_bf(l2_, l3_);
            *reinterpret_cast<uint32_t*>(&of[(size_t)r0 * DD + col]) = pk_f16(e0, e1);
            *reinterpret_cast<uint32_t*>(&of[(size_t)(r0 + 8) * DD + col]) = pk_f16(e2, e3);
        }
    }
}

// ---------------------------------------------------------------------------
// Kernel 1b: v[b][k][d] -> fp16 transposed g_vt[b][d][k].
// grid (LL/64, BB), 256 thr.
// ---------------------------------------------------------------------------
__global__ __launch_bounds__(256) void vtrans_kernel()
{
    const int b = blockIdx.y, kb = blockIdx.x * 64;
    const int t = threadIdx.x;
    __shared__ float tile[64][68];

    const int c4 = t & 15, r0 = t >> 4;
#pragma unroll
    for (int s = 0; s < 4; ++s) {
        int r = r0 + 16 * s;
        float4 v = *reinterpret_cast<const float4*>(&g_v[(size_t)(b * LL + kb + r) * DD + 4 * c4]);
        tile[r][4 * c4 + 0] = v.x; tile[r][4 * c4 + 1] = v.y;
        tile[r][4 * c4 + 2] = v.z; tile[r][4 * c4 + 3] = v.w;
    }
    __syncthreads();

    const int f8 = t & 7, d0 = t >> 3;
#pragma unroll
    for (int s = 0; s < 2; ++s) {
        int d = d0 + 32 * s;
        union { __half h[8]; uint4 u; } hi;
#pragma unroll
        for (int j = 0; j < 8; ++j)
            hi.h[j] = __float2half_rn(tile[f8 * 8 + j][d]);
        size_t o = (size_t)(b * DD + d) * LL + kb + f8 * 8;
        *reinterpret_cast<uint4*>(&g_vt[o]) = hi.u;
    }
}

// ---------------------------------------------------------------------------
// Kernel 2: scores_sum (1-pass fp16).  colsum[b,k] += sum_q exp(S[q,k]).
// Per-element dS ~5e-4 averages out over 4096-row column sums.
// grid (L/128 kb, L/128 qb, B), 256 thr, 2 CTAs/SM.
// ---------------------------------------------------------------------------
__global__ __launch_bounds__(256, 2) void scores_sum(void)
{
    extern __shared__ char smem[];
    const uint32_t sb = smem_u32(smem);
    const int t = threadIdx.x, l = t & 31, w = t >> 5;
    const int wm = w & 3, wn = w >> 2;
    const int b = blockIdx.z, qb = blockIdx.y * 128, kb = blockIdx.x * 128;

    {
        const size_t qo = (size_t)(b * LL + qb) * DD;
        const size_t ko = (size_t)(b * LL + kb) * DD;
#pragma unroll
        for (int s = 0; s < 4; ++s) {
            int u = t + 256 * s;
            int r = u >> 3, c16 = u & 7;
            uint32_t off = swzo(r, c16);
            size_t gi = qo + (size_t)r * DD + c16 * 8;
            *(uint4*)(smem + S_QF + off) = *reinterpret_cast<const uint4*>(&g_qf[gi]);
            gi = ko + (size_t)r * DD + c16 * 8;
            *(uint4*)(smem + S_KF + off) = *reinterpret_cast<const uint4*>(&g_kf[gi]);
        }
    }
    __syncthreads();

    float acc[2][8][4];
#pragma unroll
    for (int mt = 0; mt < 2; ++mt)
#pragma unroll
        for (int nt = 0; nt < 8; ++nt)
#pragma unroll
            for (int j = 0; j < 4; ++j) acc[mt][nt][j] = 0.f;

#pragma unroll
    for (int ks = 0; ks < 4; ++ks) {
        uint32_t qf[2][4];
        {
            uint32_t aoff = swzo(wm * 32 + (l & 15), ks * 2 + (l >> 4));
            ldsm4(qf[0], sb + S_QF + aoff);
            ldsm4(qf[1], sb + S_QF + aoff + 2048);
        }
        uint32_t kf[8][2];
        {
            uint32_t boff = swzo(wn * 64 + ((l >> 4) << 3) + (l & 7),
                                 ks * 2 + ((l >> 3) & 1));
#pragma unroll
            for (int pg = 0; pg < 4; ++pg) {
                uint32_t r4[4];
                ldsm4(r4, sb + S_KF + boff + pg * 2048);
                kf[pg * 2][0] = r4[0]; kf[pg * 2][1] = r4[1];
                kf[pg * 2 + 1][0] = r4[2]; kf[pg * 2 + 1][1] = r4[3];
            }
        }
#pragma unroll
        for (int mt = 0; mt < 2; ++mt)
#pragma unroll
            for (int nt = 0; nt < 8; ++nt)
                mma16816h(acc[mt][nt], qf[mt], kf[nt]);
    }

    float* colred = (float*)(smem + S_RED);
#pragma unroll
    for (int nt = 0; nt < 8; ++nt) {
        float cs0 = 0.f, cs1 = 0.f;
#pragma unroll
        for (int mt = 0; mt < 2; ++mt) {
            cs0 += __expf(acc[mt][nt][0]) + __expf(acc[mt][nt][2]);
            cs1 += __expf(acc[mt][nt][1]) + __expf(acc[mt][nt][3]);
        }
#pragma unroll
        for (int m = 4; m < 32; m <<= 1) {
            cs0 += __shfl_xor_sync(0xffffffffu, cs0, m);
            cs1 += __shfl_xor_sync(0xffffffffu, cs1, m);
        }
        if (l < 4) {
            colred[wm * 128 + wn * 64 + nt * 8 + 2 * l + 0] = cs0;
            colred[wm * 128 + wn * 64 + nt * 8 + 2 * l + 1] = cs1;
        }
    }
    __syncthreads();
    if (t < 128) {
        float s = colred[t] + colred[128 + t] + colred[256 + t] + colred[384 + t];
        atomicAdd(&g_colsum[b * LL + kb + t], s);
    }
}

// ---------------------------------------------------------------------------
// Kernel 3: av_fused.  S 3-pass bf16; P fp16; O single-pass fp16 V.
// 16 q-rows/warp, 64-col chunks, 2 CTAs/SM, cp.async double buffering.
// grid (L/128, KSPLIT, B), 256 thr.
// ---------------------------------------------------------------------------
__global__ __launch_bounds__(256, 2) void av_fused(float* __restrict__ attn)
{
    extern __shared__ char smem[];
    const uint32_t sb = smem_u32(smem);
    const int t = threadIdx.x, l = t & 31, w = t >> 5;
    const int b = blockIdx.z, split = blockIdx.y, qb = blockIdx.x * 128;
    const int kBeg = split * (LL / KSPLIT);
    constexpr int NCH = (LL / KSPLIT) / 64;          // 16 chunks

    float* invb = (float*)(smem + F_INV);            // [2][64]
    const float* cs = g_colsum + b * LL;
    float* ap = attn + (size_t)(b * LL + qb) * LL;

    // q tiles once (128 rows x 64 d, hi/lo)
    {
        const size_t qo = (size_t)(b * LL + qb) * DD;
#pragma unroll
        for (int s = 0; s < 4; ++s) {
            int u = t + 256 * s;
            int r = u >> 3, c16 = u & 7;
            uint32_t off = swzo(r, c16);
            size_t gi = qo + (size_t)r * DD + c16 * 8;
            *(uint4*)(smem + F_QH + off) = *reinterpret_cast<const uint4*>(&g_qh[gi]);
            *(uint4*)(smem + F_QL + off) = *reinterpret_cast<const uint4*>(&g_ql[gi]);
        }
    }
    if (t < 64) invb[t] = 1.f / cs[kBeg + t];

    auto issue = [&](int ci) {
        const int kc = kBeg + ci * 64;
        const uint32_t base = sb + F_KV + (uint32_t)(ci & 1) * F_STAGE;
        const size_t ko = (size_t)(b * LL + kc) * DD;
#pragma unroll
        for (int s = 0; s < 2; ++s) {
            int u = t + 256 * s;
            int r = u >> 3, c16 = u & 7;
            uint32_t off = swzo(r, c16);
            size_t gk = ko + (size_t)r * DD + c16 * 8;
            cpa16(base + off,         &g_kh[gk]);
            cpa16(base + 8192 + off,  &g_kl[gk]);
            size_t gv = (size_t)(b * DD + r) * LL + kc + c16 * 8;
            cpa16(base + 16384 + off, &g_vt[gv]);
        }
        CPA_COMMIT();
    };
    issue(0);

    float o[8][4];
#pragma unroll
    for (int nt = 0; nt < 8; ++nt)
#pragma unroll
        for (int j = 0; j < 4; ++j) o[nt][j] = 0.f;

    for (int ci = 0; ci < NCH; ++ci) {
        const int kc = kBeg + ci * 64;
        if (ci + 1 < NCH) {
            issue(ci + 1);
            asm volatile("cp.async.wait_group 1;" ::: "memory");
        } else {
            asm volatile("cp.async.wait_group 0;" ::: "memory");
        }
        __syncthreads();

        if (ci + 1 < NCH && t < 64)
            invb[((ci + 1) & 1) * 64 + t] = 1.f / cs[kc + 64 + t];

        const uint32_t kb_hi = sb + F_KV + (uint32_t)(ci & 1) * F_STAGE;
        const uint32_t kb_lo = kb_hi + 8192;
        const uint32_t vb    = kb_hi + 16384;
        const float* inv_s = invb + (ci & 1) * 64;

        // ---- S = q k^T (3-pass bf16) ----
        float acc[8][4];
#pragma unroll
        for (int nt = 0; nt < 8; ++nt)
#pragma unroll
            for (int j = 0; j < 4; ++j) acc[nt][j] = 0.f;

#pragma unroll
        for (int ks = 0; ks < 4; ++ks) {
            uint32_t qh[4], ql[4];
            {
                uint32_t aoff = swzo(w * 16 + (l & 15), ks * 2 + (l >> 4));
                ldsm4(qh, sb + F_QH + aoff);
                ldsm4(ql, sb + F_QL + aoff);
            }
            uint32_t kh[8][2], kl[8][2];
            {
                uint32_t boff = swzo(((l >> 4) << 3) + (l & 7),
                                     ks * 2 + ((l >> 3) & 1));
#pragma unroll
                for (int pg = 0; pg < 4; ++pg) {
                    uint32_t r4[4];
                    ldsm4(r4, kb_hi + boff + pg * 2048);
                    kh[pg * 2][0] = r4[0]; kh[pg * 2][1] = r4[1];
                    kh[pg * 2 + 1][0] = r4[2]; kh[pg * 2 + 1][1] = r4[3];
                    ldsm4(r4, kb_lo + boff + pg * 2048);
                    kl[pg * 2][0] = r4[0]; kl[pg * 2][1] = r4[1];
                    kl[pg * 2 + 1][0] = r4[2]; kl[pg * 2 + 1][1] = r4[3];
                }
            }
#pragma unroll
            for (int nt = 0; nt < 8; ++nt) {
                mma16816(acc[nt], qh, kh[nt]);
                mma16816(acc[nt], qh, kl[nt]);
                mma16816(acc[nt], ql, kh[nt]);
            }
        }

        // ---- P = exp(S)*inv ; store A fp32 ; pack P as fp16 A-fragments ----
        uint32_t ph[4][4];
#pragma unroll
        for (int nt = 0; nt < 8; ++nt) {
            int lc = nt * 8 + 2 * (l & 3);
            float i0 = inv_s[lc], i1 = inv_s[lc + 1];
            float e0 = __expf(acc[nt][0]) * i0;
            float e1 = __expf(acc[nt][1]) * i1;
            float e2 = __expf(acc[nt][2]) * i0;
            float e3 = __expf(acc[nt][3]) * i1;
            int r0 = w * 16 + (l >> 2);
            *reinterpret_cast<float2*>(&ap[(size_t)r0 * LL + kc + lc]) = make_float2(e0, e1);
            *reinterpret_cast<float2*>(&ap[(size_t)(r0 + 8) * LL + kc + lc]) = make_float2(e2, e3);
            int kb2 = nt >> 1, base = (nt & 1) * 2;
            ph[kb2][base + 0] = pk_f16(e0, e1);
            ph[kb2][base + 1] = pk_f16(e2, e3);
        }

        // ---- O += P @ V (single-pass fp16) ----
#pragma unroll
        for (int kb2 = 0; kb2 < 4; ++kb2) {
            uint32_t vf[8][2];
            {
                uint32_t boff = swzo(((l >> 4) << 3) + (l & 7),
                                     kb2 * 2 + ((l >> 3) & 1));
#pragma unroll
                for (int pg = 0; pg < 4; ++pg) {
                    uint32_t r4[4];
                    ldsm4(r4, vb + boff + pg * 2048);
                    vf[pg * 2][0] = r4[0]; vf[pg * 2][1] = r4[1];
                    vf[pg * 2 + 1][0] = r4[2]; vf[pg * 2 + 1][1] = r4[3];
                }
            }
#pragma unroll
            for (int nt = 0; nt < 8; ++nt)
                mma16816h(o[nt], ph[kb2], vf[nt]);
        }
        __syncthreads();
    }

    float* gv = g_vals[split];
#pragma unroll
    for (int nt = 0; nt < 8; ++nt) {
        int col = nt * 8 + 2 * (l & 3);
        size_t row = (size_t)(b * LL + qb + w * 16 + (l >> 2));
        *reinterpret_cast<float2*>(&gv[row * DD + col]) =
            make_float2(o[nt][0], o[nt][1]);
        *reinterpret_cast<float2*>(&gv[(row + 8) * DD + col]) =
            make_float2(o[nt][2], o[nt][3]);
    }
}

// ---------------------------------------------------------------------------
// Kernel 4: out = (sum_p g_vals[p]) @ Wo + bo. grid (MM/128, OUT/128), 256 thr.
// ---------------------------------------------------------------------------
__global__ __launch_bounds__(256) void out_kernel(
    const float* __restrict__ Wo, const float* __restrict__ bo,
    float* __restrict__ outp)
{
    const int mb = blockIdx.x * 128;
    const int nb = blockIdx.y * 128;
    const int t  = threadIdx.x;
    const int tx = t & 15, ty = t >> 4;

    __shared__ float vt[64 * 128];
    __shared__ float ws[64 * 128];

    {
        const int dq = t & 15, rb = t >> 4;
#pragma unroll
        for (int s = 0; s < 8; ++s) {
            int r = rb + s * 16;
            size_t base = (size_t)(mb + r) * DD + 4 * dq;
            float4 v = *reinterpret_cast<const float4*>(&g_vals[0][base]);
#pragma unroll
            for (int p = 1; p < NPART; ++p) {
                float4 u = *reinterpret_cast<const float4*>(&g_vals[p][base]);
                v.x += u.x; v.y += u.y; v.z += u.z; v.w += u.w;
            }
            vt[swz(4 * dq + 0, r)] = v.x; vt[swz(4 * dq + 1, r)] = v.y;
            vt[swz(4 * dq + 2, r)] = v.z; vt[swz(4 * dq + 3, r)] = v.w;
        }
        const int nq = t & 31, kb2 = t >> 5;
#pragma unroll
        for (int s = 0; s < 8; ++s) {
            int kr = kb2 + s * 8;
            *reinterpret_cast<float4*>(&ws[kr * 128 + 4 * nq]) =
                *reinterpret_cast<const float4*>(&Wo[(size_t)kr * OUT + nb + 4 * nq]);
        }
    }
    __syncthreads();

    u64 acc[32];
#pragma unroll
    for (int i = 0; i < 32; ++i) acc[i] = 0ull;

#pragma unroll 8
    for (int k = 0; k < 64; ++k) {
        float4 a0 = *reinterpret_cast<const float4*>(&vt[swz(k, 4 * ty)]);
        float4 a1 = *reinterpret_cast<const float4*>(&vt[swz(k, 64 + 4 * ty)]);
        float4 b0 = *reinterpret_cast<const float4*>(&ws[k * 128 + 4 * tx]);
        float4 b1 = *reinterpret_cast<const float4*>(&ws[k * 128 + 64 + 4 * tx]);
        rank1(acc, a0, a1, b0, b1);
    }

    float4 bo0 = *reinterpret_cast<const float4*>(&bo[nb + 4 * tx]);
    float4 bo1 = *reinterpret_cast<const float4*>(&bo[nb + 64 + 4 * tx]);
#pragma unroll
    for (int i = 0; i < 8; ++i) {
        int r = (i < 4) ? (4 * ty + i) : (64 + 4 * ty + (i - 4));
        float2 p0 = up2(acc[i * 4 + 0]), p1 = up2(acc[i * 4 + 1]);
        float2 p2 = up2(acc[i * 4 + 2]), p3 = up2(acc[i * 4 + 3]);
        float4 o0 = make_float4(p0.x + bo0.x, p0.y + bo0.y, p1.x + bo0.z, p1.y + bo0.w);
        float4 o1 = make_float4(p2.x + bo1.x, p2.y + bo1.y, p3.x + bo1.z, p3.y + bo1.w);
        *reinterpret_cast<float4*>(&outp[(size_t)(mb + r) * OUT + nb + 4 * tx]) = o0;
        *reinterpret_cast<float4*>(&outp[(size_t)(mb + r) * OUT + nb + 64 + 4 * tx]) = o1;
    }
}

// ---------------------------------------------------------------------------
extern "C" void kernel_launch(void* const* d_in, const int* in_sizes, int n_in,
                              void* d_out, int out_size)
{
    const float* x  = (const float*)d_in[0];
    const float* Wq = (const float*)d_in[1];
    const float* bq = (const float*)d_in[2];
    const float* Wk = (const float*)d_in[3];
    const float* bk = (const float*)d_in[4];
    const float* Wv = (const float*)d_in[5];
    const float* bv = (const float*)d_in[6];
    const float* Wo = (const float*)d_in[7];
    const float* bo = (const float*)d_in[8];

    float* outp = (float*)d_out;                   // [B, L, OUT]
    float* attn = outp + (size_t)BB * LL * OUT;    // [B, L, L]

    cudaFuncSetAttribute(qkv_mma,    cudaFuncAttributeMaxDynamicSharedMemorySize, Q_SMEM);
    cudaFuncSetAttribute(scores_sum, cudaFuncAttributeMaxDynamicSharedMemorySize, S_SMEM);
    cudaFuncSetAttribute(av_fused,   cudaFuncAttributeMaxDynamicSharedMemorySize, F_SMEM);

    qkv_mma<<<dim3(MM / 128, 3), 256, Q_SMEM>>>(x, Wq, bq, Wk, bk, Wv, bv);
    vtrans_kernel<<<dim3(LL / 64, BB), 256>>>();
    scores_sum<<<dim3(LL / 128, LL / 128, BB), 256, S_SMEM>>>();
    av_fused<<<dim3(LL / 128, KSPLIT, BB), 256, F_SMEM>>>(attn);
    out_kernel<<<dim3(MM / 128, OUT / 128), 256>>>(Wo, bo, outp);
}

// round 15
// speedup vs baseline: 4.5649x; 1.1750x over previous
#include <cuda_runtime.h>
#include <cuda_bf16.h>
#include <cuda_fp16.h>
#include <cstdint>

// ---------------------------------------------------------------------------
// AttentionBlock, Round 14: fp16 single-pass S everywhere.
//  k1  qkv_mma   : q,k,v = x@W+b via bf16 hi/lo 3-pass HMMA; q pre-scaled;
//                  q,k stored plain fp16; v fp32.
//  k1b vtrans    : v -> v^T fp16.
//  k2  scores_sum: colsum[b,k] = sum_q exp(S), 1-pass fp16 HMMA.
//  k3  av_fused  : recompute S 1-pass fp16 (bitwise-consistent with colsum),
//                  P=exp(S)*inv (fp32 store to attn, fp16 pack),
//                  O += P@V single-pass fp16.
//  k4  out       : out = (sum partials) @ Wo + bo (f32x2).
// B=4, L=4096, IN=512, D=64, OUT=512.  Outputs: (out, attention).
// ---------------------------------------------------------------------------

namespace {
constexpr int BB  = 4;
constexpr int LL  = 4096;
constexpr int IN  = 512;
constexpr int DD  = 64;
constexpr int OUT = 512;
constexpr int MM  = BB * LL;
constexpr int KSPLIT = 4;
constexpr int NPART = KSPLIT;
constexpr float SCALE = 0.125f;

// qkv_mma smem
constexpr uint32_t Q_XH = 0, Q_XL = 16384, Q_WH = 32768, Q_WL = 40960,
                   Q_ST = 49152, Q_SMEM = 49152 + 16384;   // 65536
// scores_sum smem (fp16 single tiles)
constexpr uint32_t S_QF = 0, S_KF = 16384, S_RED = 32768,
                   S_SMEM = 32768 + 2048;
// av_fused smem: Q fp16 (16K), 2 stages x (KF 8K + VF 8K) = 32K, inv.
constexpr uint32_t F_QF = 0, F_KV = 16384;
constexpr uint32_t F_STAGE = 16384;
constexpr uint32_t F_INV = F_KV + 2 * F_STAGE;             // 49152
constexpr uint32_t F_SMEM = F_INV + 512;                   // 49664
}

typedef unsigned long long u64;

// ------------------------------- helpers -----------------------------------
__device__ __forceinline__ uint32_t smem_u32(const void* p) {
    uint32_t a;
    asm("{ .reg .u64 t; cvta.to.shared.u64 t, %1; cvt.u32.u64 %0, t; }" : "=r"(a) : "l"(p));
    return a;
}
// swizzled byte offset in a [rows][64 x 16-bit] tile (128B rows, 16B units)
__device__ __forceinline__ uint32_t swzo(int r, int c16) {
    return (uint32_t)(r * 128 + ((c16 ^ (r & 7)) << 4));
}
__device__ __forceinline__ void ldsm4(uint32_t r[4], uint32_t addr) {
    asm volatile("ldmatrix.sync.aligned.m8n8.x4.shared.b16 {%0,%1,%2,%3}, [%4];"
        : "=r"(r[0]), "=r"(r[1]), "=r"(r[2]), "=r"(r[3]) : "r"(addr));
}
__device__ __forceinline__ void mma16816(float c[4], const uint32_t a[4], const uint32_t b[2]) {
    asm volatile("mma.sync.aligned.m16n8k16.row.col.f32.bf16.bf16.f32 "
        "{%0,%1,%2,%3}, {%4,%5,%6,%7}, {%8,%9}, {%0,%1,%2,%3};"
        : "+f"(c[0]), "+f"(c[1]), "+f"(c[2]), "+f"(c[3])
        : "r"(a[0]), "r"(a[1]), "r"(a[2]), "r"(a[3]), "r"(b[0]), "r"(b[1]));
}
__device__ __forceinline__ void mma16816h(float c[4], const uint32_t a[4], const uint32_t b[2]) {
    asm volatile("mma.sync.aligned.m16n8k16.row.col.f32.f16.f16.f32 "
        "{%0,%1,%2,%3}, {%4,%5,%6,%7}, {%8,%9}, {%0,%1,%2,%3};"
        : "+f"(c[0]), "+f"(c[1]), "+f"(c[2]), "+f"(c[3])
        : "r"(a[0]), "r"(a[1]), "r"(a[2]), "r"(a[3]), "r"(b[0]), "r"(b[1]));
}
__device__ __forceinline__ uint32_t pk_bf(float a, float b) {
    return (uint32_t)__bfloat16_as_ushort(__float2bfloat16(a)) |
           ((uint32_t)__bfloat16_as_ushort(__float2bfloat16(b)) << 16);
}
// packed fp16x2: lo = a, hi = b (single cvt instruction)
__device__ __forceinline__ uint32_t pk_f16(float a, float b) {
    uint32_t r;
    asm("cvt.rn.f16x2.f32 %0, %1, %2;" : "=r"(r) : "f"(b), "f"(a));
    return r;
}
__device__ __forceinline__ void split1(float v, float& hi, float& lo) {
    __nv_bfloat16 h = __float2bfloat16(v);
    hi = __bfloat162float(h);
    lo = v - hi;
}
// 8 consecutive floats -> bf16 hi/lo uint4s
__device__ __forceinline__ void split8(const float4& a, const float4& c, uint4& hi, uint4& lo) {
    float h0, l0, h1, l1;
    split1(a.x, h0, l0); split1(a.y, h1, l1);
    hi.x = pk_bf(h0, h1); lo.x = pk_bf(l0, l1);
    split1(a.z, h0, l0); split1(a.w, h1, l1);
    hi.y = pk_bf(h0, h1); lo.y = pk_bf(l0, l1);
    split1(c.x, h0, l0); split1(c.y, h1, l1);
    hi.z = pk_bf(h0, h1); lo.z = pk_bf(l0, l1);
    split1(c.z, h0, l0); split1(c.w, h1, l1);
    hi.w = pk_bf(h0, h1); lo.w = pk_bf(l0, l1);
}
__device__ __forceinline__ void cpa16(uint32_t s, const void* g) {
    asm volatile("cp.async.cg.shared.global [%0], [%1], 16;" :: "r"(s), "l"(g) : "memory");
}
#define CPA_COMMIT() asm volatile("cp.async.commit_group;" ::: "memory")

// ---------------------------- f32x2 (out) ----------------------------------
__device__ __forceinline__ void fma2(u64 &d, u64 a, u64 b) {
    asm("fma.rn.f32x2 %0, %1, %2, %0;" : "+l"(d) : "l"(a), "l"(b));
}
__device__ __forceinline__ u64 dup2(float a) {
    u64 r; asm("mov.b64 %0, {%1, %1};" : "=l"(r) : "f"(a)); return r;
}
__device__ __forceinline__ u64 pk2(float lo, float hi) {
    u64 r; asm("mov.b64 %0, {%1, %2};" : "=l"(r) : "f"(lo), "f"(hi)); return r;
}
__device__ __forceinline__ float2 up2(u64 v) {
    float2 r; asm("mov.b64 {%0, %1}, %2;" : "=f"(r.x), "=f"(r.y) : "l"(v)); return r;
}
__device__ __forceinline__ int swz(int d, int c) { return d * 128 + (c ^ (d & 28)); }

__device__ __forceinline__ void rank1(u64* acc, float4 a0, float4 a1,
                                      float4 b0, float4 b1)
{
    u64 bp0 = pk2(b0.x, b0.y), bp1 = pk2(b0.z, b0.w);
    u64 bp2 = pk2(b1.x, b1.y), bp3 = pk2(b1.z, b1.w);
    float av[8] = {a0.x, a0.y, a0.z, a0.w, a1.x, a1.y, a1.z, a1.w};
#pragma unroll
    for (int i = 0; i < 8; ++i) {
        u64 ad = dup2(av[i]);
        fma2(acc[i * 4 + 0], ad, bp0);
        fma2(acc[i * 4 + 1], ad, bp1);
        fma2(acc[i * 4 + 2], ad, bp2);
        fma2(acc[i * 4 + 3], ad, bp3);
    }
}

// ------------------------------ device scratch -----------------------------
__device__ __half g_qf[MM * DD], g_kf[MM * DD];          // q (pre-scaled), k fp16
__device__ float g_v[MM * DD];
__device__ float g_colsum[MM];
__device__ float g_vals[NPART][MM * DD];
__device__ __half g_vt[BB * DD * LL];                    // v^T fp16 [b][d][k]

// ---------------------------------------------------------------------------
// Kernel 1: qkv_mma.  q,k,v = x@W+b via 3-pass bf16 HMMA.
// grid (MM/128, 3), 256 thr.  Also zeroes g_colsum.
// ---------------------------------------------------------------------------
__global__ __launch_bounds__(256) void qkv_mma(
    const float* __restrict__ x,
    const float* __restrict__ Wq, const float* __restrict__ bq,
    const float* __restrict__ Wk, const float* __restrict__ bk,
    const float* __restrict__ Wv, const float* __restrict__ bv)
{
    extern __shared__ char smem[];
    const uint32_t sb = smem_u32(smem);
    const int t = threadIdx.x, l = t & 31, w = t >> 5;
    const int gid = (blockIdx.y * gridDim.x + blockIdx.x) * 256 + t;
    if (gid < MM) g_colsum[gid] = 0.f;

    const float* W; const float* bias; float oscale;
    __half* of = nullptr;
    if (blockIdx.y == 0)      { W = Wq; bias = bq; of = g_qf; oscale = SCALE; }
    else if (blockIdx.y == 1) { W = Wk; bias = bk; of = g_kf; oscale = 1.f; }
    else                      { W = Wv; bias = bv; oscale = 1.f; }
    const bool isv = (blockIdx.y == 2);
    const int mb = blockIdx.x * 128;

    float* stg = (float*)(smem + Q_ST);              // W fp32 stage [64][64]

    float acc[8][4];
#pragma unroll
    for (int nt = 0; nt < 8; ++nt)
#pragma unroll
        for (int j = 0; j < 4; ++j) acc[nt][j] = 0.f;

    for (int kc = 0; kc < IN; kc += 64) {
        __syncthreads();
#pragma unroll
        for (int s = 0; s < 4; ++s) {
            int u = t + 256 * s;
            int r = u >> 3, c16 = u & 7;
            const float* xp = &x[(size_t)(mb + r) * IN + kc + c16 * 8];
            float4 a = *reinterpret_cast<const float4*>(xp);
            float4 c = *reinterpret_cast<const float4*>(xp + 4);
            uint4 hi, lo;
            split8(a, c, hi, lo);
            uint32_t off = swzo(r, c16);
            *(uint4*)(smem + Q_XH + off) = hi;
            *(uint4*)(smem + Q_XL + off) = lo;
        }
#pragma unroll
        for (int s = 0; s < 4; ++s) {
            int u = t + 256 * s;
            int k = u >> 4, c4 = u & 15;
            *reinterpret_cast<float4*>(&stg[k * 64 + 4 * c4]) =
                *reinterpret_cast<const float4*>(&W[(size_t)(kc + k) * DD + 4 * c4]);
        }
        __syncthreads();
#pragma unroll
        for (int s = 0; s < 2; ++s) {
            int u = t + 256 * s;
            int k16 = u >> 6, n = u & 63;
            union { __nv_bfloat16 h[8]; uint4 u4; } hi, lo;
#pragma unroll
            for (int j = 0; j < 8; ++j) {
                float v = stg[(k16 * 8 + j) * 64 + n];
                __nv_bfloat16 hb = __float2bfloat16(v);
                hi.h[j] = hb;
                lo.h[j] = __float2bfloat16(v - __bfloat162float(hb));
            }
            uint32_t off = swzo(n, k16);
            *(uint4*)(smem + Q_WH + off) = hi.u4;
            *(uint4*)(smem + Q_WL + off) = lo.u4;
        }
        __syncthreads();
#pragma unroll
        for (int ks = 0; ks < 4; ++ks) {
            uint32_t xh[4], xl[4];
            uint32_t aoff = swzo(w * 16 + (l & 15), ks * 2 + (l >> 4));
            ldsm4(xh, sb + Q_XH + aoff);
            ldsm4(xl, sb + Q_XL + aoff);
            uint32_t wh[8][2], wl[8][2];
            uint32_t boff = swzo(((l >> 4) << 3) + (l & 7), ks * 2 + ((l >> 3) & 1));
#pragma unroll
            for (int pg = 0; pg < 4; ++pg) {
                uint32_t r4[4];
                ldsm4(r4, sb + Q_WH + boff + pg * 2048);
                wh[pg * 2][0] = r4[0]; wh[pg * 2][1] = r4[1];
                wh[pg * 2 + 1][0] = r4[2]; wh[pg * 2 + 1][1] = r4[3];
                ldsm4(r4, sb + Q_WL + boff + pg * 2048);
                wl[pg * 2][0] = r4[0]; wl[pg * 2][1] = r4[1];
                wl[pg * 2 + 1][0] = r4[2]; wl[pg * 2 + 1][1] = r4[3];
            }
#pragma unroll
            for (int nt = 0; nt < 8; ++nt) {
                mma16816(acc[nt], xh, wh[nt]);
                mma16816(acc[nt], xh, wl[nt]);
                mma16816(acc[nt], xl, wh[nt]);
            }
        }
    }
#pragma unroll
    for (int nt = 0; nt < 8; ++nt) {
        int col = nt * 8 + 2 * (l & 3);
        float b0 = bias[col], b1 = bias[col + 1];
        int r0 = mb + w * 16 + (l >> 2);
        float e0 = (acc[nt][0] + b0) * oscale;
        float e1 = (acc[nt][1] + b1) * oscale;
        float e2 = (acc[nt][2] + b0) * oscale;
        float e3 = (acc[nt][3] + b1) * oscale;
        if (isv) {
            *reinterpret_cast<float2*>(&g_v[(size_t)r0 * DD + col]) = make_float2(e0, e1);
            *reinterpret_cast<float2*>(&g_v[(size_t)(r0 + 8) * DD + col]) = make_float2(e2, e3);
        } else {
            *reinterpret_cast<uint32_t*>(&of[(size_t)r0 * DD + col]) = pk_f16(e0, e1);
            *reinterpret_cast<uint32_t*>(&of[(size_t)(r0 + 8) * DD + col]) = pk_f16(e2, e3);
        }
    }
}

// ---------------------------------------------------------------------------
// Kernel 1b: v[b][k][d] -> fp16 transposed g_vt[b][d][k].
// grid (LL/64, BB), 256 thr.
// ---------------------------------------------------------------------------
__global__ __launch_bounds__(256) void vtrans_kernel()
{
    const int b = blockIdx.y, kb = blockIdx.x * 64;
    const int t = threadIdx.x;
    __shared__ float tile[64][68];

    const int c4 = t & 15, r0 = t >> 4;
#pragma unroll
    for (int s = 0; s < 4; ++s) {
        int r = r0 + 16 * s;
        float4 v = *reinterpret_cast<const float4*>(&g_v[(size_t)(b * LL + kb + r) * DD + 4 * c4]);
        tile[r][4 * c4 + 0] = v.x; tile[r][4 * c4 + 1] = v.y;
        tile[r][4 * c4 + 2] = v.z; tile[r][4 * c4 + 3] = v.w;
    }
    __syncthreads();

    const int f8 = t & 7, d0 = t >> 3;
#pragma unroll
    for (int s = 0; s < 2; ++s) {
        int d = d0 + 32 * s;
        union { __half h[8]; uint4 u; } hi;
#pragma unroll
        for (int j = 0; j < 8; ++j)
            hi.h[j] = __float2half_rn(tile[f8 * 8 + j][d]);
        size_t o = (size_t)(b * DD + d) * LL + kb + f8 * 8;
        *reinterpret_cast<uint4*>(&g_vt[o]) = hi.u;
    }
}

// ---------------------------------------------------------------------------
// Kernel 2: scores_sum (1-pass fp16).  colsum[b,k] += sum_q exp(S[q,k]).
// grid (L/128 kb, L/128 qb, B), 256 thr, 2 CTAs/SM.
// ---------------------------------------------------------------------------
__global__ __launch_bounds__(256, 2) void scores_sum(void)
{
    extern __shared__ char smem[];
    const uint32_t sb = smem_u32(smem);
    const int t = threadIdx.x, l = t & 31, w = t >> 5;
    const int wm = w & 3, wn = w >> 2;
    const int b = blockIdx.z, qb = blockIdx.y * 128, kb = blockIdx.x * 128;

    {
        const size_t qo = (size_t)(b * LL + qb) * DD;
        const size_t ko = (size_t)(b * LL + kb) * DD;
#pragma unroll
        for (int s = 0; s < 4; ++s) {
            int u = t + 256 * s;
            int r = u >> 3, c16 = u & 7;
            uint32_t off = swzo(r, c16);
            size_t gi = qo + (size_t)r * DD + c16 * 8;
            *(uint4*)(smem + S_QF + off) = *reinterpret_cast<const uint4*>(&g_qf[gi]);
            gi = ko + (size_t)r * DD + c16 * 8;
            *(uint4*)(smem + S_KF + off) = *reinterpret_cast<const uint4*>(&g_kf[gi]);
        }
    }
    __syncthreads();

    float acc[2][8][4];
#pragma unroll
    for (int mt = 0; mt < 2; ++mt)
#pragma unroll
        for (int nt = 0; nt < 8; ++nt)
#pragma unroll
            for (int j = 0; j < 4; ++j) acc[mt][nt][j] = 0.f;

#pragma unroll
    for (int ks = 0; ks < 4; ++ks) {
        uint32_t qf[2][4];
        {
            uint32_t aoff = swzo(wm * 32 + (l & 15), ks * 2 + (l >> 4));
            ldsm4(qf[0], sb + S_QF + aoff);
            ldsm4(qf[1], sb + S_QF + aoff + 2048);
        }
        uint32_t kf[8][2];
        {
            uint32_t boff = swzo(wn * 64 + ((l >> 4) << 3) + (l & 7),
                                 ks * 2 + ((l >> 3) & 1));
#pragma unroll
            for (int pg = 0; pg < 4; ++pg) {
                uint32_t r4[4];
                ldsm4(r4, sb + S_KF + boff + pg * 2048);
                kf[pg * 2][0] = r4[0]; kf[pg * 2][1] = r4[1];
                kf[pg * 2 + 1][0] = r4[2]; kf[pg * 2 + 1][1] = r4[3];
            }
        }
#pragma unroll
        for (int mt = 0; mt < 2; ++mt)
#pragma unroll
            for (int nt = 0; nt < 8; ++nt)
                mma16816h(acc[mt][nt], qf[mt], kf[nt]);
    }

    float* colred = (float*)(smem + S_RED);
#pragma unroll
    for (int nt = 0; nt < 8; ++nt) {
        float cs0 = 0.f, cs1 = 0.f;
#pragma unroll
        for (int mt = 0; mt < 2; ++mt) {
            cs0 += __expf(acc[mt][nt][0]) + __expf(acc[mt][nt][2]);
            cs1 += __expf(acc[mt][nt][1]) + __expf(acc[mt][nt][3]);
        }
#pragma unroll
        for (int m = 4; m < 32; m <<= 1) {
            cs0 += __shfl_xor_sync(0xffffffffu, cs0, m);
            cs1 += __shfl_xor_sync(0xffffffffu, cs1, m);
        }
        if (l < 4) {
            colred[wm * 128 + wn * 64 + nt * 8 + 2 * l + 0] = cs0;
            colred[wm * 128 + wn * 64 + nt * 8 + 2 * l + 1] = cs1;
        }
    }
    __syncthreads();
    if (t < 128) {
        float s = colred[t] + colred[128 + t] + colred[256 + t] + colred[384 + t];
        atomicAdd(&g_colsum[b * LL + kb + t], s);
    }
}

// ---------------------------------------------------------------------------
// Kernel 3: av_fused.  S 1-pass fp16 (consistent with colsum); P fp16;
// O single-pass fp16 V.  16 q-rows/warp, 64-col chunks, 2 CTAs/SM,
// cp.async double buffering.  grid (L/128, KSPLIT, B), 256 thr.
// ---------------------------------------------------------------------------
__global__ __launch_bounds__(256, 2) void av_fused(float* __restrict__ attn)
{
    extern __shared__ char smem[];
    const uint32_t sb = smem_u32(smem);
    const int t = threadIdx.x, l = t & 31, w = t >> 5;
    const int b = blockIdx.z, split = blockIdx.y, qb = blockIdx.x * 128;
    const int kBeg = split * (LL / KSPLIT);
    constexpr int NCH = (LL / KSPLIT) / 64;          // 16 chunks

    float* invb = (float*)(smem + F_INV);            // [2][64]
    const float* cs = g_colsum + b * LL;
    float* ap = attn + (size_t)(b * LL + qb) * LL;

    // q tile once (128 rows x 64 d fp16)
    {
        const size_t qo = (size_t)(b * LL + qb) * DD;
#pragma unroll
        for (int s = 0; s < 4; ++s) {
            int u = t + 256 * s;
            int r = u >> 3, c16 = u & 7;
            *(uint4*)(smem + F_QF + swzo(r, c16)) =
                *reinterpret_cast<const uint4*>(&g_qf[qo + (size_t)r * DD + c16 * 8]);
        }
    }
    if (t < 64) invb[t] = 1.f / cs[kBeg + t];

    auto issue = [&](int ci) {
        const int kc = kBeg + ci * 64;
        const uint32_t base = sb + F_KV + (uint32_t)(ci & 1) * F_STAGE;
        const size_t ko = (size_t)(b * LL + kc) * DD;
#pragma unroll
        for (int s = 0; s < 2; ++s) {
            int u = t + 256 * s;
            int r = u >> 3, c16 = u & 7;
            uint32_t off = swzo(r, c16);
            cpa16(base + off,        &g_kf[ko + (size_t)r * DD + c16 * 8]);
            cpa16(base + 8192 + off, &g_vt[(size_t)(b * DD + r) * LL + kc + c16 * 8]);
        }
        CPA_COMMIT();
    };
    issue(0);

    float o[8][4];
#pragma unroll
    for (int nt = 0; nt < 8; ++nt)
#pragma unroll
        for (int j = 0; j < 4; ++j) o[nt][j] = 0.f;

    for (int ci = 0; ci < NCH; ++ci) {
        const int kc = kBeg + ci * 64;
        if (ci + 1 < NCH) {
            issue(ci + 1);
            asm volatile("cp.async.wait_group 1;" ::: "memory");
        } else {
            asm volatile("cp.async.wait_group 0;" ::: "memory");
        }
        __syncthreads();

        if (ci + 1 < NCH && t < 64)
            invb[((ci + 1) & 1) * 64 + t] = 1.f / cs[kc + 64 + t];

        const uint32_t kbuf = sb + F_KV + (uint32_t)(ci & 1) * F_STAGE;
        const uint32_t vbuf = kbuf + 8192;
        const float* inv_s = invb + (ci & 1) * 64;

        // ---- S = q k^T (1-pass fp16, identical op order to scores_sum) ----
        float acc[8][4];
#pragma unroll
        for (int nt = 0; nt < 8; ++nt)
#pragma unroll
            for (int j = 0; j < 4; ++j) acc[nt][j] = 0.f;

#pragma unroll
        for (int ks = 0; ks < 4; ++ks) {
            uint32_t qf[4];
            ldsm4(qf, sb + F_QF + swzo(w * 16 + (l & 15), ks * 2 + (l >> 4)));
            uint32_t kf[8][2];
            {
                uint32_t boff = swzo(((l >> 4) << 3) + (l & 7),
                                     ks * 2 + ((l >> 3) & 1));
#pragma unroll
                for (int pg = 0; pg < 4; ++pg) {
                    uint32_t r4[4];
                    ldsm4(r4, kbuf + boff + pg * 2048);
                    kf[pg * 2][0] = r4[0]; kf[pg * 2][1] = r4[1];
                    kf[pg * 2 + 1][0] = r4[2]; kf[pg * 2 + 1][1] = r4[3];
                }
            }
#pragma unroll
            for (int nt = 0; nt < 8; ++nt)
                mma16816h(acc[nt], qf, kf[nt]);
        }

        // ---- P = exp(S)*inv ; store A fp32 ; pack P as fp16 A-fragments ----
        uint32_t ph[4][4];
#pragma unroll
        for (int nt = 0; nt < 8; ++nt) {
            int lc = nt * 8 + 2 * (l & 3);
            float i0 = inv_s[lc], i1 = inv_s[lc + 1];
            float e0 = __expf(acc[nt][0]) * i0;
            float e1 = __expf(acc[nt][1]) * i1;
            float e2 = __expf(acc[nt][2]) * i0;
            float e3 = __expf(acc[nt][3]) * i1;
            int r0 = w * 16 + (l >> 2);
            *reinterpret_cast<float2*>(&ap[(size_t)r0 * LL + kc + lc]) = make_float2(e0, e1);
            *reinterpret_cast<float2*>(&ap[(size_t)(r0 + 8) * LL + kc + lc]) = make_float2(e2, e3);
            int kb2 = nt >> 1, base = (nt & 1) * 2;
            ph[kb2][base + 0] = pk_f16(e0, e1);
            ph[kb2][base + 1] = pk_f16(e2, e3);
        }

        // ---- O += P @ V (single-pass fp16) ----
#pragma unroll
        for (int kb2 = 0; kb2 < 4; ++kb2) {
            uint32_t vf[8][2];
            {
                uint32_t boff = swzo(((l >> 4) << 3) + (l & 7),
                                     kb2 * 2 + ((l >> 3) & 1));
#pragma unroll
                for (int pg = 0; pg < 4; ++pg) {
                    uint32_t r4[4];
                    ldsm4(r4, vbuf + boff + pg * 2048);
                    vf[pg * 2][0] = r4[0]; vf[pg * 2][1] = r4[1];
                    vf[pg * 2 + 1][0] = r4[2]; vf[pg * 2 + 1][1] = r4[3];
                }
            }
#pragma unroll
            for (int nt = 0; nt < 8; ++nt)
                mma16816h(o[nt], ph[kb2], vf[nt]);
        }
        __syncthreads();
    }

    float* gv = g_vals[split];
#pragma unroll
    for (int nt = 0; nt < 8; ++nt) {
        int col = nt * 8 + 2 * (l & 3);
        size_t row = (size_t)(b * LL + qb + w * 16 + (l >> 2));
        *reinterpret_cast<float2*>(&gv[row * DD + col]) =
            make_float2(o[nt][0], o[nt][1]);
        *reinterpret_cast<float2*>(&gv[(row + 8) * DD + col]) =
            make_float2(o[nt][2], o[nt][3]);
    }
}

// ---------------------------------------------------------------------------
// Kernel 4: out = (sum_p g_vals[p]) @ Wo + bo. grid (MM/128, OUT/128), 256 thr.
// ---------------------------------------------------------------------------
__global__ __launch_bounds__(256) void out_kernel(
    const float* __restrict__ Wo, const float* __restrict__ bo,
    float* __restrict__ outp)
{
    const int mb = blockIdx.x * 128;
    const int nb = blockIdx.y * 128;
    const int t  = threadIdx.x;
    const int tx = t & 15, ty = t >> 4;

    __shared__ float vt[64 * 128];
    __shared__ float ws[64 * 128];

    {
        const int dq = t & 15, rb = t >> 4;
#pragma unroll
        for (int s = 0; s < 8; ++s) {
            int r = rb + s * 16;
            size_t base = (size_t)(mb + r) * DD + 4 * dq;
            float4 v = *reinterpret_cast<const float4*>(&g_vals[0][base]);
#pragma unroll
            for (int p = 1; p < NPART; ++p) {
                float4 u = *reinterpret_cast<const float4*>(&g_vals[p][base]);
                v.x += u.x; v.y += u.y; v.z += u.z; v.w += u.w;
            }
            vt[swz(4 * dq + 0, r)] = v.x; vt[swz(4 * dq + 1, r)] = v.y;
            vt[swz(4 * dq + 2, r)] = v.z; vt[swz(4 * dq + 3, r)] = v.w;
        }
        const int nq = t & 31, kb2 = t >> 5;
#pragma unroll
        for (int s = 0; s < 8; ++s) {
            int kr = kb2 + s * 8;
            *reinterpret_cast<float4*>(&ws[kr * 128 + 4 * nq]) =
                *reinterpret_cast<const float4*>(&Wo[(size_t)kr * OUT + nb + 4 * nq]);
        }
    }
    __syncthreads();

    u64 acc[32];
#pragma unroll
    for (int i = 0; i < 32; ++i) acc[i] = 0ull;

#pragma unroll 8
    for (int k = 0; k < 64; ++k) {
        float4 a0 = *reinterpret_cast<const float4*>(&vt[swz(k, 4 * ty)]);
        float4 a1 = *reinterpret_cast<const float4*>(&vt[swz(k, 64 + 4 * ty)]);
        float4 b0 = *reinterpret_cast<const float4*>(&ws[k * 128 + 4 * tx]);
        float4 b1 = *reinterpret_cast<const float4*>(&ws[k * 128 + 64 + 4 * tx]);
        rank1(acc, a0, a1, b0, b1);
    }

    float4 bo0 = *reinterpret_cast<const float4*>(&bo[nb + 4 * tx]);
    float4 bo1 = *reinterpret_cast<const float4*>(&bo[nb + 64 + 4 * tx]);
#pragma unroll
    for (int i = 0; i < 8; ++i) {
        int r = (i < 4) ? (4 * ty + i) : (64 + 4 * ty + (i - 4));
        float2 p0 = up2(acc[i * 4 + 0]), p1 = up2(acc[i * 4 + 1]);
        float2 p2 = up2(acc[i * 4 + 2]), p3 = up2(acc[i * 4 + 3]);
        float4 o0 = make_float4(p0.x + bo0.x, p0.y + bo0.y, p1.x + bo0.z, p1.y + bo0.w);
        float4 o1 = make_float4(p2.x + bo1.x, p2.y + bo1.y, p3.x + bo1.z, p3.y + bo1.w);
        *reinterpret_cast<float4*>(&outp[(size_t)(mb + r) * OUT + nb + 4 * tx]) = o0;
        *reinterpret_cast<float4*>(&outp[(size_t)(mb + r) * OUT + nb + 64 + 4 * tx]) = o1;
    }
}

// ---------------------------------------------------------------------------
extern "C" void kernel_launch(void* const* d_in, const int* in_sizes, int n_in,
                              void* d_out, int out_size)
{
    const float* x  = (const float*)d_in[0];
    const float* Wq = (const float*)d_in[1];
    const float* bq = (const float*)d_in[2];
    const float* Wk = (const float*)d_in[3];
    const float* bk = (const float*)d_in[4];
    const float* Wv = (const float*)d_in[5];
    const float* bv = (const float*)d_in[6];
    const float* Wo = (const float*)d_in[7];
    const float* bo = (const float*)d_in[8];

    float* outp = (float*)d_out;                   // [B, L, OUT]
    float* attn = outp + (size_t)BB * LL * OUT;    // [B, L, L]

    cudaFuncSetAttribute(qkv_mma,    cudaFuncAttributeMaxDynamicSharedMemorySize, Q_SMEM);
    cudaFuncSetAttribute(scores_sum, cudaFuncAttributeMaxDynamicSharedMemorySize, S_SMEM);
    cudaFuncSetAttribute(av_fused,   cudaFuncAttributeMaxDynamicSharedMemorySize, F_SMEM);

    qkv_mma<<<dim3(MM / 128, 3), 256, Q_SMEM>>>(x, Wq, bq, Wk, bk, Wv, bv);
    vtrans_kernel<<<dim3(LL / 64, BB), 256>>>();
    scores_sum<<<dim3(LL / 128, LL / 128, BB), 256, S_SMEM>>>();
    av_fused<<<dim3(LL / 128, KSPLIT, BB), 256, F_SMEM>>>(attn);
    out_kernel<<<dim3(MM / 128, OUT / 128), 256>>>(Wo, bo, outp);
}

// round 17
// speedup vs baseline: 4.8407x; 1.0604x over previous
#include <cuda_runtime.h>
#include <cuda_bf16.h>
#include <cuda_fp16.h>
#include <cstdint>

// ---------------------------------------------------------------------------
// AttentionBlock, Round 16 (re-run of R15 after infra failure):
// HMMA out-projection + fp16 O partials.
//  k1  qkv_mma   : q,k,v = x@W+b via bf16 hi/lo 3-pass HMMA; q pre-scaled;
//                  q,k stored plain fp16; v fp32.
//  k1b vtrans    : v -> v^T fp16.
//  k2  scores_sum: colsum[b,k] = sum_q exp(S), 1-pass fp16 HMMA.
//  k3  av_fused  : recompute S 1-pass fp16 (consistent with colsum),
//                  P=exp(S)*inv (fp32 store to attn, fp16 pack),
//                  O += P@V single-pass fp16; fp16 partials out.
//  k4  out_mma   : out = (sum fp16 partials) @ Wo + bo, fp16 A x
//                  (fp16 hi + fp16 residual) Wo, 2-pass HMMA.
// B=4, L=4096, IN=512, D=64, OUT=512.  Outputs: (out, attention).
// ---------------------------------------------------------------------------

namespace {
constexpr int BB  = 4;
constexpr int LL  = 4096;
constexpr int IN  = 512;
constexpr int DD  = 64;
constexpr int OUT = 512;
constexpr int MM  = BB * LL;
constexpr int KSPLIT = 4;
constexpr int NPART = KSPLIT;
constexpr float SCALE = 0.125f;

// qkv_mma smem
constexpr uint32_t Q_XH = 0, Q_XL = 16384, Q_WH = 32768, Q_WL = 40960,
                   Q_ST = 49152, Q_SMEM = 49152 + 16384;   // 65536
// scores_sum smem (fp16 single tiles)
constexpr uint32_t S_QF = 0, S_KF = 16384, S_RED = 32768,
                   S_SMEM = 32768 + 2048;
// av_fused smem: Q fp16 (16K), 2 stages x (KF 8K + VF 8K) = 32K, inv.
constexpr uint32_t F_QF = 0, F_KV = 16384;
constexpr uint32_t F_STAGE = 16384;
constexpr uint32_t F_INV = F_KV + 2 * F_STAGE;             // 49152
constexpr uint32_t F_SMEM = F_INV + 512;                   // 49664
// out_mma smem: vsum fp16 (16K), Wo fp32 stage (32K), WoH/WoL fp16 (16K each)
constexpr uint32_t O_VS = 0, O_WST = 16384, O_WH = 49152, O_WL = 65536,
                   O_SMEM = 81920;
}

typedef unsigned long long u64;

// ------------------------------- helpers -----------------------------------
__device__ __forceinline__ uint32_t smem_u32(const void* p) {
    uint32_t a;
    asm("{ .reg .u64 t; cvta.to.shared.u64 t, %1; cvt.u32.u64 %0, t; }" : "=r"(a) : "l"(p));
    return a;
}
// swizzled byte offset in a [rows][64 x 16-bit] tile (128B rows, 16B units)
__device__ __forceinline__ uint32_t swzo(int r, int c16) {
    return (uint32_t)(r * 128 + ((c16 ^ (r & 7)) << 4));
}
__device__ __forceinline__ void ldsm4(uint32_t r[4], uint32_t addr) {
    asm volatile("ldmatrix.sync.aligned.m8n8.x4.shared.b16 {%0,%1,%2,%3}, [%4];"
        : "=r"(r[0]), "=r"(r[1]), "=r"(r[2]), "=r"(r[3]) : "r"(addr));
}
__device__ __forceinline__ void mma16816(float c[4], const uint32_t a[4], const uint32_t b[2]) {
    asm volatile("mma.sync.aligned.m16n8k16.row.col.f32.bf16.bf16.f32 "
        "{%0,%1,%2,%3}, {%4,%5,%6,%7}, {%8,%9}, {%0,%1,%2,%3};"
        : "+f"(c[0]), "+f"(c[1]), "+f"(c[2]), "+f"(c[3])
        : "r"(a[0]), "r"(a[1]), "r"(a[2]), "r"(a[3]), "r"(b[0]), "r"(b[1]));
}
__device__ __forceinline__ void mma16816h(float c[4], const uint32_t a[4], const uint32_t b[2]) {
    asm volatile("mma.sync.aligned.m16n8k16.row.col.f32.f16.f16.f32 "
        "{%0,%1,%2,%3}, {%4,%5,%6,%7}, {%8,%9}, {%0,%1,%2,%3};"
        : "+f"(c[0]), "+f"(c[1]), "+f"(c[2]), "+f"(c[3])
        : "r"(a[0]), "r"(a[1]), "r"(a[2]), "r"(a[3]), "r"(b[0]), "r"(b[1]));
}
__device__ __forceinline__ uint32_t pk_bf(float a, float b) {
    return (uint32_t)__bfloat16_as_ushort(__float2bfloat16(a)) |
           ((uint32_t)__bfloat16_as_ushort(__float2bfloat16(b)) << 16);
}
// packed fp16x2: lo = a, hi = b (single cvt instruction)
__device__ __forceinline__ uint32_t pk_f16(float a, float b) {
    uint32_t r;
    asm("cvt.rn.f16x2.f32 %0, %1, %2;" : "=r"(r) : "f"(b), "f"(a));
    return r;
}
__device__ __forceinline__ float2 h2f(uint32_t u) {
    __half2 h = *reinterpret_cast<__half2*>(&u);
    return __half22float2(h);
}
__device__ __forceinline__ void split1(float v, float& hi, float& lo) {
    __nv_bfloat16 h = __float2bfloat16(v);
    hi = __bfloat162float(h);
    lo = v - hi;
}
// 8 consecutive floats -> bf16 hi/lo uint4s
__device__ __forceinline__ void split8(const float4& a, const float4& c, uint4& hi, uint4& lo) {
    float h0, l0, h1, l1;
    split1(a.x, h0, l0); split1(a.y, h1, l1);
    hi.x = pk_bf(h0, h1); lo.x = pk_bf(l0, l1);
    split1(a.z, h0, l0); split1(a.w, h1, l1);
    hi.y = pk_bf(h0, h1); lo.y = pk_bf(l0, l1);
    split1(c.x, h0, l0); split1(c.y, h1, l1);
    hi.z = pk_bf(h0, h1); lo.z = pk_bf(l0, l1);
    split1(c.z, h0, l0); split1(c.w, h1, l1);
    hi.w = pk_bf(h0, h1); lo.w = pk_bf(l0, l1);
}
__device__ __forceinline__ void cpa16(uint32_t s, const void* g) {
    asm volatile("cp.async.cg.shared.global [%0], [%1], 16;" :: "r"(s), "l"(g) : "memory");
}
#define CPA_COMMIT() asm volatile("cp.async.commit_group;" ::: "memory")

// ------------------------------ device scratch -----------------------------
__device__ __half g_qf[MM * DD], g_kf[MM * DD];          // q (pre-scaled), k fp16
__device__ float g_v[MM * DD];
__device__ float g_colsum[MM];
__device__ __half g_valsh[NPART][MM * DD];               // fp16 O partials
__device__ __half g_vt[BB * DD * LL];                    // v^T fp16 [b][d][k]

// ---------------------------------------------------------------------------
// Kernel 1: qkv_mma.  q,k,v = x@W+b via 3-pass bf16 HMMA.
// grid (MM/128, 3), 256 thr.  Also zeroes g_colsum.
// ---------------------------------------------------------------------------
__global__ __launch_bounds__(256) void qkv_mma(
    const float* __restrict__ x,
    const float* __restrict__ Wq, const float* __restrict__ bq,
    const float* __restrict__ Wk, const float* __restrict__ bk,
    const float* __restrict__ Wv, const float* __restrict__ bv)
{
    extern __shared__ char smem[];
    const uint32_t sb = smem_u32(smem);
    const int t = threadIdx.x, l = t & 31, w = t >> 5;
    const int gid = (blockIdx.y * gridDim.x + blockIdx.x) * 256 + t;
    if (gid < MM) g_colsum[gid] = 0.f;

    const float* W; const float* bias; float oscale;
    __half* of = nullptr;
    if (blockIdx.y == 0)      { W = Wq; bias = bq; of = g_qf; oscale = SCALE; }
    else if (blockIdx.y == 1) { W = Wk; bias = bk; of = g_kf; oscale = 1.f; }
    else                      { W = Wv; bias = bv; oscale = 1.f; }
    const bool isv = (blockIdx.y == 2);
    const int mb = blockIdx.x * 128;

    float* stg = (float*)(smem + Q_ST);              // W fp32 stage [64][64]

    float acc[8][4];
#pragma unroll
    for (int nt = 0; nt < 8; ++nt)
#pragma unroll
        for (int j = 0; j < 4; ++j) acc[nt][j] = 0.f;

    for (int kc = 0; kc < IN; kc += 64) {
        __syncthreads();
#pragma unroll
        for (int s = 0; s < 4; ++s) {
            int u = t + 256 * s;
            int r = u >> 3, c16 = u & 7;
            const float* xp = &x[(size_t)(mb + r) * IN + kc + c16 * 8];
            float4 a = *reinterpret_cast<const float4*>(xp);
            float4 c = *reinterpret_cast<const float4*>(xp + 4);
            uint4 hi, lo;
            split8(a, c, hi, lo);
            uint32_t off = swzo(r, c16);
            *(uint4*)(smem + Q_XH + off) = hi;
            *(uint4*)(smem + Q_XL + off) = lo;
        }
#pragma unroll
        for (int s = 0; s < 4; ++s) {
            int u = t + 256 * s;
            int k = u >> 4, c4 = u & 15;
            *reinterpret_cast<float4*>(&stg[k * 64 + 4 * c4]) =
                *reinterpret_cast<const float4*>(&W[(size_t)(kc + k) * DD + 4 * c4]);
        }
        __syncthreads();
#pragma unroll
        for (int s = 0; s < 2; ++s) {
            int u = t + 256 * s;
            int k16 = u >> 6, n = u & 63;
            union { __nv_bfloat16 h[8]; uint4 u4; } hi, lo;
#pragma unroll
            for (int j = 0; j < 8; ++j) {
                float v = stg[(k16 * 8 + j) * 64 + n];
                __nv_bfloat16 hb = __float2bfloat16(v);
                hi.h[j] = hb;
                lo.h[j] = __float2bfloat16(v - __bfloat162float(hb));
            }
            uint32_t off = swzo(n, k16);
            *(uint4*)(smem + Q_WH + off) = hi.u4;
            *(uint4*)(smem + Q_WL + off) = lo.u4;
        }
        __syncthreads();
#pragma unroll
        for (int ks = 0; ks < 4; ++ks) {
            uint32_t xh[4], xl[4];
            uint32_t aoff = swzo(w * 16 + (l & 15), ks * 2 + (l >> 4));
            ldsm4(xh, sb + Q_XH + aoff);
            ldsm4(xl, sb + Q_XL + aoff);
            uint32_t wh[8][2], wl[8][2];
            uint32_t boff = swzo(((l >> 4) << 3) + (l & 7), ks * 2 + ((l >> 3) & 1));
#pragma unroll
            for (int pg = 0; pg < 4; ++pg) {
                uint32_t r4[4];
                ldsm4(r4, sb + Q_WH + boff + pg * 2048);
                wh[pg * 2][0] = r4[0]; wh[pg * 2][1] = r4[1];
                wh[pg * 2 + 1][0] = r4[2]; wh[pg * 2 + 1][1] = r4[3];
                ldsm4(r4, sb + Q_WL + boff + pg * 2048);
                wl[pg * 2][0] = r4[0]; wl[pg * 2][1] = r4[1];
                wl[pg * 2 + 1][0] = r4[2]; wl[pg * 2 + 1][1] = r4[3];
            }
#pragma unroll
            for (int nt = 0; nt < 8; ++nt) {
                mma16816(acc[nt], xh, wh[nt]);
                mma16816(acc[nt], xh, wl[nt]);
                mma16816(acc[nt], xl, wh[nt]);
            }
        }
    }
#pragma unroll
    for (int nt = 0; nt < 8; ++nt) {
        int col = nt * 8 + 2 * (l & 3);
        float b0 = bias[col], b1 = bias[col + 1];
        int r0 = mb + w * 16 + (l >> 2);
        float e0 = (acc[nt][0] + b0) * oscale;
        float e1 = (acc[nt][1] + b1) * oscale;
        float e2 = (acc[nt][2] + b0) * oscale;
        float e3 = (acc[nt][3] + b1) * oscale;
        if (isv) {
            *reinterpret_cast<float2*>(&g_v[(size_t)r0 * DD + col]) = make_float2(e0, e1);
            *reinterpret_cast<float2*>(&g_v[(size_t)(r0 + 8) * DD + col]) = make_float2(e2, e3);
        } else {
            *reinterpret_cast<uint32_t*>(&of[(size_t)r0 * DD + col]) = pk_f16(e0, e1);
            *reinterpret_cast<uint32_t*>(&of[(size_t)(r0 + 8) * DD + col]) = pk_f16(e2, e3);
        }
    }
}

// ---------------------------------------------------------------------------
// Kernel 1b: v[b][k][d] -> fp16 transposed g_vt[b][d][k].
// grid (LL/64, BB), 256 thr.
// ---------------------------------------------------------------------------
__global__ __launch_bounds__(256) void vtrans_kernel()
{
    const int b = blockIdx.y, kb = blockIdx.x * 64;
    const int t = threadIdx.x;
    __shared__ float tile[64][68];

    const int c4 = t & 15, r0 = t >> 4;
#pragma unroll
    for (int s = 0; s < 4; ++s) {
        int r = r0 + 16 * s;
        float4 v = *reinterpret_cast<const float4*>(&g_v[(size_t)(b * LL + kb + r) * DD + 4 * c4]);
        tile[r][4 * c4 + 0] = v.x; tile[r][4 * c4 + 1] = v.y;
        tile[r][4 * c4 + 2] = v.z; tile[r][4 * c4 + 3] = v.w;
    }
    __syncthreads();

    const int f8 = t & 7, d0 = t >> 3;
#pragma unroll
    for (int s = 0; s < 2; ++s) {
        int d = d0 + 32 * s;
        union { __half h[8]; uint4 u; } hi;
#pragma unroll
        for (int j = 0; j < 8; ++j)
            hi.h[j] = __float2half_rn(tile[f8 * 8 + j][d]);
        size_t o = (size_t)(b * DD + d) * LL + kb + f8 * 8;
        *reinterpret_cast<uint4*>(&g_vt[o]) = hi.u;
    }
}

// ---------------------------------------------------------------------------
// Kernel 2: scores_sum (1-pass fp16).  colsum[b,k] += sum_q exp(S[q,k]).
// grid (L/128 kb, L/128 qb, B), 256 thr, 2 CTAs/SM.
// ---------------------------------------------------------------------------
__global__ __launch_bounds__(256, 2) void scores_sum(void)
{
    extern __shared__ char smem[];
    const uint32_t sb = smem_u32(smem);
    const int t = threadIdx.x, l = t & 31, w = t >> 5;
    const int wm = w & 3, wn = w >> 2;
    const int b = blockIdx.z, qb = blockIdx.y * 128, kb = blockIdx.x * 128;

    {
        const size_t qo = (size_t)(b * LL + qb) * DD;
        const size_t ko = (size_t)(b * LL + kb) * DD;
#pragma unroll
        for (int s = 0; s < 4; ++s) {
            int u = t + 256 * s;
            int r = u >> 3, c16 = u & 7;
            uint32_t off = swzo(r, c16);
            size_t gi = qo + (size_t)r * DD + c16 * 8;
            *(uint4*)(smem + S_QF + off) = *reinterpret_cast<const uint4*>(&g_qf[gi]);
            gi = ko + (size_t)r * DD + c16 * 8;
            *(uint4*)(smem + S_KF + off) = *reinterpret_cast<const uint4*>(&g_kf[gi]);
        }
    }
    __syncthreads();

    float acc[2][8][4];
#pragma unroll
    for (int mt = 0; mt < 2; ++mt)
#pragma unroll
        for (int nt = 0; nt < 8; ++nt)
#pragma unroll
            for (int j = 0; j < 4; ++j) acc[mt][nt][j] = 0.f;

#pragma unroll
    for (int ks = 0; ks < 4; ++ks) {
        uint32_t qf[2][4];
        {
            uint32_t aoff = swzo(wm * 32 + (l & 15), ks * 2 + (l >> 4));
            ldsm4(qf[0], sb + S_QF + aoff);
            ldsm4(qf[1], sb + S_QF + aoff + 2048);
        }
        uint32_t kf[8][2];
        {
            uint32_t boff = swzo(wn * 64 + ((l >> 4) << 3) + (l & 7),
                                 ks * 2 + ((l >> 3) & 1));
#pragma unroll
            for (int pg = 0; pg < 4; ++pg) {
                uint32_t r4[4];
                ldsm4(r4, sb + S_KF + boff + pg * 2048);
                kf[pg * 2][0] = r4[0]; kf[pg * 2][1] = r4[1];
                kf[pg * 2 + 1][0] = r4[2]; kf[pg * 2 + 1][1] = r4[3];
            }
        }
#pragma unroll
        for (int mt = 0; mt < 2; ++mt)
#pragma unroll
            for (int nt = 0; nt < 8; ++nt)
                mma16816h(acc[mt][nt], qf[mt], kf[nt]);
    }

    float* colred = (float*)(smem + S_RED);
#pragma unroll
    for (int nt = 0; nt < 8; ++nt) {
        float cs0 = 0.f, cs1 = 0.f;
#pragma unroll
        for (int mt = 0; mt < 2; ++mt) {
            cs0 += __expf(acc[mt][nt][0]) + __expf(acc[mt][nt][2]);
            cs1 += __expf(acc[mt][nt][1]) + __expf(acc[mt][nt][3]);
        }
#pragma unroll
        for (int m = 4; m < 32; m <<= 1) {
            cs0 += __shfl_xor_sync(0xffffffffu, cs0, m);
            cs1 += __shfl_xor_sync(0xffffffffu, cs1, m);
        }
        if (l < 4) {
            colred[wm * 128 + wn * 64 + nt * 8 + 2 * l + 0] = cs0;
            colred[wm * 128 + wn * 64 + nt * 8 + 2 * l + 1] = cs1;
        }
    }
    __syncthreads();
    if (t < 128) {
        float s = colred[t] + colred[128 + t] + colred[256 + t] + colred[384 + t];
        atomicAdd(&g_colsum[b * LL + kb + t], s);
    }
}

// ---------------------------------------------------------------------------
// Kernel 3: av_fused.  S 1-pass fp16 (consistent with colsum); P fp16;
// O single-pass fp16 V; fp16 partials out.  16 q-rows/warp, 64-col chunks,
// 2 CTAs/SM, cp.async double buffering.  grid (L/128, KSPLIT, B), 256 thr.
// ---------------------------------------------------------------------------
__global__ __launch_bounds__(256, 2) void av_fused(float* __restrict__ attn)
{
    extern __shared__ char smem[];
    const uint32_t sb = smem_u32(smem);
    const int t = threadIdx.x, l = t & 31, w = t >> 5;
    const int b = blockIdx.z, split = blockIdx.y, qb = blockIdx.x * 128;
    const int kBeg = split * (LL / KSPLIT);
    constexpr int NCH = (LL / KSPLIT) / 64;          // 16 chunks

    float* invb = (float*)(smem + F_INV);            // [2][64]
    const float* cs = g_colsum + b * LL;
    float* ap = attn + (size_t)(b * LL + qb) * LL;

    // q tile once (128 rows x 64 d fp16)
    {
        const size_t qo = (size_t)(b * LL + qb) * DD;
#pragma unroll
        for (int s = 0; s < 4; ++s) {
            int u = t + 256 * s;
            int r = u >> 3, c16 = u & 7;
            *(uint4*)(smem + F_QF + swzo(r, c16)) =
                *reinterpret_cast<const uint4*>(&g_qf[qo + (size_t)r * DD + c16 * 8]);
        }
    }
    if (t < 64) invb[t] = 1.f / cs[kBeg + t];

    auto issue = [&](int ci) {
        const int kc = kBeg + ci * 64;
        const uint32_t base = sb + F_KV + (uint32_t)(ci & 1) * F_STAGE;
        const size_t ko = (size_t)(b * LL + kc) * DD;
#pragma unroll
        for (int s = 0; s < 2; ++s) {
            int u = t + 256 * s;
            int r = u >> 3, c16 = u & 7;
            uint32_t off = swzo(r, c16);
            cpa16(base + off,        &g_kf[ko + (size_t)r * DD + c16 * 8]);
            cpa16(base + 8192 + off, &g_vt[(size_t)(b * DD + r) * LL + kc + c16 * 8]);
        }
        CPA_COMMIT();
    };
    issue(0);

    float o[8][4];
#pragma unroll
    for (int nt = 0; nt < 8; ++nt)
#pragma unroll
        for (int j = 0; j < 4; ++j) o[nt][j] = 0.f;

    for (int ci = 0; ci < NCH; ++ci) {
        const int kc = kBeg + ci * 64;
        if (ci + 1 < NCH) {
            issue(ci + 1);
            asm volatile("cp.async.wait_group 1;" ::: "memory");
        } else {
            asm volatile("cp.async.wait_group 0;" ::: "memory");
        }
        __syncthreads();

        if (ci + 1 < NCH && t < 64)
            invb[((ci + 1) & 1) * 64 + t] = 1.f / cs[kc + 64 + t];

        const uint32_t kbuf = sb + F_KV + (uint32_t)(ci & 1) * F_STAGE;
        const uint32_t vbuf = kbuf + 8192;
        const float* inv_s = invb + (ci & 1) * 64;

        // ---- S = q k^T (1-pass fp16, identical op order to scores_sum) ----
        float acc[8][4];
#pragma unroll
        for (int nt = 0; nt < 8; ++nt)
#pragma unroll
            for (int j = 0; j < 4; ++j) acc[nt][j] = 0.f;

#pragma unroll
        for (int ks = 0; ks < 4; ++ks) {
            uint32_t qf[4];
            ldsm4(qf, sb + F_QF + swzo(w * 16 + (l & 15), ks * 2 + (l >> 4)));
            uint32_t kf[8][2];
            {
                uint32_t boff = swzo(((l >> 4) << 3) + (l & 7),
                                     ks * 2 + ((l >> 3) & 1));
#pragma unroll
                for (int pg = 0; pg < 4; ++pg) {
                    uint32_t r4[4];
                    ldsm4(r4, kbuf + boff + pg * 2048);
                    kf[pg * 2][0] = r4[0]; kf[pg * 2][1] = r4[1];
                    kf[pg * 2 + 1][0] = r4[2]; kf[pg * 2 + 1][1] = r4[3];
                }
            }
#pragma unroll
            for (int nt = 0; nt < 8; ++nt)
                mma16816h(acc[nt], qf, kf[nt]);
        }

        // ---- P = exp(S)*inv ; store A fp32 ; pack P as fp16 A-fragments ----
        uint32_t ph[4][4];
#pragma unroll
        for (int nt = 0; nt < 8; ++nt) {
            int lc = nt * 8 + 2 * (l & 3);
            float i0 = inv_s[lc], i1 = inv_s[lc + 1];
            float e0 = __expf(acc[nt][0]) * i0;
            float e1 = __expf(acc[nt][1]) * i1;
            float e2 = __expf(acc[nt][2]) * i0;
            float e3 = __expf(acc[nt][3]) * i1;
            int r0 = w * 16 + (l >> 2);
            *reinterpret_cast<float2*>(&ap[(size_t)r0 * LL + kc + lc]) = make_float2(e0, e1);
            *reinterpret_cast<float2*>(&ap[(size_t)(r0 + 8) * LL + kc + lc]) = make_float2(e2, e3);
            int kb2 = nt >> 1, base = (nt & 1) * 2;
            ph[kb2][base + 0] = pk_f16(e0, e1);
            ph[kb2][base + 1] = pk_f16(e2, e3);
        }

        // ---- O += P @ V (single-pass fp16) ----
#pragma unroll
        for (int kb2 = 0; kb2 < 4; ++kb2) {
            uint32_t vf[8][2];
            {
                uint32_t boff = swzo(((l >> 4) << 3) + (l & 7),
                                     kb2 * 2 + ((l >> 3) & 1));
#pragma unroll
                for (int pg = 0; pg < 4; ++pg) {
                    uint32_t r4[4];
                    ldsm4(r4, vbuf + boff + pg * 2048);
                    vf[pg * 2][0] = r4[0]; vf[pg * 2][1] = r4[1];
                    vf[pg * 2 + 1][0] = r4[2]; vf[pg * 2 + 1][1] = r4[3];
                }
            }
#pragma unroll
            for (int nt = 0; nt < 8; ++nt)
                mma16816h(o[nt], ph[kb2], vf[nt]);
        }
        __syncthreads();
    }

    // epilogue: fp16 O partials
    __half* gvh = g_valsh[split];
#pragma unroll
    for (int nt = 0; nt < 8; ++nt) {
        int col = nt * 8 + 2 * (l & 3);
        size_t row = (size_t)(b * LL + qb + w * 16 + (l >> 2));
        *reinterpret_cast<uint32_t*>(&gvh[row * DD + col]) = pk_f16(o[nt][0], o[nt][1]);
        *reinterpret_cast<uint32_t*>(&gvh[(row + 8) * DD + col]) = pk_f16(o[nt][2], o[nt][3]);
    }
}

// ---------------------------------------------------------------------------
// Kernel 4: out_mma.  out = (sum fp16 partials) @ Wo + bo.
// A = vsum fp16 (1 op), B = Wo fp16 hi + fp16 residual (2-pass).
// grid (MM/128, OUT/128), 256 thr, dynamic smem O_SMEM.
// ---------------------------------------------------------------------------
__global__ __launch_bounds__(256) void out_mma(
    const float* __restrict__ Wo, const float* __restrict__ bo,
    float* __restrict__ outp)
{
    extern __shared__ char smem[];
    const uint32_t sb = smem_u32(smem);
    const int t = threadIdx.x, l = t & 31, w = t >> 5;
    const int mb = blockIdx.x * 128;
    const int nb = blockIdx.y * 128;

    // ---- vsum = sum of 4 fp16 partials -> fp16 tile [128 m][64 k] ----
#pragma unroll
    for (int s = 0; s < 4; ++s) {
        int u = t + 256 * s;
        int r = u >> 3, c16 = u & 7;
        size_t base = (size_t)(mb + r) * DD + c16 * 8;
        uint4 p0 = *reinterpret_cast<const uint4*>(&g_valsh[0][base]);
        uint4 p1 = *reinterpret_cast<const uint4*>(&g_valsh[1][base]);
        uint4 p2 = *reinterpret_cast<const uint4*>(&g_valsh[2][base]);
        uint4 p3 = *reinterpret_cast<const uint4*>(&g_valsh[3][base]);
        uint4 res;
        {
            float2 f;
            f = h2f(p0.x); float2 g1 = h2f(p1.x), g2 = h2f(p2.x), g3 = h2f(p3.x);
            res.x = pk_f16(f.x + g1.x + g2.x + g3.x, f.y + g1.y + g2.y + g3.y);
            f = h2f(p0.y); g1 = h2f(p1.y); g2 = h2f(p2.y); g3 = h2f(p3.y);
            res.y = pk_f16(f.x + g1.x + g2.x + g3.x, f.y + g1.y + g2.y + g3.y);
            f = h2f(p0.z); g1 = h2f(p1.z); g2 = h2f(p2.z); g3 = h2f(p3.z);
            res.z = pk_f16(f.x + g1.x + g2.x + g3.x, f.y + g1.y + g2.y + g3.y);
            f = h2f(p0.w); g1 = h2f(p1.w); g2 = h2f(p2.w); g3 = h2f(p3.w);
            res.w = pk_f16(f.x + g1.x + g2.x + g3.x, f.y + g1.y + g2.y + g3.y);
        }
        *(uint4*)(smem + O_VS + swzo(r, c16)) = res;
    }
    // ---- Wo fp32 stage [64 k][128 n] ----
    {
        float* stg = (float*)(smem + O_WST);
#pragma unroll
        for (int s = 0; s < 8; ++s) {
            int u = t + 256 * s;
            int k = u >> 5, c4 = u & 31;
            *reinterpret_cast<float4*>(&stg[k * 128 + 4 * c4]) =
                *reinterpret_cast<const float4*>(&Wo[(size_t)k * OUT + nb + 4 * c4]);
        }
    }
    __syncthreads();
    // ---- transpose + split -> WoH/WoL fp16 [128 n][64 k] ----
    {
        const float* stg = (const float*)(smem + O_WST);
#pragma unroll
        for (int s = 0; s < 4; ++s) {
            int u = t + 256 * s;
            int k16 = u >> 7, n = u & 127;
            union { __half h[8]; uint4 u4; } hi, lo;
#pragma unroll
            for (int j = 0; j < 8; ++j) {
                float v = stg[(k16 * 8 + j) * 128 + n];
                __half hb = __float2half_rn(v);
                hi.h[j] = hb;
                lo.h[j] = __float2half_rn(v - __half2float(hb));
            }
            uint32_t off = swzo(n, k16);
            *(uint4*)(smem + O_WH + off) = hi.u4;
            *(uint4*)(smem + O_WL + off) = lo.u4;
        }
    }
    __syncthreads();

    // ---- MMA: each warp 16 m-rows x 128 n ----
    float acc[16][4];
#pragma unroll
    for (int nt = 0; nt < 16; ++nt)
#pragma unroll
        for (int j = 0; j < 4; ++j) acc[nt][j] = 0.f;

#pragma unroll
    for (int ks = 0; ks < 4; ++ks) {
        uint32_t af[4];
        ldsm4(af, sb + O_VS + swzo(w * 16 + (l & 15), ks * 2 + (l >> 4)));
        uint32_t boff0 = swzo(((l >> 4) << 3) + (l & 7), ks * 2 + ((l >> 3) & 1));
#pragma unroll
        for (int half = 0; half < 2; ++half) {
            uint32_t wh[8][2], wl[8][2];
#pragma unroll
            for (int pg = 0; pg < 4; ++pg) {
                uint32_t r4[4];
                ldsm4(r4, sb + O_WH + boff0 + (half * 4 + pg) * 2048);
                wh[pg * 2][0] = r4[0]; wh[pg * 2][1] = r4[1];
                wh[pg * 2 + 1][0] = r4[2]; wh[pg * 2 + 1][1] = r4[3];
                ldsm4(r4, sb + O_WL + boff0 + (half * 4 + pg) * 2048);
                wl[pg * 2][0] = r4[0]; wl[pg * 2][1] = r4[1];
                wl[pg * 2 + 1][0] = r4[2]; wl[pg * 2 + 1][1] = r4[3];
            }
#pragma unroll
            for (int nt = 0; nt < 8; ++nt) {
                mma16816h(acc[half * 8 + nt], af, wh[nt]);
                mma16816h(acc[half * 8 + nt], af, wl[nt]);
            }
        }
    }

    // ---- epilogue ----
#pragma unroll
    for (int nt = 0; nt < 16; ++nt) {
        int col = nb + nt * 8 + 2 * (l & 3);
        float b0 = bo[col], b1 = bo[col + 1];
        size_t row = (size_t)(mb + w * 16 + (l >> 2));
        *reinterpret_cast<float2*>(&outp[row * OUT + col]) =
            make_float2(acc[nt][0] + b0, acc[nt][1] + b1);
        *reinterpret_cast<float2*>(&outp[(row + 8) * OUT + col]) =
            make_float2(acc[nt][2] + b0, acc[nt][3] + b1);
    }
}

// ---------------------------------------------------------------------------
extern "C" void kernel_launch(void* const* d_in, const int* in_sizes, int n_in,
                              void* d_out, int out_size)
{
    const float* x  = (const float*)d_in[0];
    const float* Wq = (const float*)d_in[1];
    const float* bq = (const float*)d_in[2];
    const float* Wk = (const float*)d_in[3];
    const float* bk = (const float*)d_in[4];
    const float* Wv = (const float*)d_in[5];
    const float* bv = (const float*)d_in[6];
    const float* Wo = (const float*)d_in[7];
    const float* bo = (const float*)d_in[8];

    float* outp = (float*)d_out;                   // [B, L, OUT]
    float* attn = outp + (size_t)BB * LL * OUT;    // [B, L, L]

    cudaFuncSetAttribute(qkv_mma,    cudaFuncAttributeMaxDynamicSharedMemorySize, Q_SMEM);
    cudaFuncSetAttribute(scores_sum, cudaFuncAttributeMaxDynamicSharedMemorySize, S_SMEM);
    cudaFuncSetAttribute(av_fused,   cudaFuncAttributeMaxDynamicSharedMemorySize, F_SMEM);
    cudaFuncSetAttribute(out_mma,    cudaFuncAttributeMaxDynamicSharedMemorySize, O_SMEM);

    qkv_mma<<<dim3(MM / 128, 3), 256, Q_SMEM>>>(x, Wq, bq, Wk, bk, Wv, bv);
    vtrans_kernel<<<dim3(LL / 64, BB), 256>>>();
    scores_sum<<<dim3(LL / 128, LL / 128, BB), 256, S_SMEM>>>();
    av_fused<<<dim3(LL / 128, KSPLIT, BB), 256, F_SMEM>>>(attn);
    out_mma<<<dim3(MM / 128, OUT / 128), 256, O_SMEM>>>(Wo, bo, outp);
}